// round 6
// baseline (speedup 1.0000x reference)
#include <cuda_runtime.h>
#include <cstdint>
#include <cstddef>

#define N_NODES 20000
#define IN_DIM  1536
#define HID     256
#define HEADS   4
#define HOPS    3
#define NCLS    3
#define NE      320000
#define EP      (NE + N_NODES)     /* 340000 edges incl. self loops */
#define LN_EPS  1e-5f
#define NEG_SLOPE 0.2f

// ---------------- scratch (static device globals: no runtime allocation) ----------------
__device__ float g_x [N_NODES * HID];     // current node features
__device__ float g_xl[N_NODES * HID];     // source transform (also reused for head1 out)
__device__ float g_xr[N_NODES * HID];     // target transform
__device__ float g_logits[EP * HEADS];    // logits -> (in place) alpha
__device__ int   g_rowstart[N_NODES + 1]; // CSR row offsets by dst
__device__ int   g_counts[N_NODES];
__device__ int   g_cursor[N_NODES];
__device__ int   g_src[EP];               // src per CSR slot
__device__ int   g_dst[EP];               // dst per CSR slot

__device__ __forceinline__ float warp_sum32(float v){
#pragma unroll
    for (int o = 16; o > 0; o >>= 1) v += __shfl_xor_sync(0xffffffffu, v, o);
    return v;
}
__device__ __forceinline__ float lrelu(float t){ return t > 0.f ? t : NEG_SLOPE * t; }
__device__ __forceinline__ int clamp_idx(int v){
    return ((unsigned)v < (unsigned)N_NODES) ? v : 0;   // defensive: wrong-answer beats device fault
}

// ---------------- CSR build ----------------
__global__ void k_clear(){
    int i = blockIdx.x * blockDim.x + threadIdx.x;
    if (i < N_NODES){ g_counts[i] = 0; g_cursor[i] = 0; }
}
// edge_index is int32 (JAX x64 disabled: jnp.int64 request yields int32)
__global__ void k_hist(const int* __restrict__ ei){
    int e = blockIdx.x * blockDim.x + threadIdx.x;
    if (e >= EP) return;
    int dst = (e < NE) ? clamp_idx(ei[NE + e]) : (e - NE);
    atomicAdd(&g_counts[dst], 1);
}
__global__ void k_scan(){   // single-block exclusive scan of g_counts -> g_rowstart
    __shared__ int sm[1024];
    __shared__ int soff;
    int tid = threadIdx.x;
    if (tid == 0) soff = 0;
    __syncthreads();
    for (int base = 0; base < N_NODES; base += 1024){
        int idx = base + tid;
        int v = (idx < N_NODES) ? g_counts[idx] : 0;
        sm[tid] = v;
        __syncthreads();
        for (int s = 1; s < 1024; s <<= 1){
            int t = (tid >= s) ? sm[tid - s] : 0;
            __syncthreads();
            sm[tid] += t;
            __syncthreads();
        }
        if (idx < N_NODES) g_rowstart[idx] = soff + sm[tid] - v;
        int tot = sm[1023];
        __syncthreads();
        if (tid == 0) soff += tot;
        __syncthreads();
    }
    if (tid == 0) g_rowstart[N_NODES] = soff;
}
__global__ void k_scatter(const int* __restrict__ ei){
    int e = blockIdx.x * blockDim.x + threadIdx.x;
    if (e >= EP) return;
    int src, dst;
    if (e < NE){ src = clamp_idx(ei[e]); dst = clamp_idx(ei[NE + e]); }
    else       { src = e - NE;           dst = src; }
    int pos = g_rowstart[dst] + atomicAdd(&g_cursor[dst], 1);
    g_src[pos] = src;
    g_dst[pos] = dst;
}

// ---------------- fused GEMM: out[M,256] = A[M,K] @ W[K,256] + bias, optional LN / GELU ----
// BM=64, BN=256 (full row per block -> LN is one warp reduction), BK=16, blockDim 256.
// Warp y owns rows y*8..y*8+7; lane x owns column pairs (2x+64j, +1), j=0..3.
// A tile stored DUPLICATED in smem -> broadcast LDS.64 gives (a,a); B read as natural
// column pairs via LDS.64. Inner product = packed fp32 FFMA2 (fma.rn.f32x2).
// MODE: 0 plain, 1 +LayerNorm, 2 +exact GELU.  ASEL: 0 ext A, 1 g_x.  OSEL: 1 g_x, 2 g_xl, 3 g_xr
#define BM 64
#define BK 16

template<int MODE, int ASEL, int OSEL>
__global__ __launch_bounds__(256, 1)
void k_gemm256(const float* __restrict__ Aext,
               const float* __restrict__ W,
               const float* __restrict__ bias,
               const float* __restrict__ lng,
               const float* __restrict__ lnb,
               int M, int K)
{
    __shared__ float Asd[BK][136];   // duplicated A: [k][2*row(+pad)]  (544B row, 8B aligned)
    __shared__ float Ws [BK][256];   // natural W: [k][col]

    const float* A   = (ASEL == 0) ? Aext : (const float*)g_x;
    float*       out = (OSEL == 1) ? g_x : (OSEL == 2 ? g_xl : g_xr);

    int tid = threadIdx.x;
    int x = tid & 31, y = tid >> 5;
    int row0 = blockIdx.x * BM;

    unsigned long long acc[8][4];    // [row r][col-pair j]
#pragma unroll
    for (int r = 0; r < 8; r++)
#pragma unroll
        for (int j = 0; j < 4; j++) acc[r][j] = 0ull;

    int arow = tid >> 2;                 // 0..63
    int akk  = (tid & 3) << 2;           // 0,4,8,12
    bool arowok = (row0 + arow) < M;
    const float* Aptr = A + (size_t)(row0 + arow) * K + akk;

    for (int k0 = 0; k0 < K; k0 += BK){
        float4 av = arowok ? *(const float4*)(Aptr + k0) : make_float4(0.f, 0.f, 0.f, 0.f);
        float4 wv[4];
#pragma unroll
        for (int r = 0; r < 4; r++){
            int q = tid + 256 * r;           // 0..1023
            int krow = q >> 6, col4 = (q & 63) << 2;
            wv[r] = *(const float4*)(W + (size_t)(k0 + krow) * HID + col4);
        }
        __syncthreads();
        {   // duplicated A store: Asd[akk+c][2*arow .. +1] = av.c
            unsigned long long d0, d1, d2, d3;
            asm("mov.b64 %0, {%1, %1};" : "=l"(d0) : "r"(__float_as_uint(av.x)));
            asm("mov.b64 %0, {%1, %1};" : "=l"(d1) : "r"(__float_as_uint(av.y)));
            asm("mov.b64 %0, {%1, %1};" : "=l"(d2) : "r"(__float_as_uint(av.z)));
            asm("mov.b64 %0, {%1, %1};" : "=l"(d3) : "r"(__float_as_uint(av.w)));
            *(unsigned long long*)&Asd[akk + 0][2 * arow] = d0;
            *(unsigned long long*)&Asd[akk + 1][2 * arow] = d1;
            *(unsigned long long*)&Asd[akk + 2][2 * arow] = d2;
            *(unsigned long long*)&Asd[akk + 3][2 * arow] = d3;
        }
#pragma unroll
        for (int r = 0; r < 4; r++){
            int q = tid + 256 * r;
            int krow = q >> 6, col4 = (q & 63) << 2;
            *(float4*)&Ws[krow][col4] = wv[r];
        }
        __syncthreads();
#pragma unroll
        for (int kk = 0; kk < BK; kk++){
            unsigned long long a[8];
#pragma unroll
            for (int r = 0; r < 8; r++)      // broadcast (a,a) pairs
                a[r] = *(const unsigned long long*)&Asd[kk][2 * (y * 8 + r)];
#pragma unroll
            for (int j = 0; j < 4; j++){
                unsigned long long bb = *(const unsigned long long*)&Ws[kk][2 * x + 64 * j];
                asm("fma.rn.f32x2 %0, %1, %2, %0;" : "+l"(acc[0][j]) : "l"(a[0]), "l"(bb));
                asm("fma.rn.f32x2 %0, %1, %2, %0;" : "+l"(acc[1][j]) : "l"(a[1]), "l"(bb));
                asm("fma.rn.f32x2 %0, %1, %2, %0;" : "+l"(acc[2][j]) : "l"(a[2]), "l"(bb));
                asm("fma.rn.f32x2 %0, %1, %2, %0;" : "+l"(acc[3][j]) : "l"(a[3]), "l"(bb));
                asm("fma.rn.f32x2 %0, %1, %2, %0;" : "+l"(acc[4][j]) : "l"(a[4]), "l"(bb));
                asm("fma.rn.f32x2 %0, %1, %2, %0;" : "+l"(acc[5][j]) : "l"(a[5]), "l"(bb));
                asm("fma.rn.f32x2 %0, %1, %2, %0;" : "+l"(acc[6][j]) : "l"(a[6]), "l"(bb));
                asm("fma.rn.f32x2 %0, %1, %2, %0;" : "+l"(acc[7][j]) : "l"(a[7]), "l"(bb));
            }
        }
    }

    // ---------------- epilogue: lane x owns cols c = 2x + 64j + p ----------------
    float b8[4][2], g8[4][2], be8[4][2];
#pragma unroll
    for (int j = 0; j < 4; j++)
#pragma unroll
        for (int p = 0; p < 2; p++){
            int c = 2 * x + 64 * j + p;
            b8[j][p] = bias[c];
            if (MODE == 1){ g8[j][p] = lng[c]; be8[j][p] = lnb[c]; }
        }
#pragma unroll
    for (int r = 0; r < 8; r++){
        int row = row0 + y * 8 + r;
        float v[4][2];
#pragma unroll
        for (int j = 0; j < 4; j++){
            unsigned int lo, hi;
            asm("mov.b64 {%0, %1}, %2;" : "=r"(lo), "=r"(hi) : "l"(acc[r][j]));
            v[j][0] = __uint_as_float(lo) + b8[j][0];
            v[j][1] = __uint_as_float(hi) + b8[j][1];
        }
        if (MODE == 1){
            float s = 0.f, ss = 0.f;
#pragma unroll
            for (int j = 0; j < 4; j++)
#pragma unroll
                for (int p = 0; p < 2; p++){ s += v[j][p]; ss += v[j][p] * v[j][p]; }
            s  = warp_sum32(s);
            ss = warp_sum32(ss);
            float mu  = s  * (1.f / 256.f);
            float var = ss * (1.f / 256.f) - mu * mu;
            float inv = rsqrtf(var + LN_EPS);
            if (row < M){
#pragma unroll
                for (int j = 0; j < 4; j++)
#pragma unroll
                    for (int p = 0; p < 2; p++)
                        out[(size_t)row * HID + 2 * x + 64 * j + p] =
                            (v[j][p] - mu) * inv * g8[j][p] + be8[j][p];
            }
        } else if (MODE == 2){
            if (row < M){
#pragma unroll
                for (int j = 0; j < 4; j++)
#pragma unroll
                    for (int p = 0; p < 2; p++){
                        float t = v[j][p];
                        out[(size_t)row * HID + 2 * x + 64 * j + p] =
                            0.5f * t * (1.f + erff(t * 0.70710678118654752440f));
                    }
            }
        } else {
            if (row < M){
#pragma unroll
                for (int j = 0; j < 4; j++)
#pragma unroll
                    for (int p = 0; p < 2; p++)
                        out[(size_t)row * HID + 2 * x + 64 * j + p] = v[j][p];
            }
        }
    }
}

// ---------------- edge logits: one warp per CSR slot; lane owns 8 dims (one head each) -----
__global__ void k_logits_kern(const float* __restrict__ att){
    int gw = (int)((blockIdx.x * blockDim.x + threadIdx.x) >> 5);
    if (gw >= EP) return;
    int lane = threadIdx.x & 31;
    int src = g_src[gw], dst = g_dst[gw];
    int d = lane * 8;
    const float4* pl = (const float4*)(g_xl + (size_t)src * HID + d);
    const float4* pr = (const float4*)(g_xr + (size_t)dst * HID + d);
    float4 l0 = pl[0], l1 = pl[1];
    float4 r0 = pr[0], r1 = pr[1];
    const float4* pa = (const float4*)(att + d);
    float4 a0 = __ldg(pa), a1 = __ldg(pa + 1);

    float acc = 0.f;
    acc = fmaf(lrelu(l0.x + r0.x), a0.x, acc);
    acc = fmaf(lrelu(l0.y + r0.y), a0.y, acc);
    acc = fmaf(lrelu(l0.z + r0.z), a0.z, acc);
    acc = fmaf(lrelu(l0.w + r0.w), a0.w, acc);
    acc = fmaf(lrelu(l1.x + r1.x), a1.x, acc);
    acc = fmaf(lrelu(l1.y + r1.y), a1.y, acc);
    acc = fmaf(lrelu(l1.z + r1.z), a1.z, acc);
    acc = fmaf(lrelu(l1.w + r1.w), a1.w, acc);

    acc += __shfl_xor_sync(0xffffffffu, acc, 1);
    acc += __shfl_xor_sync(0xffffffffu, acc, 2);
    acc += __shfl_xor_sync(0xffffffffu, acc, 4);
    if ((lane & 7) == 0) g_logits[(size_t)gw * HEADS + (lane >> 3)] = acc;
}

// ---------------- softmax per (node, head) over CSR segment: atomic-free, in place ----------
__global__ void k_softmax(){
    int t = blockIdx.x * blockDim.x + threadIdx.x;
    if (t >= N_NODES * HEADS) return;
    int n = t >> 2, h = t & 3;
    int s = g_rowstart[n], e = g_rowstart[n + 1];
    float m = -1e30f;
    for (int j = s; j < e; j++) m = fmaxf(m, g_logits[(size_t)j * HEADS + h]);
    float sum = 0.f;
    for (int j = s; j < e; j++){
        float ex = expf(g_logits[(size_t)j * HEADS + h] - m);
        g_logits[(size_t)j * HEADS + h] = ex;
        sum += ex;
    }
    float inv = 1.f / sum;
    for (int j = s; j < e; j++) g_logits[(size_t)j * HEADS + h] *= inv;
}

// ---------------- aggregate + gbias + residual + LayerNorm, one warp per node --------------
__global__ void k_agg_ln(const float* __restrict__ gbias,
                         const float* __restrict__ lng,
                         const float* __restrict__ lnb){
    int gw = (int)((blockIdx.x * blockDim.x + threadIdx.x) >> 5);
    if (gw >= N_NODES) return;
    int lane = threadIdx.x & 31;
    int s = g_rowstart[gw], e = g_rowstart[gw + 1];
    int d = lane * 8;
    int hh = lane >> 3;                      // head for these 8 dims
    float4 acc0 = make_float4(0.f, 0.f, 0.f, 0.f);
    float4 acc1 = make_float4(0.f, 0.f, 0.f, 0.f);
    for (int j = s; j < e; j++){
        int src = g_src[j];
        float a = g_logits[(size_t)j * HEADS + hh];  // alpha
        const float4* p = (const float4*)(g_xl + (size_t)src * HID + d);
        float4 v0 = p[0], v1 = p[1];
        acc0.x = fmaf(v0.x, a, acc0.x);  acc0.y = fmaf(v0.y, a, acc0.y);
        acc0.z = fmaf(v0.z, a, acc0.z);  acc0.w = fmaf(v0.w, a, acc0.w);
        acc1.x = fmaf(v1.x, a, acc1.x);  acc1.y = fmaf(v1.y, a, acc1.y);
        acc1.z = fmaf(v1.z, a, acc1.z);  acc1.w = fmaf(v1.w, a, acc1.w);
    }
    float* xp = g_x + (size_t)gw * HID + d;
    float v[8];
    v[0] = acc0.x + gbias[d + 0] + xp[0];
    v[1] = acc0.y + gbias[d + 1] + xp[1];
    v[2] = acc0.z + gbias[d + 2] + xp[2];
    v[3] = acc0.w + gbias[d + 3] + xp[3];
    v[4] = acc1.x + gbias[d + 4] + xp[4];
    v[5] = acc1.y + gbias[d + 5] + xp[5];
    v[6] = acc1.z + gbias[d + 6] + xp[6];
    v[7] = acc1.w + gbias[d + 7] + xp[7];
    float sm = 0.f, ss = 0.f;
#pragma unroll
    for (int q = 0; q < 8; q++){ sm += v[q]; ss += v[q] * v[q]; }
    sm = warp_sum32(sm);
    ss = warp_sum32(ss);
    float mu  = sm * (1.f / 256.f);
    float var = ss * (1.f / 256.f) - mu * mu;
    float inv = rsqrtf(var + LN_EPS);
#pragma unroll
    for (int q = 0; q < 8; q++)
        xp[q] = (v[q] - mu) * inv * lng[d + q] + lnb[d + q];
}

// ---------------- head 2: out[N,3] = gelu_out @ h2_W + h2_b, one warp per node -------------
__global__ void k_head2(const float* __restrict__ W2, const float* __restrict__ b2,
                        float* __restrict__ out){
    __shared__ float ws[HID * NCLS];
    int tid = threadIdx.x;
    for (int i = tid; i < HID * NCLS; i += blockDim.x) ws[i] = W2[i];
    __syncthreads();
    int gw = (int)((blockIdx.x * blockDim.x + tid) >> 5);
    if (gw >= N_NODES) return;
    int lane = tid & 31;
    const float* row = g_xl + (size_t)gw * HID;   // head1 output lives in g_xl
    float a0 = 0.f, a1 = 0.f, a2 = 0.f;
#pragma unroll
    for (int q = 0; q < 8; q++){
        int k = lane + 32 * q;
        float xv = row[k];
        a0 = fmaf(xv, ws[k * 3 + 0], a0);
        a1 = fmaf(xv, ws[k * 3 + 1], a1);
        a2 = fmaf(xv, ws[k * 3 + 2], a2);
    }
    a0 = warp_sum32(a0); a1 = warp_sum32(a1); a2 = warp_sum32(a2);
    if (lane == 0){
        out[(size_t)gw * NCLS + 0] = a0 + b2[0];
        out[(size_t)gw * NCLS + 1] = a1 + b2[1];
        out[(size_t)gw * NCLS + 2] = a2 + b2[2];
    }
}

// ---------------- launch ----------------
extern "C" void kernel_launch(void* const* d_in, const int* in_sizes, int n_in,
                              void* d_out, int out_size)
{
    const float* features = (const float*)d_in[0];
    const int*   ei       = (const int*)d_in[1];     // int32 (JAX x64 disabled)
    const float* proj_W = (const float*)d_in[2];
    const float* proj_b = (const float*)d_in[3];
    const float* n0_g   = (const float*)d_in[4];
    const float* n0_b   = (const float*)d_in[5];
    const float* Wl     = (const float*)d_in[6];
    const float* bl     = (const float*)d_in[7];
    const float* Wr     = (const float*)d_in[8];
    const float* br     = (const float*)d_in[9];
    const float* att    = (const float*)d_in[10];
    const float* gbias  = (const float*)d_in[11];
    const float* ln_g   = (const float*)d_in[12];
    const float* ln_b   = (const float*)d_in[13];
    const float* h1_W   = (const float*)d_in[14];
    const float* h1_b   = (const float*)d_in[15];
    const float* h2_W   = (const float*)d_in[16];
    const float* h2_b   = (const float*)d_in[17];
    float* out = (float*)d_out;

    // CSR build (cheap; rebuilt every launch -> deterministic call)
    k_clear  <<<(N_NODES + 255) / 256, 256>>>();
    k_hist   <<<(EP + 255) / 256, 256>>>(ei);
    k_scan   <<<1, 1024>>>();
    k_scatter<<<(EP + 255) / 256, 256>>>(ei);

    const int GB = (N_NODES + BM - 1) / BM;   // 313 blocks

    // x = LN(features @ proj_W + proj_b)
    k_gemm256<1, 0, 1><<<GB, 256>>>(features, proj_W, proj_b, n0_g, n0_b, N_NODES, IN_DIM);

    for (int h = 0; h < HOPS; h++){
        const float* wl = Wl + (size_t)h * HID * HID;
        const float* wr = Wr + (size_t)h * HID * HID;
        k_gemm256<0, 1, 2><<<GB, 256>>>(nullptr, wl, bl + h * HID, nullptr, nullptr, N_NODES, HID);
        k_gemm256<0, 1, 3><<<GB, 256>>>(nullptr, wr, br + h * HID, nullptr, nullptr, N_NODES, HID);
        k_logits_kern<<<(EP * 32 + 255) / 256, 256>>>(att + h * HEADS * (HID / HEADS));
        k_softmax<<<(N_NODES * HEADS + 255) / 256, 256>>>();
        k_agg_ln<<<(N_NODES * 32 + 255) / 256, 256>>>(gbias + h * HID, ln_g + h * HID, ln_b + h * HID);
    }

    // head: gelu(x @ h1_W + h1_b) -> g_xl ; then @ h2_W + h2_b -> out
    k_gemm256<2, 1, 2><<<GB, 256>>>(nullptr, h1_W, h1_b, nullptr, nullptr, N_NODES, HID);
    k_head2<<<(N_NODES * 32 + 255) / 256, 256>>>(h2_W, h2_b, out);

    (void)in_sizes; (void)n_in; (void)out_size;
}

// round 8
// speedup vs baseline: 1.6157x; 1.6157x over previous
#include <cuda_runtime.h>
#include <cuda_bf16.h>
#include <cstdint>
#include <cstddef>

#define N_NODES 20000
#define IN_DIM  1536
#define HID     256
#define HEADS   4
#define HOPS    3
#define NCLS    3
#define NE      320000
#define EP      (NE + N_NODES)     /* 340000 edges incl. self loops */
#define LN_EPS  1e-5f
#define NEG_SLOPE 0.2f

// weight arena offsets (bf16 elements), all K-major transposed: Wt[n][k] = W[k][n]
#define OFF_PROJ 0                         /* 256 x 1536 */
#define OFF_WL   393216                    /* 3 x 256 x 256 */
#define OFF_WR   589824                    /* 3 x 256 x 256 */
#define OFF_H1   786432                    /* 256 x 256 */
#define W_ARENA  851968

// ---------------- scratch (static device globals: no runtime allocation) ----------------
__device__ float g_x [N_NODES * HID];
__device__ float g_xl[N_NODES * HID];     // also proj tmp + head1 out
__device__ float g_xr[N_NODES * HID];
__device__ float g_logits[EP * HEADS];
__device__ int   g_rowstart[N_NODES + 1];
__device__ int   g_counts[N_NODES];
__device__ int   g_cursor[N_NODES];
__device__ int   g_src[EP];
__device__ int   g_dst[EP];
__device__ __nv_bfloat16 g_bhi[W_ARENA];  // weight hi split (transposed, K-major)
__device__ __nv_bfloat16 g_blo[W_ARENA];  // weight lo split

// ---------------- small helpers ----------------
__device__ __forceinline__ float warp_sum32(float v){
#pragma unroll
    for (int o = 16; o > 0; o >>= 1) v += __shfl_xor_sync(0xffffffffu, v, o);
    return v;
}
__device__ __forceinline__ float lrelu(float t){ return t > 0.f ? t : NEG_SLOPE * t; }
__device__ __forceinline__ int clamp_idx(int v){
    return ((unsigned)v < (unsigned)N_NODES) ? v : 0;
}
__device__ __forceinline__ uint32_t smem_u32(const void* p){
    uint32_t a;
    asm("{ .reg .u64 t; cvta.to.shared.u64 t, %1; cvt.u32.u64 %0, t; }" : "=r"(a) : "l"(p));
    return a;
}
// split two fp32 into packed bf16x2 hi and lo parts (k-even in low half)
__device__ __forceinline__ void split2(float f0, float f1, uint32_t& hi, uint32_t& lo){
    __nv_bfloat16 h0 = __float2bfloat16(f0);
    __nv_bfloat16 h1 = __float2bfloat16(f1);
    hi = ((uint32_t)__bfloat16_as_ushort(h1) << 16) | (uint32_t)__bfloat16_as_ushort(h0);
    __nv_bfloat16 l0 = __float2bfloat16(f0 - __bfloat162float(h0));
    __nv_bfloat16 l1 = __float2bfloat16(f1 - __bfloat162float(h1));
    lo = ((uint32_t)__bfloat16_as_ushort(l1) << 16) | (uint32_t)__bfloat16_as_ushort(l0);
}

#define LDMX4(r, addr) \
    asm volatile("ldmatrix.sync.aligned.m8n8.x4.shared.b16 {%0,%1,%2,%3}, [%4];" \
                 : "=r"((r)[0]), "=r"((r)[1]), "=r"((r)[2]), "=r"((r)[3]) : "r"(addr))

__device__ __forceinline__ void mma16816(float* c, const uint32_t* a, uint32_t b0, uint32_t b1){
    asm volatile(
        "mma.sync.aligned.m16n8k16.row.col.f32.bf16.bf16.f32 "
        "{%0,%1,%2,%3}, {%4,%5,%6,%7}, {%8,%9}, {%0,%1,%2,%3};"
        : "+f"(c[0]), "+f"(c[1]), "+f"(c[2]), "+f"(c[3])
        : "r"(a[0]), "r"(a[1]), "r"(a[2]), "r"(a[3]), "r"(b0), "r"(b1));
}

// ---------------- CSR build ----------------
__global__ void k_clear(){
    int i = blockIdx.x * blockDim.x + threadIdx.x;
    if (i < N_NODES){ g_counts[i] = 0; g_cursor[i] = 0; }
}
__global__ void k_hist(const int* __restrict__ ei){
    int e = blockIdx.x * blockDim.x + threadIdx.x;
    if (e >= EP) return;
    int dst = (e < NE) ? clamp_idx(ei[NE + e]) : (e - NE);
    atomicAdd(&g_counts[dst], 1);
}
__global__ void k_scan(){
    __shared__ int sm[1024];
    __shared__ int soff;
    int tid = threadIdx.x;
    if (tid == 0) soff = 0;
    __syncthreads();
    for (int base = 0; base < N_NODES; base += 1024){
        int idx = base + tid;
        int v = (idx < N_NODES) ? g_counts[idx] : 0;
        sm[tid] = v;
        __syncthreads();
        for (int s = 1; s < 1024; s <<= 1){
            int t = (tid >= s) ? sm[tid - s] : 0;
            __syncthreads();
            sm[tid] += t;
            __syncthreads();
        }
        if (idx < N_NODES) g_rowstart[idx] = soff + sm[tid] - v;
        int tot = sm[1023];
        __syncthreads();
        if (tid == 0) soff += tot;
        __syncthreads();
    }
    if (tid == 0) g_rowstart[N_NODES] = soff;
}
__global__ void k_scatter(const int* __restrict__ ei){
    int e = blockIdx.x * blockDim.x + threadIdx.x;
    if (e >= EP) return;
    int src, dst;
    if (e < NE){ src = clamp_idx(ei[e]); dst = clamp_idx(ei[NE + e]); }
    else       { src = e - NE;           dst = src; }
    int pos = g_rowstart[dst] + atomicAdd(&g_cursor[dst], 1);
    g_src[pos] = src;
    g_dst[pos] = dst;
}

// ---------------- weight transpose + bf16 split (once per launch) ----------------
__global__ void k_tsplit(const float* __restrict__ W, int K, int N, int ooff){
    int i = blockIdx.x * blockDim.x + threadIdx.x;
    if (i >= K * N) return;
    int k = i / N, n = i - k * N;
    float w = W[i];
    __nv_bfloat16 h = __float2bfloat16(w);
    g_bhi[ooff + (size_t)n * K + k] = h;
    g_blo[ooff + (size_t)n * K + k] = __float2bfloat16(w - __bfloat162float(h));
}

// ---------------- warp-MMA bf16 split GEMM: out[M,256] = A[M,K] @ Wt^T + bias (+GELU) -----
// CTA tile 128x128, 8 warps (4m x 2n), warp tile 32x64, BK=32.
// D = Ah*Bh + Al*Bh + Ah*Bl  (residual ~2^-17).
// SMEM rows padded to 40 bf16 (80B stride) -> conflict-free ldmatrix.
#define SROW 40
template<int GELU, int ASEL, int OSEL>
__global__ __launch_bounds__(256, 2)
void k_gemm_mma(const float* __restrict__ Aext, int boff,
                const float* __restrict__ bias, int M, int K)
{
    __shared__ __align__(16) __nv_bfloat16 sAh[128 * SROW];
    __shared__ __align__(16) __nv_bfloat16 sAl[128 * SROW];
    __shared__ __align__(16) __nv_bfloat16 sBh[128 * SROW];
    __shared__ __align__(16) __nv_bfloat16 sBl[128 * SROW];

    const float* A   = (ASEL == 0) ? Aext : (const float*)g_x;
    float*       out = (OSEL == 0) ? g_xl : g_xr;

    int tid = threadIdx.x, wid = tid >> 5, lane = tid & 31;
    int warp_m = wid & 3, warp_n = wid >> 2;
    int row0 = blockIdx.x * 128, nc0 = blockIdx.y * 128;

    float acc[2][8][4];
#pragma unroll
    for (int mt = 0; mt < 2; mt++)
#pragma unroll
        for (int nt = 0; nt < 8; nt++)
#pragma unroll
            for (int q = 0; q < 4; q++) acc[mt][nt][q] = 0.f;

    // ---- loader mapping: thread -> (row r, k-half) ----
    int r = tid >> 1, half = tid & 1;
    int grow = row0 + r;
    bool rok = grow < M;
    const float* aptr = A + (size_t)grow * K + half * 16;
    const __nv_bfloat16* bhp = g_bhi + boff + (size_t)(nc0 + r) * K + half * 16;
    const __nv_bfloat16* blp = g_blo + boff + (size_t)(nc0 + r) * K + half * 16;
    int soff = r * SROW + half * 16;

    uint32_t uAh = smem_u32(sAh), uAl = smem_u32(sAl);
    uint32_t uBh = smem_u32(sBh), uBl = smem_u32(sBl);

    // ---- ldmatrix per-lane addressing ----
    int lrow = lane & 15, lcol = (lane >> 4) * 8;
    uint32_t aBaseH = uAh + (uint32_t)(((warp_m * 32 + lrow) * SROW + lcol) * 2);
    uint32_t aBaseL = uAl + (uint32_t)(((warp_m * 32 + lrow) * SROW + lcol) * 2);
    uint32_t bBaseH = uBh + (uint32_t)(((warp_n * 64 + lrow) * SROW + lcol) * 2);
    uint32_t bBaseL = uBl + (uint32_t)(((warp_n * 64 + lrow) * SROW + lcol) * 2);

    int iters = K >> 5;
    for (int it = 0; it < iters; it++){
        int k0 = it << 5;
        // A: 16 fp32 -> split -> 8 hi u32 + 8 lo u32
        float4 f0, f1, f2, f3;
        if (rok){
            f0 = *(const float4*)(aptr + k0);
            f1 = *(const float4*)(aptr + k0 + 4);
            f2 = *(const float4*)(aptr + k0 + 8);
            f3 = *(const float4*)(aptr + k0 + 12);
        } else {
            f0 = f1 = f2 = f3 = make_float4(0.f, 0.f, 0.f, 0.f);
        }
        uint32_t h[8], l[8];
        split2(f0.x, f0.y, h[0], l[0]);  split2(f0.z, f0.w, h[1], l[1]);
        split2(f1.x, f1.y, h[2], l[2]);  split2(f1.z, f1.w, h[3], l[3]);
        split2(f2.x, f2.y, h[4], l[4]);  split2(f2.z, f2.w, h[5], l[5]);
        split2(f3.x, f3.y, h[6], l[6]);  split2(f3.z, f3.w, h[7], l[7]);

        const uint4* bhq = (const uint4*)(bhp + k0);
        const uint4* blq = (const uint4*)(blp + k0);
        uint4 bh0 = bhq[0], bh1 = bhq[1];
        uint4 bl0 = blq[0], bl1 = blq[1];

        __syncthreads();   // previous iteration's fragment reads done
        *(uint4*)(sAh + soff)     = make_uint4(h[0], h[1], h[2], h[3]);
        *(uint4*)(sAh + soff + 8) = make_uint4(h[4], h[5], h[6], h[7]);
        *(uint4*)(sAl + soff)     = make_uint4(l[0], l[1], l[2], l[3]);
        *(uint4*)(sAl + soff + 8) = make_uint4(l[4], l[5], l[6], l[7]);
        *(uint4*)(sBh + soff)     = bh0;
        *(uint4*)(sBh + soff + 8) = bh1;
        *(uint4*)(sBl + soff)     = bl0;
        *(uint4*)(sBl + soff + 8) = bl1;
        __syncthreads();

#pragma unroll
        for (int kc = 0; kc < 2; kc++){
            uint32_t ah[2][4], al[2][4];
#pragma unroll
            for (int mt = 0; mt < 2; mt++){
                LDMX4(ah[mt], aBaseH + (uint32_t)((mt * 16 * SROW + kc * 16) * 2));
                LDMX4(al[mt], aBaseL + (uint32_t)((mt * 16 * SROW + kc * 16) * 2));
            }
#pragma unroll
            for (int nt2 = 0; nt2 < 4; nt2++){
                uint32_t bh[4], bl[4];
                LDMX4(bh, bBaseH + (uint32_t)((nt2 * 16 * SROW + kc * 16) * 2));
                LDMX4(bl, bBaseL + (uint32_t)((nt2 * 16 * SROW + kc * 16) * 2));
#pragma unroll
                for (int p = 0; p < 2; p++){
                    int nt = nt2 * 2 + p;
                    uint32_t b0h = bh[p], b1h = bh[p + 2];
                    uint32_t b0l = bl[p], b1l = bl[p + 2];
#pragma unroll
                    for (int mt = 0; mt < 2; mt++){
                        mma16816(acc[mt][nt], ah[mt], b0h, b1h);   // hi*hi
                        mma16816(acc[mt][nt], al[mt], b0h, b1h);   // lo*hi
                        mma16816(acc[mt][nt], ah[mt], b0l, b1l);   // hi*lo
                    }
                }
            }
        }
    }

    // ---------------- epilogue: bias (+GELU), fp32 store ----------------
    int groupID = lane >> 2, tig = lane & 3;
#pragma unroll
    for (int mt = 0; mt < 2; mt++){
        int ra = row0 + warp_m * 32 + mt * 16 + groupID;
        int rb = ra + 8;
#pragma unroll
        for (int nt = 0; nt < 8; nt++){
            int col = nc0 + warp_n * 64 + nt * 8 + tig * 2;
            float b0 = bias[col], b1 = bias[col + 1];
            float v0 = acc[mt][nt][0] + b0, v1 = acc[mt][nt][1] + b1;
            float v2 = acc[mt][nt][2] + b0, v3 = acc[mt][nt][3] + b1;
            if (GELU){
                v0 = 0.5f * v0 * (1.f + erff(v0 * 0.70710678118654752440f));
                v1 = 0.5f * v1 * (1.f + erff(v1 * 0.70710678118654752440f));
                v2 = 0.5f * v2 * (1.f + erff(v2 * 0.70710678118654752440f));
                v3 = 0.5f * v3 * (1.f + erff(v3 * 0.70710678118654752440f));
            }
            if (ra < M){
                out[(size_t)ra * HID + col]     = v0;
                out[(size_t)ra * HID + col + 1] = v1;
            }
            if (rb < M){
                out[(size_t)rb * HID + col]     = v2;
                out[(size_t)rb * HID + col + 1] = v3;
            }
        }
    }
}

// ---------------- LayerNorm (proj output): g_x = LN(g_xl) ----------------
__global__ void k_ln(const float* __restrict__ g, const float* __restrict__ b){
    int gw = (int)((blockIdx.x * blockDim.x + threadIdx.x) >> 5);
    if (gw >= N_NODES) return;
    int lane = threadIdx.x & 31, d = lane * 8;
    const float4* p = (const float4*)(g_xl + (size_t)gw * HID + d);
    float4 v0 = p[0], v1 = p[1];
    float v[8] = {v0.x, v0.y, v0.z, v0.w, v1.x, v1.y, v1.z, v1.w};
    float s = 0.f, ss = 0.f;
#pragma unroll
    for (int q = 0; q < 8; q++){ s += v[q]; ss += v[q] * v[q]; }
    s  = warp_sum32(s);
    ss = warp_sum32(ss);
    float mu  = s  * (1.f / 256.f);
    float var = ss * (1.f / 256.f) - mu * mu;
    float inv = rsqrtf(var + LN_EPS);
    float* op = g_x + (size_t)gw * HID + d;
#pragma unroll
    for (int q = 0; q < 8; q++)
        op[q] = (v[q] - mu) * inv * g[d + q] + b[d + q];
}

// ---------------- edge logits ----------------
__global__ void k_logits_kern(const float* __restrict__ att){
    int gw = (int)((blockIdx.x * blockDim.x + threadIdx.x) >> 5);
    if (gw >= EP) return;
    int lane = threadIdx.x & 31;
    int src = g_src[gw], dst = g_dst[gw];
    int d = lane * 8;
    const float4* pl = (const float4*)(g_xl + (size_t)src * HID + d);
    const float4* pr = (const float4*)(g_xr + (size_t)dst * HID + d);
    float4 l0 = pl[0], l1 = pl[1];
    float4 r0 = pr[0], r1 = pr[1];
    const float4* pa = (const float4*)(att + d);
    float4 a0 = __ldg(pa), a1 = __ldg(pa + 1);

    float acc = 0.f;
    acc = fmaf(lrelu(l0.x + r0.x), a0.x, acc);
    acc = fmaf(lrelu(l0.y + r0.y), a0.y, acc);
    acc = fmaf(lrelu(l0.z + r0.z), a0.z, acc);
    acc = fmaf(lrelu(l0.w + r0.w), a0.w, acc);
    acc = fmaf(lrelu(l1.x + r1.x), a1.x, acc);
    acc = fmaf(lrelu(l1.y + r1.y), a1.y, acc);
    acc = fmaf(lrelu(l1.z + r1.z), a1.z, acc);
    acc = fmaf(lrelu(l1.w + r1.w), a1.w, acc);

    acc += __shfl_xor_sync(0xffffffffu, acc, 1);
    acc += __shfl_xor_sync(0xffffffffu, acc, 2);
    acc += __shfl_xor_sync(0xffffffffu, acc, 4);
    if ((lane & 7) == 0) g_logits[(size_t)gw * HEADS + (lane >> 3)] = acc;
}

// ---------------- softmax per (node, head) ----------------
__global__ void k_softmax(){
    int t = blockIdx.x * blockDim.x + threadIdx.x;
    if (t >= N_NODES * HEADS) return;
    int n = t >> 2, h = t & 3;
    int s = g_rowstart[n], e = g_rowstart[n + 1];
    float m = -1e30f;
    for (int j = s; j < e; j++) m = fmaxf(m, g_logits[(size_t)j * HEADS + h]);
    float sum = 0.f;
    for (int j = s; j < e; j++){
        float ex = expf(g_logits[(size_t)j * HEADS + h] - m);
        g_logits[(size_t)j * HEADS + h] = ex;
        sum += ex;
    }
    float inv = 1.f / sum;
    for (int j = s; j < e; j++) g_logits[(size_t)j * HEADS + h] *= inv;
}

// ---------------- aggregate + gbias + residual + LayerNorm ----------------
__global__ void k_agg_ln(const float* __restrict__ gbias,
                         const float* __restrict__ lng,
                         const float* __restrict__ lnb){
    int gw = (int)((blockIdx.x * blockDim.x + threadIdx.x) >> 5);
    if (gw >= N_NODES) return;
    int lane = threadIdx.x & 31;
    int s = g_rowstart[gw], e = g_rowstart[gw + 1];
    int d = lane * 8;
    int hh = lane >> 3;
    float4 acc0 = make_float4(0.f, 0.f, 0.f, 0.f);
    float4 acc1 = make_float4(0.f, 0.f, 0.f, 0.f);
    for (int j = s; j < e; j++){
        int src = g_src[j];
        float a = g_logits[(size_t)j * HEADS + hh];
        const float4* p = (const float4*)(g_xl + (size_t)src * HID + d);
        float4 v0 = p[0], v1 = p[1];
        acc0.x = fmaf(v0.x, a, acc0.x);  acc0.y = fmaf(v0.y, a, acc0.y);
        acc0.z = fmaf(v0.z, a, acc0.z);  acc0.w = fmaf(v0.w, a, acc0.w);
        acc1.x = fmaf(v1.x, a, acc1.x);  acc1.y = fmaf(v1.y, a, acc1.y);
        acc1.z = fmaf(v1.z, a, acc1.z);  acc1.w = fmaf(v1.w, a, acc1.w);
    }
    float* xp = g_x + (size_t)gw * HID + d;
    float v[8];
    v[0] = acc0.x + gbias[d + 0] + xp[0];
    v[1] = acc0.y + gbias[d + 1] + xp[1];
    v[2] = acc0.z + gbias[d + 2] + xp[2];
    v[3] = acc0.w + gbias[d + 3] + xp[3];
    v[4] = acc1.x + gbias[d + 4] + xp[4];
    v[5] = acc1.y + gbias[d + 5] + xp[5];
    v[6] = acc1.z + gbias[d + 6] + xp[6];
    v[7] = acc1.w + gbias[d + 7] + xp[7];
    float sm = 0.f, ss = 0.f;
#pragma unroll
    for (int q = 0; q < 8; q++){ sm += v[q]; ss += v[q] * v[q]; }
    sm = warp_sum32(sm);
    ss = warp_sum32(ss);
    float mu  = sm * (1.f / 256.f);
    float var = ss * (1.f / 256.f) - mu * mu;
    float inv = rsqrtf(var + LN_EPS);
#pragma unroll
    for (int q = 0; q < 8; q++)
        xp[q] = (v[q] - mu) * inv * lng[d + q] + lnb[d + q];
}

// ---------------- head 2 ----------------
__global__ void k_head2(const float* __restrict__ W2, const float* __restrict__ b2,
                        float* __restrict__ out){
    __shared__ float ws[HID * NCLS];
    int tid = threadIdx.x;
    for (int i = tid; i < HID * NCLS; i += blockDim.x) ws[i] = W2[i];
    __syncthreads();
    int gw = (int)((blockIdx.x * blockDim.x + tid) >> 5);
    if (gw >= N_NODES) return;
    int lane = tid & 31;
    const float* row = g_xl + (size_t)gw * HID;
    float a0 = 0.f, a1 = 0.f, a2 = 0.f;
#pragma unroll
    for (int q = 0; q < 8; q++){
        int k = lane + 32 * q;
        float xv = row[k];
        a0 = fmaf(xv, ws[k * 3 + 0], a0);
        a1 = fmaf(xv, ws[k * 3 + 1], a1);
        a2 = fmaf(xv, ws[k * 3 + 2], a2);
    }
    a0 = warp_sum32(a0); a1 = warp_sum32(a1); a2 = warp_sum32(a2);
    if (lane == 0){
        out[(size_t)gw * NCLS + 0] = a0 + b2[0];
        out[(size_t)gw * NCLS + 1] = a1 + b2[1];
        out[(size_t)gw * NCLS + 2] = a2 + b2[2];
    }
}

// ---------------- launch ----------------
extern "C" void kernel_launch(void* const* d_in, const int* in_sizes, int n_in,
                              void* d_out, int out_size)
{
    const float* features = (const float*)d_in[0];
    const int*   ei       = (const int*)d_in[1];     // int32 (JAX x64 disabled)
    const float* proj_W = (const float*)d_in[2];
    const float* proj_b = (const float*)d_in[3];
    const float* n0_g   = (const float*)d_in[4];
    const float* n0_b   = (const float*)d_in[5];
    const float* Wl     = (const float*)d_in[6];
    const float* bl     = (const float*)d_in[7];
    const float* Wr     = (const float*)d_in[8];
    const float* br     = (const float*)d_in[9];
    const float* att    = (const float*)d_in[10];
    const float* gbias  = (const float*)d_in[11];
    const float* ln_g   = (const float*)d_in[12];
    const float* ln_b   = (const float*)d_in[13];
    const float* h1_W   = (const float*)d_in[14];
    const float* h1_b   = (const float*)d_in[15];
    const float* h2_W   = (const float*)d_in[16];
    const float* h2_b   = (const float*)d_in[17];
    float* out = (float*)d_out;

    // CSR build
    k_clear  <<<(N_NODES + 255) / 256, 256>>>();
    k_hist   <<<(EP + 255) / 256, 256>>>(ei);
    k_scan   <<<1, 1024>>>();
    k_scatter<<<(EP + 255) / 256, 256>>>(ei);

    // weight transpose + split
    k_tsplit<<<(IN_DIM * HID) / 256, 256>>>(proj_W, IN_DIM, HID, OFF_PROJ);
    for (int h = 0; h < HOPS; h++){
        k_tsplit<<<(HID * HID) / 256, 256>>>(Wl + (size_t)h * HID * HID, HID, HID, OFF_WL + h * HID * HID);
        k_tsplit<<<(HID * HID) / 256, 256>>>(Wr + (size_t)h * HID * HID, HID, HID, OFF_WR + h * HID * HID);
    }
    k_tsplit<<<(HID * HID) / 256, 256>>>(h1_W, HID, HID, OFF_H1);

    const dim3 GG((N_NODES + 127) / 128, 2);   // 157 x 2 tiles

    // x = LN(features @ proj_W + proj_b)
    k_gemm_mma<0, 0, 0><<<GG, 256>>>(features, OFF_PROJ, proj_b, N_NODES, IN_DIM);
    k_ln<<<(N_NODES * 32 + 255) / 256, 256>>>(n0_g, n0_b);

    for (int h = 0; h < HOPS; h++){
        k_gemm_mma<0, 1, 0><<<GG, 256>>>(nullptr, OFF_WL + h * HID * HID, bl + h * HID, N_NODES, HID);
        k_gemm_mma<0, 1, 1><<<GG, 256>>>(nullptr, OFF_WR + h * HID * HID, br + h * HID, N_NODES, HID);
        k_logits_kern<<<(EP * 32 + 255) / 256, 256>>>(att + h * HEADS * (HID / HEADS));
        k_softmax<<<(N_NODES * HEADS + 255) / 256, 256>>>();
        k_agg_ln<<<(N_NODES * 32 + 255) / 256, 256>>>(gbias + h * HID, ln_g + h * HID, ln_b + h * HID);
    }

    // head: gelu(x @ h1_W + h1_b) -> g_xl ; then @ h2_W + h2_b -> out
    k_gemm_mma<1, 1, 0><<<GG, 256>>>(nullptr, OFF_H1, h1_b, N_NODES, HID);
    k_head2<<<(N_NODES * 32 + 255) / 256, 256>>>(h2_W, h2_b, out);

    (void)in_sizes; (void)n_in; (void)out_size;
}

// round 10
// speedup vs baseline: 1.9408x; 1.2012x over previous
#include <cuda_runtime.h>
#include <cuda_bf16.h>
#include <cstdint>
#include <cstddef>

#define N_NODES 20000
#define IN_DIM  1536
#define HID     256
#define HEADS   4
#define HOPS    3
#define NCLS    3
#define NE      320000
#define EP      (NE + N_NODES)     /* 340000 edges incl. self loops */
#define LN_EPS  1e-5f
#define NEG_SLOPE 0.2f

// weight arena offsets (bf16 elements), all K-major transposed: Wt[n][k] = W[k][n]
#define OFF_PROJ 0                         /* 256 x 1536 */
#define OFF_WL   393216                    /* 3 x 256 x 256 */
#define OFF_WR   589824                    /* 3 x 256 x 256 */
#define OFF_H1   786432                    /* 256 x 256 */
#define W_ARENA  851968

// ---------------- scratch (static device globals: no runtime allocation) ----------------
__device__ float g_x [N_NODES * HID];
__device__ float g_xl[N_NODES * HID];     // also head1 out
__device__ float g_xr[N_NODES * HID];
__device__ int   g_rowstart[N_NODES + 1];
__device__ int   g_counts[N_NODES];
__device__ int   g_cursor[N_NODES];
__device__ int   g_src[EP];
__device__ __nv_bfloat16 g_bhi[W_ARENA];          // weight hi split (K-major)
__device__ __nv_bfloat16 g_blo[W_ARENA];          // weight lo split
__device__ __nv_bfloat16 g_ahi[N_NODES * IN_DIM]; // activation hi split
__device__ __nv_bfloat16 g_alo[N_NODES * IN_DIM]; // activation lo split

// ---------------- small helpers ----------------
__device__ __forceinline__ float warp_sum32(float v){
#pragma unroll
    for (int o = 16; o > 0; o >>= 1) v += __shfl_xor_sync(0xffffffffu, v, o);
    return v;
}
__device__ __forceinline__ float lrelu(float t){ return t > 0.f ? t : NEG_SLOPE * t; }
__device__ __forceinline__ int clamp_idx(int v){
    return ((unsigned)v < (unsigned)N_NODES) ? v : 0;
}
__device__ __forceinline__ uint32_t smem_u32(const void* p){
    uint32_t a;
    asm("{ .reg .u64 t; cvta.to.shared.u64 t, %1; cvt.u32.u64 %0, t; }" : "=r"(a) : "l"(p));
    return a;
}
// split two fp32 into packed bf16x2 hi and lo parts (k-even in low half)
__device__ __forceinline__ void split2(float f0, float f1, uint32_t& hi, uint32_t& lo){
    __nv_bfloat16 h0 = __float2bfloat16(f0);
    __nv_bfloat16 h1 = __float2bfloat16(f1);
    hi = ((uint32_t)__bfloat16_as_ushort(h1) << 16) | (uint32_t)__bfloat16_as_ushort(h0);
    __nv_bfloat16 l0 = __float2bfloat16(f0 - __bfloat162float(h0));
    __nv_bfloat16 l1 = __float2bfloat16(f1 - __bfloat162float(h1));
    lo = ((uint32_t)__bfloat16_as_ushort(l1) << 16) | (uint32_t)__bfloat16_as_ushort(l0);
}

#define LDMX4(r, addr) \
    asm volatile("ldmatrix.sync.aligned.m8n8.x4.shared.b16 {%0,%1,%2,%3}, [%4];" \
                 : "=r"((r)[0]), "=r"((r)[1]), "=r"((r)[2]), "=r"((r)[3]) : "r"(addr))

__device__ __forceinline__ void mma16816(float* c, const uint32_t* a, uint32_t b0, uint32_t b1){
    asm volatile(
        "mma.sync.aligned.m16n8k16.row.col.f32.bf16.bf16.f32 "
        "{%0,%1,%2,%3}, {%4,%5,%6,%7}, {%8,%9}, {%0,%1,%2,%3};"
        : "+f"(c[0]), "+f"(c[1]), "+f"(c[2]), "+f"(c[3])
        : "r"(a[0]), "r"(a[1]), "r"(a[2]), "r"(a[3]), "r"(b0), "r"(b1));
}

// ---------------- CSR build ----------------
__global__ void k_clear(){
    int i = blockIdx.x * blockDim.x + threadIdx.x;
    if (i < N_NODES){ g_counts[i] = 0; g_cursor[i] = 0; }
}
__global__ void k_hist(const int* __restrict__ ei){
    int e = blockIdx.x * blockDim.x + threadIdx.x;
    if (e >= EP) return;
    int dst = (e < NE) ? clamp_idx(ei[NE + e]) : (e - NE);
    atomicAdd(&g_counts[dst], 1);
}
__global__ void k_scan(){
    __shared__ int sm[1024];
    __shared__ int soff;
    int tid = threadIdx.x;
    if (tid == 0) soff = 0;
    __syncthreads();
    for (int base = 0; base < N_NODES; base += 1024){
        int idx = base + tid;
        int v = (idx < N_NODES) ? g_counts[idx] : 0;
        sm[tid] = v;
        __syncthreads();
        for (int s = 1; s < 1024; s <<= 1){
            int t = (tid >= s) ? sm[tid - s] : 0;
            __syncthreads();
            sm[tid] += t;
            __syncthreads();
        }
        if (idx < N_NODES) g_rowstart[idx] = soff + sm[tid] - v;
        int tot = sm[1023];
        __syncthreads();
        if (tid == 0) soff += tot;
        __syncthreads();
    }
    if (tid == 0) g_rowstart[N_NODES] = soff;
}
__global__ void k_scatter(const int* __restrict__ ei){
    int e = blockIdx.x * blockDim.x + threadIdx.x;
    if (e >= EP) return;
    int src, dst;
    if (e < NE){ src = clamp_idx(ei[e]); dst = clamp_idx(ei[NE + e]); }
    else       { src = e - NE;           dst = src; }
    int pos = g_rowstart[dst] + atomicAdd(&g_cursor[dst], 1);
    g_src[pos] = src;
}

// ---------------- weight transpose + bf16 split (once per launch) ----------------
__global__ void k_tsplit(const float* __restrict__ W, int K, int N, int ooff){
    int i = blockIdx.x * blockDim.x + threadIdx.x;
    if (i >= K * N) return;
    int k = i / N, n = i - k * N;
    float w = W[i];
    __nv_bfloat16 h = __float2bfloat16(w);
    g_bhi[ooff + (size_t)n * K + k] = h;
    g_blo[ooff + (size_t)n * K + k] = __float2bfloat16(w - __bfloat162float(h));
}

// ---------------- activation bf16 split: g_ahi/g_alo = split(A), vectorized x4 ------------
// SRC: 0 = external pointer (features), 1 = g_x (device global resolved IN DEVICE CODE)
template<int SRC>
__global__ void k_asplit(const float* __restrict__ Aext, int total4){
    int i = blockIdx.x * blockDim.x + threadIdx.x;
    if (i >= total4) return;
    const float* A = (SRC == 0) ? Aext : (const float*)g_x;
    float4 f = ((const float4*)A)[i];
    uint32_t h0, l0, h1, l1;
    split2(f.x, f.y, h0, l0);
    split2(f.z, f.w, h1, l1);
    ((uint2*)g_ahi)[i] = make_uint2(h0, h1);
    ((uint2*)g_alo)[i] = make_uint2(l0, l1);
}

// ---------------- warp-MMA bf16 split GEMM: out[M,256] = A[M,K] @ Wt^T + bias (+GELU) -----
// CTA tile 128x128, 8 warps (4m x 2n), warp tile 32x64, BK=32.
// D = Ah*Bh + Al*Bh + Ah*Bl  (residual ~2^-17). A read pre-split from g_ahi/g_alo.
// SMEM rows padded to 40 bf16 (80B stride) -> conflict-free ldmatrix.
#define SROW 40
template<int GELU, int OSEL>
__global__ __launch_bounds__(256, 2)
void k_gemm_mma(int boff, const float* __restrict__ bias, int M, int K)
{
    __shared__ __align__(16) __nv_bfloat16 sAh[128 * SROW];
    __shared__ __align__(16) __nv_bfloat16 sAl[128 * SROW];
    __shared__ __align__(16) __nv_bfloat16 sBh[128 * SROW];
    __shared__ __align__(16) __nv_bfloat16 sBl[128 * SROW];

    float* out = (OSEL == 0) ? g_xl : g_xr;

    int tid = threadIdx.x, wid = tid >> 5, lane = tid & 31;
    int warp_m = wid & 3, warp_n = wid >> 2;
    int row0 = blockIdx.x * 128, nc0 = blockIdx.y * 128;

    float acc[2][8][4];
#pragma unroll
    for (int mt = 0; mt < 2; mt++)
#pragma unroll
        for (int nt = 0; nt < 8; nt++)
#pragma unroll
            for (int q = 0; q < 4; q++) acc[mt][nt][q] = 0.f;

    // ---- loader mapping: thread -> (row r, k-half) ----
    int r = tid >> 1, half = tid & 1;
    int grow = row0 + r;
    bool rok = grow < M;
    const __nv_bfloat16* ahp = g_ahi + (size_t)grow * K + half * 16;
    const __nv_bfloat16* alp = g_alo + (size_t)grow * K + half * 16;
    const __nv_bfloat16* bhp = g_bhi + boff + (size_t)(nc0 + r) * K + half * 16;
    const __nv_bfloat16* blp = g_blo + boff + (size_t)(nc0 + r) * K + half * 16;
    int soff = r * SROW + half * 16;

    uint32_t uAh = smem_u32(sAh), uAl = smem_u32(sAl);
    uint32_t uBh = smem_u32(sBh), uBl = smem_u32(sBl);

    // ---- ldmatrix per-lane addressing ----
    int lrow = lane & 15, lcol = (lane >> 4) * 8;
    uint32_t aBaseH = uAh + (uint32_t)(((warp_m * 32 + lrow) * SROW + lcol) * 2);
    uint32_t aBaseL = uAl + (uint32_t)(((warp_m * 32 + lrow) * SROW + lcol) * 2);
    uint32_t bBaseH = uBh + (uint32_t)(((warp_n * 64 + lrow) * SROW + lcol) * 2);
    uint32_t bBaseL = uBl + (uint32_t)(((warp_n * 64 + lrow) * SROW + lcol) * 2);

    int iters = K >> 5;
    for (int it = 0; it < iters; it++){
        int k0 = it << 5;
        uint4 z = make_uint4(0u, 0u, 0u, 0u);
        uint4 ah0 = z, ah1 = z, al0 = z, al1 = z;
        if (rok){
            const uint4* ahq = (const uint4*)(ahp + k0);
            const uint4* alq = (const uint4*)(alp + k0);
            ah0 = ahq[0];  ah1 = ahq[1];
            al0 = alq[0];  al1 = alq[1];
        }
        const uint4* bhq = (const uint4*)(bhp + k0);
        const uint4* blq = (const uint4*)(blp + k0);
        uint4 bh0 = bhq[0], bh1 = bhq[1];
        uint4 bl0 = blq[0], bl1 = blq[1];

        __syncthreads();   // previous iteration's fragment reads done
        *(uint4*)(sAh + soff)     = ah0;
        *(uint4*)(sAh + soff + 8) = ah1;
        *(uint4*)(sAl + soff)     = al0;
        *(uint4*)(sAl + soff + 8) = al1;
        *(uint4*)(sBh + soff)     = bh0;
        *(uint4*)(sBh + soff + 8) = bh1;
        *(uint4*)(sBl + soff)     = bl0;
        *(uint4*)(sBl + soff + 8) = bl1;
        __syncthreads();

#pragma unroll
        for (int kc = 0; kc < 2; kc++){
            uint32_t ah[2][4], al[2][4];
#pragma unroll
            for (int mt = 0; mt < 2; mt++){
                LDMX4(ah[mt], aBaseH + (uint32_t)((mt * 16 * SROW + kc * 16) * 2));
                LDMX4(al[mt], aBaseL + (uint32_t)((mt * 16 * SROW + kc * 16) * 2));
            }
#pragma unroll
            for (int nt2 = 0; nt2 < 4; nt2++){
                uint32_t bh[4], bl[4];
                LDMX4(bh, bBaseH + (uint32_t)((nt2 * 16 * SROW + kc * 16) * 2));
                LDMX4(bl, bBaseL + (uint32_t)((nt2 * 16 * SROW + kc * 16) * 2));
#pragma unroll
                for (int p = 0; p < 2; p++){
                    int nt = nt2 * 2 + p;
                    uint32_t b0h = bh[p], b1h = bh[p + 2];
                    uint32_t b0l = bl[p], b1l = bl[p + 2];
#pragma unroll
                    for (int mt = 0; mt < 2; mt++){
                        mma16816(acc[mt][nt], ah[mt], b0h, b1h);   // hi*hi
                        mma16816(acc[mt][nt], al[mt], b0h, b1h);   // lo*hi
                        mma16816(acc[mt][nt], ah[mt], b0l, b1l);   // hi*lo
                    }
                }
            }
        }
    }

    // ---------------- epilogue: bias (+GELU), fp32 store ----------------
    int groupID = lane >> 2, tig = lane & 3;
#pragma unroll
    for (int mt = 0; mt < 2; mt++){
        int ra = row0 + warp_m * 32 + mt * 16 + groupID;
        int rb = ra + 8;
#pragma unroll
        for (int nt = 0; nt < 8; nt++){
            int col = nc0 + warp_n * 64 + nt * 8 + tig * 2;
            float b0 = bias[col], b1 = bias[col + 1];
            float v0 = acc[mt][nt][0] + b0, v1 = acc[mt][nt][1] + b1;
            float v2 = acc[mt][nt][2] + b0, v3 = acc[mt][nt][3] + b1;
            if (GELU){
                v0 = 0.5f * v0 * (1.f + erff(v0 * 0.70710678118654752440f));
                v1 = 0.5f * v1 * (1.f + erff(v1 * 0.70710678118654752440f));
                v2 = 0.5f * v2 * (1.f + erff(v2 * 0.70710678118654752440f));
                v3 = 0.5f * v3 * (1.f + erff(v3 * 0.70710678118654752440f));
            }
            if (ra < M){
                out[(size_t)ra * HID + col]     = v0;
                out[(size_t)ra * HID + col + 1] = v1;
            }
            if (rb < M){
                out[(size_t)rb * HID + col]     = v2;
                out[(size_t)rb * HID + col + 1] = v3;
            }
        }
    }
}

// ---------------- LayerNorm (proj output): g_x = LN(g_xl) ----------------
__global__ void k_ln(const float* __restrict__ g, const float* __restrict__ b){
    int gw = (int)((blockIdx.x * blockDim.x + threadIdx.x) >> 5);
    if (gw >= N_NODES) return;
    int lane = threadIdx.x & 31, d = lane * 8;
    const float4* p = (const float4*)(g_xl + (size_t)gw * HID + d);
    float4 v0 = p[0], v1 = p[1];
    float v[8] = {v0.x, v0.y, v0.z, v0.w, v1.x, v1.y, v1.z, v1.w};
    float s = 0.f, ss = 0.f;
#pragma unroll
    for (int q = 0; q < 8; q++){ s += v[q]; ss += v[q] * v[q]; }
    s  = warp_sum32(s);
    ss = warp_sum32(ss);
    float mu  = s  * (1.f / 256.f);
    float var = ss * (1.f / 256.f) - mu * mu;
    float inv = rsqrtf(var + LN_EPS);
    float* op = g_x + (size_t)gw * HID + d;
#pragma unroll
    for (int q = 0; q < 8; q++)
        op[q] = (v[q] - mu) * inv * g[d + q] + b[d + q];
}

// ---------------- fused GAT hop: online softmax + aggregate + gbias + residual + LN -------
// One warp per dst node; lane owns 8 dims (all within one head: head = lane>>3).
// Online softmax over the CSR segment is algebraically identical to segment max/exp/sum.
__global__ void k_gat(const float* __restrict__ att,
                      const float* __restrict__ gbias,
                      const float* __restrict__ lng,
                      const float* __restrict__ lnb){
    int gw = (int)((blockIdx.x * blockDim.x + threadIdx.x) >> 5);
    if (gw >= N_NODES) return;
    int lane = threadIdx.x & 31, d = lane * 8;

    const float4* pr = (const float4*)(g_xr + (size_t)gw * HID + d);
    float4 r0 = pr[0], r1 = pr[1];
    const float4* pa = (const float4*)(att + d);
    float4 a0 = __ldg(pa), a1 = __ldg(pa + 1);

    float m = -1e30f, denom = 0.f;
    float acc[8] = {0.f, 0.f, 0.f, 0.f, 0.f, 0.f, 0.f, 0.f};

    int s = g_rowstart[gw], e = g_rowstart[gw + 1];
    for (int j = s; j < e; j++){
        int src = g_src[j];
        const float4* pl = (const float4*)(g_xl + (size_t)src * HID + d);
        float4 l0 = pl[0], l1 = pl[1];

        float t = 0.f;
        t = fmaf(lrelu(l0.x + r0.x), a0.x, t);
        t = fmaf(lrelu(l0.y + r0.y), a0.y, t);
        t = fmaf(lrelu(l0.z + r0.z), a0.z, t);
        t = fmaf(lrelu(l0.w + r0.w), a0.w, t);
        t = fmaf(lrelu(l1.x + r1.x), a1.x, t);
        t = fmaf(lrelu(l1.y + r1.y), a1.y, t);
        t = fmaf(lrelu(l1.z + r1.z), a1.z, t);
        t = fmaf(lrelu(l1.w + r1.w), a1.w, t);
        // reduce within the 8-lane head group (all lanes end with the head logit)
        t += __shfl_xor_sync(0xffffffffu, t, 1);
        t += __shfl_xor_sync(0xffffffffu, t, 2);
        t += __shfl_xor_sync(0xffffffffu, t, 4);

        float mn = fmaxf(m, t);
        float sc = expf(m - mn);      // first iter: expf(-inf) = 0
        float w  = expf(t - mn);
        denom = fmaf(denom, sc, w);
        acc[0] = fmaf(acc[0], sc, w * l0.x);
        acc[1] = fmaf(acc[1], sc, w * l0.y);
        acc[2] = fmaf(acc[2], sc, w * l0.z);
        acc[3] = fmaf(acc[3], sc, w * l0.w);
        acc[4] = fmaf(acc[4], sc, w * l1.x);
        acc[5] = fmaf(acc[5], sc, w * l1.y);
        acc[6] = fmaf(acc[6], sc, w * l1.z);
        acc[7] = fmaf(acc[7], sc, w * l1.w);
        m = mn;
    }

    float inv = 1.f / denom;
    float* xp = g_x + (size_t)gw * HID + d;
    float v[8];
#pragma unroll
    for (int q = 0; q < 8; q++) v[q] = fmaf(acc[q], inv, gbias[d + q] + xp[q]);

    float sm = 0.f, ss = 0.f;
#pragma unroll
    for (int q = 0; q < 8; q++){ sm += v[q]; ss += v[q] * v[q]; }
    sm = warp_sum32(sm);
    ss = warp_sum32(ss);
    float mu  = sm * (1.f / 256.f);
    float var = ss * (1.f / 256.f) - mu * mu;
    float rin = rsqrtf(var + LN_EPS);
#pragma unroll
    for (int q = 0; q < 8; q++)
        xp[q] = (v[q] - mu) * rin * lng[d + q] + lnb[d + q];
}

// ---------------- head 2 ----------------
__global__ void k_head2(const float* __restrict__ W2, const float* __restrict__ b2,
                        float* __restrict__ out){
    __shared__ float ws[HID * NCLS];
    int tid = threadIdx.x;
    for (int i = tid; i < HID * NCLS; i += blockDim.x) ws[i] = W2[i];
    __syncthreads();
    int gw = (int)((blockIdx.x * blockDim.x + tid) >> 5);
    if (gw >= N_NODES) return;
    int lane = tid & 31;
    const float* row = g_xl + (size_t)gw * HID;
    float a0 = 0.f, a1 = 0.f, a2 = 0.f;
#pragma unroll
    for (int q = 0; q < 8; q++){
        int k = lane + 32 * q;
        float xv = row[k];
        a0 = fmaf(xv, ws[k * 3 + 0], a0);
        a1 = fmaf(xv, ws[k * 3 + 1], a1);
        a2 = fmaf(xv, ws[k * 3 + 2], a2);
    }
    a0 = warp_sum32(a0); a1 = warp_sum32(a1); a2 = warp_sum32(a2);
    if (lane == 0){
        out[(size_t)gw * NCLS + 0] = a0 + b2[0];
        out[(size_t)gw * NCLS + 1] = a1 + b2[1];
        out[(size_t)gw * NCLS + 2] = a2 + b2[2];
    }
}

// ---------------- launch ----------------
extern "C" void kernel_launch(void* const* d_in, const int* in_sizes, int n_in,
                              void* d_out, int out_size)
{
    const float* features = (const float*)d_in[0];
    const int*   ei       = (const int*)d_in[1];     // int32 (JAX x64 disabled)
    const float* proj_W = (const float*)d_in[2];
    const float* proj_b = (const float*)d_in[3];
    const float* n0_g   = (const float*)d_in[4];
    const float* n0_b   = (const float*)d_in[5];
    const float* Wl     = (const float*)d_in[6];
    const float* bl     = (const float*)d_in[7];
    const float* Wr     = (const float*)d_in[8];
    const float* br     = (const float*)d_in[9];
    const float* att    = (const float*)d_in[10];
    const float* gbias  = (const float*)d_in[11];
    const float* ln_g   = (const float*)d_in[12];
    const float* ln_b   = (const float*)d_in[13];
    const float* h1_W   = (const float*)d_in[14];
    const float* h1_b   = (const float*)d_in[15];
    const float* h2_W   = (const float*)d_in[16];
    const float* h2_b   = (const float*)d_in[17];
    float* out = (float*)d_out;

    // CSR build
    k_clear  <<<(N_NODES + 255) / 256, 256>>>();
    k_hist   <<<(EP + 255) / 256, 256>>>(ei);
    k_scan   <<<1, 1024>>>();
    k_scatter<<<(EP + 255) / 256, 256>>>(ei);

    // weight transpose + split
    k_tsplit<<<(IN_DIM * HID) / 256, 256>>>(proj_W, IN_DIM, HID, OFF_PROJ);
    for (int h = 0; h < HOPS; h++){
        k_tsplit<<<(HID * HID) / 256, 256>>>(Wl + (size_t)h * HID * HID, HID, HID, OFF_WL + h * HID * HID);
        k_tsplit<<<(HID * HID) / 256, 256>>>(Wr + (size_t)h * HID * HID, HID, HID, OFF_WR + h * HID * HID);
    }
    k_tsplit<<<(HID * HID) / 256, 256>>>(h1_W, HID, HID, OFF_H1);

    const dim3 GG((N_NODES + 127) / 128, 2);   // 157 x 2 tiles
    const int T4F = (N_NODES * IN_DIM) / 4;    // feature split quads
    const int T4X = (N_NODES * HID) / 4;       // hidden split quads

    // x = LN(features @ proj_W + proj_b)
    k_asplit<0><<<(T4F + 255) / 256, 256>>>(features, T4F);
    k_gemm_mma<0, 0><<<GG, 256>>>(OFF_PROJ, proj_b, N_NODES, IN_DIM);
    k_ln<<<(N_NODES * 32 + 255) / 256, 256>>>(n0_g, n0_b);

    for (int h = 0; h < HOPS; h++){
        k_asplit<1><<<(T4X + 255) / 256, 256>>>(nullptr, T4X);
        k_gemm_mma<0, 0><<<GG, 256>>>(OFF_WL + h * HID * HID, bl + h * HID, N_NODES, HID);
        k_gemm_mma<0, 1><<<GG, 256>>>(OFF_WR + h * HID * HID, br + h * HID, N_NODES, HID);
        k_gat<<<(N_NODES * 32 + 255) / 256, 256>>>(att + h * HEADS * (HID / HEADS),
                                                   gbias + h * HID, ln_g + h * HID, ln_b + h * HID);
    }

    // head: gelu(x @ h1_W + h1_b) -> g_xl ; then @ h2_W + h2_b -> out
    k_asplit<1><<<(T4X + 255) / 256, 256>>>(nullptr, T4X);
    k_gemm_mma<1, 0><<<GG, 256>>>(OFF_H1, h1_b, N_NODES, HID);
    k_head2<<<(N_NODES * 32 + 255) / 256, 256>>>(h2_W, h2_b, out);

    (void)in_sizes; (void)n_in; (void)out_size;
}

// round 12
// speedup vs baseline: 2.1267x; 1.0957x over previous
#include <cuda_runtime.h>
#include <cuda_bf16.h>
#include <cstdint>
#include <cstddef>

#define N_NODES 20000
#define IN_DIM  1536
#define HID     256
#define HEADS   4
#define HOPS    3
#define NCLS    3
#define NE      320000
#define EP      (NE + N_NODES)     /* 340000 edges incl. self loops */
#define LN_EPS  1e-5f
#define NEG_SLOPE 0.2f

// weight arena offsets (bf16 elements), all K-major transposed: Wt[n][k] = W[k][n]
#define OFF_PROJ 0                         /* 256 x 1536 */
#define OFF_WL   393216                    /* 3 x 256 x 256 */
#define OFF_WR   589824                    /* 3 x 256 x 256 */
#define OFF_H1   786432                    /* 256 x 256 */
#define W_ARENA  851968

// ---------------- scratch (static device globals: no runtime allocation) ----------------
__device__ float g_x [N_NODES * HID];
__device__ float g_xl[N_NODES * HID];     // also head1 out
__device__ float g_xr[N_NODES * HID];
__device__ int   g_rowstart[N_NODES + 1];
__device__ int   g_counts[N_NODES];
__device__ int   g_cursor[N_NODES];
__device__ int   g_src[EP];
__device__ __nv_bfloat16 g_bhi[W_ARENA];          // weight hi split (K-major)
__device__ __nv_bfloat16 g_blo[W_ARENA];          // weight lo split
__device__ __nv_bfloat16 g_ahi[N_NODES * IN_DIM]; // activation hi split
__device__ __nv_bfloat16 g_alo[N_NODES * IN_DIM]; // activation lo split

// ---------------- small helpers ----------------
__device__ __forceinline__ float warp_sum32(float v){
#pragma unroll
    for (int o = 16; o > 0; o >>= 1) v += __shfl_xor_sync(0xffffffffu, v, o);
    return v;
}
__device__ __forceinline__ float lrelu(float t){ return t > 0.f ? t : NEG_SLOPE * t; }
__device__ __forceinline__ int clamp_idx(int v){
    return ((unsigned)v < (unsigned)N_NODES) ? v : 0;
}
__device__ __forceinline__ uint32_t smem_u32(const void* p){
    uint32_t a;
    asm("{ .reg .u64 t; cvta.to.shared.u64 t, %1; cvt.u32.u64 %0, t; }" : "=r"(a) : "l"(p));
    return a;
}
// split two fp32 into packed bf16x2 hi and lo parts (k-even in low half)
__device__ __forceinline__ void split2(float f0, float f1, uint32_t& hi, uint32_t& lo){
    __nv_bfloat16 h0 = __float2bfloat16(f0);
    __nv_bfloat16 h1 = __float2bfloat16(f1);
    hi = ((uint32_t)__bfloat16_as_ushort(h1) << 16) | (uint32_t)__bfloat16_as_ushort(h0);
    __nv_bfloat16 l0 = __float2bfloat16(f0 - __bfloat162float(h0));
    __nv_bfloat16 l1 = __float2bfloat16(f1 - __bfloat162float(h1));
    lo = ((uint32_t)__bfloat16_as_ushort(l1) << 16) | (uint32_t)__bfloat16_as_ushort(l0);
}
// async 16B copy; pred=false -> zero-fill (src not read)
__device__ __forceinline__ void cp16(uint32_t dst, const void* src, bool pred){
    int sz = pred ? 16 : 0;
    asm volatile("cp.async.cg.shared.global [%0], [%1], 16, %2;"
                 :: "r"(dst), "l"(src), "r"(sz));
}

#define LDMX4(r, addr) \
    asm volatile("ldmatrix.sync.aligned.m8n8.x4.shared.b16 {%0,%1,%2,%3}, [%4];" \
                 : "=r"((r)[0]), "=r"((r)[1]), "=r"((r)[2]), "=r"((r)[3]) : "r"(addr))

__device__ __forceinline__ void mma16816(float* c, const uint32_t* a, uint32_t b0, uint32_t b1){
    asm volatile(
        "mma.sync.aligned.m16n8k16.row.col.f32.bf16.bf16.f32 "
        "{%0,%1,%2,%3}, {%4,%5,%6,%7}, {%8,%9}, {%0,%1,%2,%3};"
        : "+f"(c[0]), "+f"(c[1]), "+f"(c[2]), "+f"(c[3])
        : "r"(a[0]), "r"(a[1]), "r"(a[2]), "r"(a[3]), "r"(b0), "r"(b1));
}

// ---------------- CSR build ----------------
__global__ void k_clear(){
    int i = blockIdx.x * blockDim.x + threadIdx.x;
    if (i < N_NODES){ g_counts[i] = 0; g_cursor[i] = 0; }
}
__global__ void k_hist(const int* __restrict__ ei){
    int e = blockIdx.x * blockDim.x + threadIdx.x;
    if (e >= EP) return;
    int dst = (e < NE) ? clamp_idx(ei[NE + e]) : (e - NE);
    atomicAdd(&g_counts[dst], 1);
}
__global__ void k_scan(){
    __shared__ int sm[1024];
    __shared__ int soff;
    int tid = threadIdx.x;
    if (tid == 0) soff = 0;
    __syncthreads();
    for (int base = 0; base < N_NODES; base += 1024){
        int idx = base + tid;
        int v = (idx < N_NODES) ? g_counts[idx] : 0;
        sm[tid] = v;
        __syncthreads();
        for (int s = 1; s < 1024; s <<= 1){
            int t = (tid >= s) ? sm[tid - s] : 0;
            __syncthreads();
            sm[tid] += t;
            __syncthreads();
        }
        if (idx < N_NODES) g_rowstart[idx] = soff + sm[tid] - v;
        int tot = sm[1023];
        __syncthreads();
        if (tid == 0) soff += tot;
        __syncthreads();
    }
    if (tid == 0) g_rowstart[N_NODES] = soff;
}
__global__ void k_scatter(const int* __restrict__ ei){
    int e = blockIdx.x * blockDim.x + threadIdx.x;
    if (e >= EP) return;
    int src, dst;
    if (e < NE){ src = clamp_idx(ei[e]); dst = clamp_idx(ei[NE + e]); }
    else       { src = e - NE;           dst = src; }
    int pos = g_rowstart[dst] + atomicAdd(&g_cursor[dst], 1);
    g_src[pos] = src;
}

// ---------------- weight transpose + bf16 split ----------------
__global__ void k_tsplit(const float* __restrict__ W, int K, int N, int ooff){
    int i = blockIdx.x * blockDim.x + threadIdx.x;
    if (i >= K * N) return;
    int k = i / N, n = i - k * N;
    float w = W[i];
    __nv_bfloat16 h = __float2bfloat16(w);
    g_bhi[ooff + (size_t)n * K + k] = h;
    g_blo[ooff + (size_t)n * K + k] = __float2bfloat16(w - __bfloat162float(h));
}
// all seven 256x256 weights in one launch: 3x Wl, 3x Wr, h1
__global__ void k_tsplit7(const float* __restrict__ Wl, const float* __restrict__ Wr,
                          const float* __restrict__ h1){
    int i = blockIdx.x * blockDim.x + threadIdx.x;
    if (i >= 7 * 65536) return;
    int slab = i >> 16, j = i & 65535;
    const float* src; int ooff;
    if (slab < 3){ src = Wl + slab * 65536;      ooff = OFF_WL + slab * 65536; }
    else if (slab < 6){ src = Wr + (slab - 3) * 65536; ooff = OFF_WR + (slab - 3) * 65536; }
    else { src = h1; ooff = OFF_H1; }
    int k = j >> 8, n = j & 255;
    float w = src[j];
    __nv_bfloat16 h = __float2bfloat16(w);
    g_bhi[ooff + n * 256 + k] = h;
    g_blo[ooff + n * 256 + k] = __float2bfloat16(w - __bfloat162float(h));
}

// ---------------- feature bf16 split (proj input only) ----------------
__global__ void k_asplit(const float* __restrict__ A, int total4){
    int i = blockIdx.x * blockDim.x + threadIdx.x;
    if (i >= total4) return;
    float4 f = ((const float4*)A)[i];
    uint32_t h0, l0, h1, l1;
    split2(f.x, f.y, h0, l0);
    split2(f.z, f.w, h1, l1);
    ((uint2*)g_ahi)[i] = make_uint2(h0, h1);
    ((uint2*)g_alo)[i] = make_uint2(l0, l1);
}

// ---------------- warp-MMA bf16 split GEMM, cp.async double-buffered --------------------
// CTA tile 128x128, 8 warps (4m x 2n), warp tile 32x64, BK=32.
// D = Ah*Bh + Al*Bh + Ah*Bl  (residual ~2^-17). A pre-split in g_ahi/g_alo.
// Dynamic smem: 2 stages x 4 arrays x 128 x SROW bf16 = 81920 B.
// HOP=0: grid.y in {0,1} -> nc0, out=g_xl, weights boffL/biasL.
// HOP=1: grid.y in {0..3} -> (y&1)->nc0, (y>>1)->L/R weight + g_xl/g_xr output.
#define SROW 40
#define OFF_AH  0
#define OFF_AL  10240
#define OFF_BH  20480
#define OFF_BL  30720
#define STG_B   40960

template<int GELU, int HOP>
__global__ __launch_bounds__(256, 2)
void k_gemm(int boffL, int boffR, const float* __restrict__ biasL,
            const float* __restrict__ biasR, int M, int K)
{
    extern __shared__ __align__(16) uint8_t dyn[];

    int tid = threadIdx.x, wid = tid >> 5, lane = tid & 31;
    int warp_m = wid & 3, warp_n = wid >> 2;
    int row0 = blockIdx.x * 128;

    int nc0, boff;
    const float* bias;
    float* out;
    if (HOP){
        int yy = blockIdx.y;
        int isR = yy >> 1;
        nc0  = (yy & 1) * 128;
        boff = isR ? boffR : boffL;
        bias = isR ? biasR : biasL;
        out  = isR ? g_xr : g_xl;
    } else {
        nc0  = blockIdx.y * 128;
        boff = boffL;
        bias = biasL;
        out  = g_xl;
    }

    float acc[2][8][4];
#pragma unroll
    for (int mt = 0; mt < 2; mt++)
#pragma unroll
        for (int nt = 0; nt < 8; nt++)
#pragma unroll
            for (int q = 0; q < 4; q++) acc[mt][nt][q] = 0.f;

    // ---- loader mapping: thread -> (row r, k-half) ----
    int r = tid >> 1, half = tid & 1;
    int grow = row0 + r;
    bool rok = grow < M;
    const __nv_bfloat16* ahp = g_ahi + (size_t)grow * K + half * 16;
    const __nv_bfloat16* alp = g_alo + (size_t)grow * K + half * 16;
    const __nv_bfloat16* bhp = g_bhi + boff + (size_t)(nc0 + r) * K + half * 16;
    const __nv_bfloat16* blp = g_blo + boff + (size_t)(nc0 + r) * K + half * 16;

    uint32_t base = smem_u32(dyn);
    uint32_t ldOff = (uint32_t)((r * SROW + half * 16) * 2);

    // ---- ldmatrix per-lane fragment offsets (within an array) ----
    int lrow = lane & 15, lcol = (lane >> 4) * 8;
    uint32_t aFrag = (uint32_t)(((warp_m * 32 + lrow) * SROW + lcol) * 2);
    uint32_t bFrag = (uint32_t)(((warp_n * 64 + lrow) * SROW + lcol) * 2);

    int iters = K >> 5;

    // prologue: stage 0 loads
    {
        uint32_t sb = base;
        cp16(sb + OFF_AH + ldOff,      ahp,     rok);
        cp16(sb + OFF_AH + ldOff + 16, ahp + 8, rok);
        cp16(sb + OFF_AL + ldOff,      alp,     rok);
        cp16(sb + OFF_AL + ldOff + 16, alp + 8, rok);
        cp16(sb + OFF_BH + ldOff,      bhp,     true);
        cp16(sb + OFF_BH + ldOff + 16, bhp + 8, true);
        cp16(sb + OFF_BL + ldOff,      blp,     true);
        cp16(sb + OFF_BL + ldOff + 16, blp + 8, true);
        asm volatile("cp.async.commit_group;" ::: "memory");
    }

    for (int it = 0; it < iters; it++){
        if (it + 1 < iters){
            int k1 = (it + 1) << 5;
            uint32_t sb = base + ((it + 1) & 1) * STG_B;
            cp16(sb + OFF_AH + ldOff,      ahp + k1,     rok);
            cp16(sb + OFF_AH + ldOff + 16, ahp + k1 + 8, rok);
            cp16(sb + OFF_AL + ldOff,      alp + k1,     rok);
            cp16(sb + OFF_AL + ldOff + 16, alp + k1 + 8, rok);
            cp16(sb + OFF_BH + ldOff,      bhp + k1,     true);
            cp16(sb + OFF_BH + ldOff + 16, bhp + k1 + 8, true);
            cp16(sb + OFF_BL + ldOff,      blp + k1,     true);
            cp16(sb + OFF_BL + ldOff + 16, blp + k1 + 8, true);
            asm volatile("cp.async.commit_group;" ::: "memory");
            asm volatile("cp.async.wait_group 1;" ::: "memory");
        } else {
            asm volatile("cp.async.wait_group 0;" ::: "memory");
        }
        __syncthreads();

        uint32_t sb = base + (it & 1) * STG_B;
        uint32_t aBH = sb + OFF_AH + aFrag, aBL = sb + OFF_AL + aFrag;
        uint32_t bBH = sb + OFF_BH + bFrag, bBL = sb + OFF_BL + bFrag;

#pragma unroll
        for (int kc = 0; kc < 2; kc++){
            uint32_t ah[2][4], al[2][4];
#pragma unroll
            for (int mt = 0; mt < 2; mt++){
                LDMX4(ah[mt], aBH + (uint32_t)((mt * 16 * SROW + kc * 16) * 2));
                LDMX4(al[mt], aBL + (uint32_t)((mt * 16 * SROW + kc * 16) * 2));
            }
#pragma unroll
            for (int nt2 = 0; nt2 < 4; nt2++){
                uint32_t bh[4], bl[4];
                LDMX4(bh, bBH + (uint32_t)((nt2 * 16 * SROW + kc * 16) * 2));
                LDMX4(bl, bBL + (uint32_t)((nt2 * 16 * SROW + kc * 16) * 2));
#pragma unroll
                for (int p = 0; p < 2; p++){
                    int nt = nt2 * 2 + p;
                    uint32_t b0h = bh[p], b1h = bh[p + 2];
                    uint32_t b0l = bl[p], b1l = bl[p + 2];
#pragma unroll
                    for (int mt = 0; mt < 2; mt++){
                        mma16816(acc[mt][nt], ah[mt], b0h, b1h);   // hi*hi
                        mma16816(acc[mt][nt], al[mt], b0h, b1h);   // lo*hi
                        mma16816(acc[mt][nt], ah[mt], b0l, b1l);   // hi*lo
                    }
                }
            }
        }
        __syncthreads();   // all fragment reads done before stage is overwritten
    }

    // ---------------- epilogue: bias (+GELU), fp32 store ----------------
    int groupID = lane >> 2, tig = lane & 3;
#pragma unroll
    for (int mt = 0; mt < 2; mt++){
        int ra = row0 + warp_m * 32 + mt * 16 + groupID;
        int rb = ra + 8;
#pragma unroll
        for (int nt = 0; nt < 8; nt++){
            int col = nc0 + warp_n * 64 + nt * 8 + tig * 2;
            float b0 = bias[col], b1 = bias[col + 1];
            float v0 = acc[mt][nt][0] + b0, v1 = acc[mt][nt][1] + b1;
            float v2 = acc[mt][nt][2] + b0, v3 = acc[mt][nt][3] + b1;
            if (GELU){
                v0 = 0.5f * v0 * (1.f + erff(v0 * 0.70710678118654752440f));
                v1 = 0.5f * v1 * (1.f + erff(v1 * 0.70710678118654752440f));
                v2 = 0.5f * v2 * (1.f + erff(v2 * 0.70710678118654752440f));
                v3 = 0.5f * v3 * (1.f + erff(v3 * 0.70710678118654752440f));
            }
            if (ra < M){
                out[(size_t)ra * HID + col]     = v0;
                out[(size_t)ra * HID + col + 1] = v1;
            }
            if (rb < M){
                out[(size_t)rb * HID + col]     = v2;
                out[(size_t)rb * HID + col + 1] = v3;
            }
        }
    }
}

// ---------------- LayerNorm (proj): g_x = LN(g_xl); also emits bf16 splits ----------------
__global__ void k_ln(const float* __restrict__ g, const float* __restrict__ b){
    int gw = (int)((blockIdx.x * blockDim.x + threadIdx.x) >> 5);
    if (gw >= N_NODES) return;
    int lane = threadIdx.x & 31, d = lane * 8;
    const float4* p = (const float4*)(g_xl + (size_t)gw * HID + d);
    float4 v0 = p[0], v1 = p[1];
    float v[8] = {v0.x, v0.y, v0.z, v0.w, v1.x, v1.y, v1.z, v1.w};
    float s = 0.f, ss = 0.f;
#pragma unroll
    for (int q = 0; q < 8; q++){ s += v[q]; ss += v[q] * v[q]; }
    s  = warp_sum32(s);
    ss = warp_sum32(ss);
    float mu  = s  * (1.f / 256.f);
    float var = ss * (1.f / 256.f) - mu * mu;
    float inv = rsqrtf(var + LN_EPS);
    float* op = g_x + (size_t)gw * HID + d;
    float o[8];
#pragma unroll
    for (int q = 0; q < 8; q++){
        o[q] = (v[q] - mu) * inv * g[d + q] + b[d + q];
        op[q] = o[q];
    }
    uint32_t h0, l0, h1, l1, h2, l2, h3, l3;
    split2(o[0], o[1], h0, l0);  split2(o[2], o[3], h1, l1);
    split2(o[4], o[5], h2, l2);  split2(o[6], o[7], h3, l3);
    int idx = gw * (HID / 4) + lane * 2;
    ((uint2*)g_ahi)[idx]     = make_uint2(h0, h1);
    ((uint2*)g_ahi)[idx + 1] = make_uint2(h2, h3);
    ((uint2*)g_alo)[idx]     = make_uint2(l0, l1);
    ((uint2*)g_alo)[idx + 1] = make_uint2(l2, l3);
}

// ---------------- fused GAT hop: online softmax + agg + gbias + residual + LN + split -----
__global__ void k_gat(const float* __restrict__ att,
                      const float* __restrict__ gbias,
                      const float* __restrict__ lng,
                      const float* __restrict__ lnb){
    int gw = (int)((blockIdx.x * blockDim.x + threadIdx.x) >> 5);
    if (gw >= N_NODES) return;
    int lane = threadIdx.x & 31, d = lane * 8;

    const float4* pr = (const float4*)(g_xr + (size_t)gw * HID + d);
    float4 r0 = pr[0], r1 = pr[1];
    const float4* pa = (const float4*)(att + d);
    float4 a0 = __ldg(pa), a1 = __ldg(pa + 1);

    float m = -1e30f, denom = 0.f;
    float acc[8] = {0.f, 0.f, 0.f, 0.f, 0.f, 0.f, 0.f, 0.f};

    int s = g_rowstart[gw], e = g_rowstart[gw + 1];
    for (int j = s; j < e; j++){
        int src = g_src[j];
        const float4* pl = (const float4*)(g_xl + (size_t)src * HID + d);
        float4 l0 = pl[0], l1 = pl[1];

        float t = 0.f;
        t = fmaf(lrelu(l0.x + r0.x), a0.x, t);
        t = fmaf(lrelu(l0.y + r0.y), a0.y, t);
        t = fmaf(lrelu(l0.z + r0.z), a0.z, t);
        t = fmaf(lrelu(l0.w + r0.w), a0.w, t);
        t = fmaf(lrelu(l1.x + r1.x), a1.x, t);
        t = fmaf(lrelu(l1.y + r1.y), a1.y, t);
        t = fmaf(lrelu(l1.z + r1.z), a1.z, t);
        t = fmaf(lrelu(l1.w + r1.w), a1.w, t);
        t += __shfl_xor_sync(0xffffffffu, t, 1);
        t += __shfl_xor_sync(0xffffffffu, t, 2);
        t += __shfl_xor_sync(0xffffffffu, t, 4);

        float mn = fmaxf(m, t);
        float sc = expf(m - mn);      // first iter: expf(-inf) = 0
        float w  = expf(t - mn);
        denom = fmaf(denom, sc, w);
        acc[0] = fmaf(acc[0], sc, w * l0.x);
        acc[1] = fmaf(acc[1], sc, w * l0.y);
        acc[2] = fmaf(acc[2], sc, w * l0.z);
        acc[3] = fmaf(acc[3], sc, w * l0.w);
        acc[4] = fmaf(acc[4], sc, w * l1.x);
        acc[5] = fmaf(acc[5], sc, w * l1.y);
        acc[6] = fmaf(acc[6], sc, w * l1.z);
        acc[7] = fmaf(acc[7], sc, w * l1.w);
        m = mn;
    }

    float inv = 1.f / denom;
    float* xp = g_x + (size_t)gw * HID + d;
    float v[8];
#pragma unroll
    for (int q = 0; q < 8; q++) v[q] = fmaf(acc[q], inv, gbias[d + q] + xp[q]);

    float sm = 0.f, ss = 0.f;
#pragma unroll
    for (int q = 0; q < 8; q++){ sm += v[q]; ss += v[q] * v[q]; }
    sm = warp_sum32(sm);
    ss = warp_sum32(ss);
    float mu  = sm * (1.f / 256.f);
    float var = ss * (1.f / 256.f) - mu * mu;
    float rin = rsqrtf(var + LN_EPS);
    float o[8];
#pragma unroll
    for (int q = 0; q < 8; q++){
        o[q] = (v[q] - mu) * rin * lng[d + q] + lnb[d + q];
        xp[q] = o[q];
    }
    uint32_t h0, l0, h1, l1, h2, l2, h3, l3;
    split2(o[0], o[1], h0, l0);  split2(o[2], o[3], h1, l1);
    split2(o[4], o[5], h2, l2);  split2(o[6], o[7], h3, l3);
    int idx = gw * (HID / 4) + lane * 2;
    ((uint2*)g_ahi)[idx]     = make_uint2(h0, h1);
    ((uint2*)g_ahi)[idx + 1] = make_uint2(h2, h3);
    ((uint2*)g_alo)[idx]     = make_uint2(l0, l1);
    ((uint2*)g_alo)[idx + 1] = make_uint2(l2, l3);
}

// ---------------- head 2 ----------------
__global__ void k_head2(const float* __restrict__ W2, const float* __restrict__ b2,
                        float* __restrict__ out){
    __shared__ float ws[HID * NCLS];
    int tid = threadIdx.x;
    for (int i = tid; i < HID * NCLS; i += blockDim.x) ws[i] = W2[i];
    __syncthreads();
    int gw = (int)((blockIdx.x * blockDim.x + tid) >> 5);
    if (gw >= N_NODES) return;
    int lane = tid & 31;
    const float* row = g_xl + (size_t)gw * HID;
    float a0 = 0.f, a1 = 0.f, a2 = 0.f;
#pragma unroll
    for (int q = 0; q < 8; q++){
        int k = lane + 32 * q;
        float xv = row[k];
        a0 = fmaf(xv, ws[k * 3 + 0], a0);
        a1 = fmaf(xv, ws[k * 3 + 1], a1);
        a2 = fmaf(xv, ws[k * 3 + 2], a2);
    }
    a0 = warp_sum32(a0); a1 = warp_sum32(a1); a2 = warp_sum32(a2);
    if (lane == 0){
        out[(size_t)gw * NCLS + 0] = a0 + b2[0];
        out[(size_t)gw * NCLS + 1] = a1 + b2[1];
        out[(size_t)gw * NCLS + 2] = a2 + b2[2];
    }
}

// ---------------- launch ----------------
extern "C" void kernel_launch(void* const* d_in, const int* in_sizes, int n_in,
                              void* d_out, int out_size)
{
    const float* features = (const float*)d_in[0];
    const int*   ei       = (const int*)d_in[1];     // int32 (JAX x64 disabled)
    const float* proj_W = (const float*)d_in[2];
    const float* proj_b = (const float*)d_in[3];
    const float* n0_g   = (const float*)d_in[4];
    const float* n0_b   = (const float*)d_in[5];
    const float* Wl     = (const float*)d_in[6];
    const float* bl     = (const float*)d_in[7];
    const float* Wr     = (const float*)d_in[8];
    const float* br     = (const float*)d_in[9];
    const float* att    = (const float*)d_in[10];
    const float* gbias  = (const float*)d_in[11];
    const float* ln_g   = (const float*)d_in[12];
    const float* ln_b   = (const float*)d_in[13];
    const float* h1_W   = (const float*)d_in[14];
    const float* h1_b   = (const float*)d_in[15];
    const float* h2_W   = (const float*)d_in[16];
    const float* h2_b   = (const float*)d_in[17];
    float* out = (float*)d_out;

    const int DSM = 2 * STG_B;   // 81920 B dynamic smem
    cudaFuncSetAttribute(k_gemm<0, 0>, cudaFuncAttributeMaxDynamicSharedMemorySize, DSM);
    cudaFuncSetAttribute(k_gemm<0, 1>, cudaFuncAttributeMaxDynamicSharedMemorySize, DSM);
    cudaFuncSetAttribute(k_gemm<1, 0>, cudaFuncAttributeMaxDynamicSharedMemorySize, DSM);
    (void)cudaGetLastError();   // clear any sticky non-fatal status before capture

    // CSR build
    k_clear  <<<(N_NODES + 255) / 256, 256>>>();
    k_hist   <<<(EP + 255) / 256, 256>>>(ei);
    k_scan   <<<1, 1024>>>();
    k_scatter<<<(EP + 255) / 256, 256>>>(ei);

    // weight transpose + split (proj separately; the 7 square matrices in one launch)
    k_tsplit <<<(IN_DIM * HID) / 256, 256>>>(proj_W, IN_DIM, HID, OFF_PROJ);
    k_tsplit7<<<(7 * 65536) / 256, 256>>>(Wl, Wr, h1_W);

    const dim3 GP((N_NODES + 127) / 128, 2);   // proj / h1 tiles
    const dim3 GH((N_NODES + 127) / 128, 4);   // fused hop tiles (L cols0/1, R cols0/1)
    const int T4F = (N_NODES * IN_DIM) / 4;

    // x = LN(features @ proj_W + proj_b); LN emits activation splits
    k_asplit<<<(T4F + 255) / 256, 256>>>(features, T4F);
    k_gemm<0, 0><<<GP, 256, DSM>>>(OFF_PROJ, 0, proj_b, nullptr, N_NODES, IN_DIM);
    k_ln<<<(N_NODES * 32 + 255) / 256, 256>>>(n0_g, n0_b);

    for (int h = 0; h < HOPS; h++){
        k_gemm<0, 1><<<GH, 256, DSM>>>(OFF_WL + h * HID * HID, OFF_WR + h * HID * HID,
                                       bl + h * HID, br + h * HID, N_NODES, HID);
        k_gat<<<(N_NODES * 32 + 255) / 256, 256>>>(att + h * HEADS * (HID / HEADS),
                                                   gbias + h * HID, ln_g + h * HID, ln_b + h * HID);
    }

    // head: gelu(x @ h1_W + h1_b) -> g_xl ; then @ h2_W + h2_b -> out
    k_gemm<1, 0><<<GP, 256, DSM>>>(OFF_H1, 0, h1_b, nullptr, N_NODES, HID);
    k_head2<<<(N_NODES * 32 + 255) / 256, 256>>>(h2_W, h2_b, out);

    (void)in_sizes; (void)n_in; (void)out_size;
}

// round 13
// speedup vs baseline: 2.2135x; 1.0409x over previous
#include <cuda_runtime.h>
#include <cuda_bf16.h>
#include <cstdint>
#include <cstddef>

#define N_NODES 20000
#define IN_DIM  1536
#define HID     256
#define HEADS   4
#define HOPS    3
#define NCLS    3
#define NE      320000
#define EP      (NE + N_NODES)     /* 340000 edges incl. self loops */
#define LN_EPS  1e-5f
#define NEG_SLOPE 0.2f

// weight arena offsets (bf16 elements), all K-major transposed: Wt[n][k] = W[k][n]
#define OFF_PROJ 0                         /* 256 x 1536 */
#define OFF_WL   393216                    /* 3 x 256 x 256 */
#define OFF_WR   589824                    /* 3 x 256 x 256 */
#define OFF_H1   786432                    /* 256 x 256 */
#define W_ARENA  851968

// ---------------- scratch (static device globals: no runtime allocation) ----------------
__device__ float g_x [N_NODES * HID];
__device__ float g_xl[N_NODES * HID];     // also head1 partial out
__device__ float g_xr[N_NODES * HID];
__device__ float g_pp[N_NODES * HID];     // split-K partial (proj / h1)
__device__ int   g_rowstart[N_NODES + 1];
__device__ int   g_counts[N_NODES];
__device__ int   g_cursor[N_NODES];
__device__ int   g_src[EP];
__device__ __nv_bfloat16 g_bhi[W_ARENA];          // weight hi split (K-major)
__device__ __nv_bfloat16 g_blo[W_ARENA];          // weight lo split
__device__ __nv_bfloat16 g_ahi[N_NODES * IN_DIM]; // activation hi split
__device__ __nv_bfloat16 g_alo[N_NODES * IN_DIM]; // activation lo split

// ---------------- small helpers ----------------
__device__ __forceinline__ float warp_sum32(float v){
#pragma unroll
    for (int o = 16; o > 0; o >>= 1) v += __shfl_xor_sync(0xffffffffu, v, o);
    return v;
}
__device__ __forceinline__ float lrelu(float t){ return t > 0.f ? t : NEG_SLOPE * t; }
__device__ __forceinline__ int clamp_idx(int v){
    return ((unsigned)v < (unsigned)N_NODES) ? v : 0;
}
__device__ __forceinline__ uint32_t smem_u32(const void* p){
    uint32_t a;
    asm("{ .reg .u64 t; cvta.to.shared.u64 t, %1; cvt.u32.u64 %0, t; }" : "=r"(a) : "l"(p));
    return a;
}
// split two fp32 into packed bf16x2 hi and lo parts (k-even in low half)
__device__ __forceinline__ void split2(float f0, float f1, uint32_t& hi, uint32_t& lo){
    __nv_bfloat16 h0 = __float2bfloat16(f0);
    __nv_bfloat16 h1 = __float2bfloat16(f1);
    hi = ((uint32_t)__bfloat16_as_ushort(h1) << 16) | (uint32_t)__bfloat16_as_ushort(h0);
    __nv_bfloat16 l0 = __float2bfloat16(f0 - __bfloat162float(h0));
    __nv_bfloat16 l1 = __float2bfloat16(f1 - __bfloat162float(h1));
    lo = ((uint32_t)__bfloat16_as_ushort(l1) << 16) | (uint32_t)__bfloat16_as_ushort(l0);
}
// async 16B copy; pred=false -> zero-fill (src not read)
__device__ __forceinline__ void cp16(uint32_t dst, const void* src, bool pred){
    int sz = pred ? 16 : 0;
    asm volatile("cp.async.cg.shared.global [%0], [%1], 16, %2;"
                 :: "r"(dst), "l"(src), "r"(sz));
}

#define LDMX4(r, addr) \
    asm volatile("ldmatrix.sync.aligned.m8n8.x4.shared.b16 {%0,%1,%2,%3}, [%4];" \
                 : "=r"((r)[0]), "=r"((r)[1]), "=r"((r)[2]), "=r"((r)[3]) : "r"(addr))

__device__ __forceinline__ void mma16816(float* c, const uint32_t* a, uint32_t b0, uint32_t b1){
    asm volatile(
        "mma.sync.aligned.m16n8k16.row.col.f32.bf16.bf16.f32 "
        "{%0,%1,%2,%3}, {%4,%5,%6,%7}, {%8,%9}, {%0,%1,%2,%3};"
        : "+f"(c[0]), "+f"(c[1]), "+f"(c[2]), "+f"(c[3])
        : "r"(a[0]), "r"(a[1]), "r"(a[2]), "r"(a[3]), "r"(b0), "r"(b1));
}

// ---------------- CSR build ----------------
__global__ void k_clear(){
    int i = blockIdx.x * blockDim.x + threadIdx.x;
    if (i < N_NODES){ g_counts[i] = 0; g_cursor[i] = 0; }
}
__global__ void k_hist(const int* __restrict__ ei){
    int e = blockIdx.x * blockDim.x + threadIdx.x;
    if (e >= EP) return;
    int dst = (e < NE) ? clamp_idx(ei[NE + e]) : (e - NE);
    atomicAdd(&g_counts[dst], 1);
}
__global__ void k_scan(){
    __shared__ int sm[1024];
    __shared__ int soff;
    int tid = threadIdx.x;
    if (tid == 0) soff = 0;
    __syncthreads();
    for (int base = 0; base < N_NODES; base += 1024){
        int idx = base + tid;
        int v = (idx < N_NODES) ? g_counts[idx] : 0;
        sm[tid] = v;
        __syncthreads();
        for (int s = 1; s < 1024; s <<= 1){
            int t = (tid >= s) ? sm[tid - s] : 0;
            __syncthreads();
            sm[tid] += t;
            __syncthreads();
        }
        if (idx < N_NODES) g_rowstart[idx] = soff + sm[tid] - v;
        int tot = sm[1023];
        __syncthreads();
        if (tid == 0) soff += tot;
        __syncthreads();
    }
    if (tid == 0) g_rowstart[N_NODES] = soff;
}
__global__ void k_scatter(const int* __restrict__ ei){
    int e = blockIdx.x * blockDim.x + threadIdx.x;
    if (e >= EP) return;
    int src, dst;
    if (e < NE){ src = clamp_idx(ei[e]); dst = clamp_idx(ei[NE + e]); }
    else       { src = e - NE;           dst = src; }
    int pos = g_rowstart[dst] + atomicAdd(&g_cursor[dst], 1);
    g_src[pos] = src;
}

// ---------------- weight transpose + bf16 split ----------------
__global__ void k_tsplit(const float* __restrict__ W, int K, int N, int ooff){
    int i = blockIdx.x * blockDim.x + threadIdx.x;
    if (i >= K * N) return;
    int k = i / N, n = i - k * N;
    float w = W[i];
    __nv_bfloat16 h = __float2bfloat16(w);
    g_bhi[ooff + (size_t)n * K + k] = h;
    g_blo[ooff + (size_t)n * K + k] = __float2bfloat16(w - __bfloat162float(h));
}
// all seven 256x256 weights in one launch: 3x Wl, 3x Wr, h1
__global__ void k_tsplit7(const float* __restrict__ Wl, const float* __restrict__ Wr,
                          const float* __restrict__ h1){
    int i = blockIdx.x * blockDim.x + threadIdx.x;
    if (i >= 7 * 65536) return;
    int slab = i >> 16, j = i & 65535;
    const float* src; int ooff;
    if (slab < 3){ src = Wl + slab * 65536;      ooff = OFF_WL + slab * 65536; }
    else if (slab < 6){ src = Wr + (slab - 3) * 65536; ooff = OFF_WR + (slab - 3) * 65536; }
    else { src = h1; ooff = OFF_H1; }
    int k = j >> 8, n = j & 255;
    float w = src[j];
    __nv_bfloat16 h = __float2bfloat16(w);
    g_bhi[ooff + n * 256 + k] = h;
    g_blo[ooff + n * 256 + k] = __float2bfloat16(w - __bfloat162float(h));
}

// ---------------- feature bf16 split (proj input only) ----------------
__global__ void k_asplit(const float* __restrict__ A, int total4){
    int i = blockIdx.x * blockDim.x + threadIdx.x;
    if (i >= total4) return;
    float4 f = ((const float4*)A)[i];
    uint32_t h0, l0, h1, l1;
    split2(f.x, f.y, h0, l0);
    split2(f.z, f.w, h1, l1);
    ((uint2*)g_ahi)[i] = make_uint2(h0, h1);
    ((uint2*)g_alo)[i] = make_uint2(l0, l1);
}

// ---------------- warp-MMA bf16 split GEMM, cp.async double-buffered --------------------
// CTA tile 128x128, 8 warps (4m x 2n), warp tile 32x64, BK=32.
// D = Ah*Bh + Al*Bh + Ah*Bl  (residual ~2^-17). A pre-split in g_ahi/g_alo.
// Dynamic smem: 2 stages x 4 arrays x 128 x SROW bf16 = 81920 B.
// HOP=1: grid (tiles,4): (y&1)->nc0, (y>>1)->L/R weight + g_xl/g_xr output.
// SPLITK=1 (HOP=0): grid (tiles,2,2): z = K-half; z=0 -> g_xl (+bias), z=1 -> g_pp (raw).
#define SROW 40
#define OFF_AH  0
#define OFF_AL  10240
#define OFF_BH  20480
#define OFF_BL  30720
#define STG_B   40960

template<int HOP, int SPLITK>
__global__ __launch_bounds__(256, 2)
void k_gemm(int boffL, int boffR, const float* __restrict__ biasL,
            const float* __restrict__ biasR, int M, int K)
{
    extern __shared__ __align__(16) uint8_t dyn[];

    int tid = threadIdx.x, wid = tid >> 5, lane = tid & 31;
    int warp_m = wid & 3, warp_n = wid >> 2;
    int row0 = blockIdx.x * 128;

    int nc0, boff, kbase = 0, Keff = K;
    bool addb = true;
    const float* bias;
    float* out;
    if (HOP){
        int yy = blockIdx.y;
        int isR = yy >> 1;
        nc0  = (yy & 1) * 128;
        boff = isR ? boffR : boffL;
        bias = isR ? biasR : biasL;
        out  = isR ? g_xr : g_xl;
    } else {
        nc0  = blockIdx.y * 128;
        boff = boffL;
        bias = biasL;
        out  = g_xl;
        if (SPLITK){
            int z = blockIdx.z;
            Keff  = K >> 1;
            kbase = z * Keff;
            out   = z ? g_pp : g_xl;
            addb  = (z == 0);
        }
    }

    float acc[2][8][4];
#pragma unroll
    for (int mt = 0; mt < 2; mt++)
#pragma unroll
        for (int nt = 0; nt < 8; nt++)
#pragma unroll
            for (int q = 0; q < 4; q++) acc[mt][nt][q] = 0.f;

    // ---- loader mapping: thread -> (row r, k-half) ----
    int r = tid >> 1, half = tid & 1;
    int grow = row0 + r;
    bool rok = grow < M;
    const __nv_bfloat16* ahp = g_ahi + (size_t)grow * K + kbase + half * 16;
    const __nv_bfloat16* alp = g_alo + (size_t)grow * K + kbase + half * 16;
    const __nv_bfloat16* bhp = g_bhi + boff + (size_t)(nc0 + r) * K + kbase + half * 16;
    const __nv_bfloat16* blp = g_blo + boff + (size_t)(nc0 + r) * K + kbase + half * 16;

    uint32_t base = smem_u32(dyn);
    uint32_t ldOff = (uint32_t)((r * SROW + half * 16) * 2);

    // ---- ldmatrix per-lane fragment offsets (within an array) ----
    int lrow = lane & 15, lcol = (lane >> 4) * 8;
    uint32_t aFrag = (uint32_t)(((warp_m * 32 + lrow) * SROW + lcol) * 2);
    uint32_t bFrag = (uint32_t)(((warp_n * 64 + lrow) * SROW + lcol) * 2);

    int iters = Keff >> 5;

    // prologue: stage 0 loads
    {
        uint32_t sb = base;
        cp16(sb + OFF_AH + ldOff,      ahp,     rok);
        cp16(sb + OFF_AH + ldOff + 16, ahp + 8, rok);
        cp16(sb + OFF_AL + ldOff,      alp,     rok);
        cp16(sb + OFF_AL + ldOff + 16, alp + 8, rok);
        cp16(sb + OFF_BH + ldOff,      bhp,     true);
        cp16(sb + OFF_BH + ldOff + 16, bhp + 8, true);
        cp16(sb + OFF_BL + ldOff,      blp,     true);
        cp16(sb + OFF_BL + ldOff + 16, blp + 8, true);
        asm volatile("cp.async.commit_group;" ::: "memory");
    }

    for (int it = 0; it < iters; it++){
        if (it + 1 < iters){
            int k1 = (it + 1) << 5;
            uint32_t sb = base + ((it + 1) & 1) * STG_B;
            cp16(sb + OFF_AH + ldOff,      ahp + k1,     rok);
            cp16(sb + OFF_AH + ldOff + 16, ahp + k1 + 8, rok);
            cp16(sb + OFF_AL + ldOff,      alp + k1,     rok);
            cp16(sb + OFF_AL + ldOff + 16, alp + k1 + 8, rok);
            cp16(sb + OFF_BH + ldOff,      bhp + k1,     true);
            cp16(sb + OFF_BH + ldOff + 16, bhp + k1 + 8, true);
            cp16(sb + OFF_BL + ldOff,      blp + k1,     true);
            cp16(sb + OFF_BL + ldOff + 16, blp + k1 + 8, true);
            asm volatile("cp.async.commit_group;" ::: "memory");
            asm volatile("cp.async.wait_group 1;" ::: "memory");
        } else {
            asm volatile("cp.async.wait_group 0;" ::: "memory");
        }
        __syncthreads();

        uint32_t sb = base + (it & 1) * STG_B;
        uint32_t aBH = sb + OFF_AH + aFrag, aBL = sb + OFF_AL + aFrag;
        uint32_t bBH = sb + OFF_BH + bFrag, bBL = sb + OFF_BL + bFrag;

#pragma unroll
        for (int kc = 0; kc < 2; kc++){
            uint32_t ah[2][4], al[2][4];
#pragma unroll
            for (int mt = 0; mt < 2; mt++){
                LDMX4(ah[mt], aBH + (uint32_t)((mt * 16 * SROW + kc * 16) * 2));
                LDMX4(al[mt], aBL + (uint32_t)((mt * 16 * SROW + kc * 16) * 2));
            }
#pragma unroll
            for (int nt2 = 0; nt2 < 4; nt2++){
                uint32_t bh[4], bl[4];
                LDMX4(bh, bBH + (uint32_t)((nt2 * 16 * SROW + kc * 16) * 2));
                LDMX4(bl, bBL + (uint32_t)((nt2 * 16 * SROW + kc * 16) * 2));
#pragma unroll
                for (int p = 0; p < 2; p++){
                    int nt = nt2 * 2 + p;
                    uint32_t b0h = bh[p], b1h = bh[p + 2];
                    uint32_t b0l = bl[p], b1l = bl[p + 2];
#pragma unroll
                    for (int mt = 0; mt < 2; mt++){
                        mma16816(acc[mt][nt], ah[mt], b0h, b1h);   // hi*hi
                        mma16816(acc[mt][nt], al[mt], b0h, b1h);   // lo*hi
                        mma16816(acc[mt][nt], ah[mt], b0l, b1l);   // hi*lo
                    }
                }
            }
        }
        __syncthreads();   // all fragment reads done before stage is overwritten
    }

    // ---------------- epilogue: (+bias on z=0), fp32 store ----------------
    int groupID = lane >> 2, tig = lane & 3;
#pragma unroll
    for (int mt = 0; mt < 2; mt++){
        int ra = row0 + warp_m * 32 + mt * 16 + groupID;
        int rb = ra + 8;
#pragma unroll
        for (int nt = 0; nt < 8; nt++){
            int col = nc0 + warp_n * 64 + nt * 8 + tig * 2;
            float b0 = addb ? bias[col]     : 0.f;
            float b1 = addb ? bias[col + 1] : 0.f;
            float v0 = acc[mt][nt][0] + b0, v1 = acc[mt][nt][1] + b1;
            float v2 = acc[mt][nt][2] + b0, v3 = acc[mt][nt][3] + b1;
            if (ra < M){
                out[(size_t)ra * HID + col]     = v0;
                out[(size_t)ra * HID + col + 1] = v1;
            }
            if (rb < M){
                out[(size_t)rb * HID + col]     = v2;
                out[(size_t)rb * HID + col + 1] = v3;
            }
        }
    }
}

// ---------------- LayerNorm (proj): g_x = LN(g_xl + g_pp); emits bf16 splits --------------
__global__ void k_ln(const float* __restrict__ g, const float* __restrict__ b){
    int gw = (int)((blockIdx.x * blockDim.x + threadIdx.x) >> 5);
    if (gw >= N_NODES) return;
    int lane = threadIdx.x & 31, d = lane * 8;
    const float4* p  = (const float4*)(g_xl + (size_t)gw * HID + d);
    const float4* pq = (const float4*)(g_pp + (size_t)gw * HID + d);
    float4 v0 = p[0], v1 = p[1];
    float4 w0 = pq[0], w1 = pq[1];
    float v[8] = {v0.x + w0.x, v0.y + w0.y, v0.z + w0.z, v0.w + w0.w,
                  v1.x + w1.x, v1.y + w1.y, v1.z + w1.z, v1.w + w1.w};
    float s = 0.f, ss = 0.f;
#pragma unroll
    for (int q = 0; q < 8; q++){ s += v[q]; ss += v[q] * v[q]; }
    s  = warp_sum32(s);
    ss = warp_sum32(ss);
    float mu  = s  * (1.f / 256.f);
    float var = ss * (1.f / 256.f) - mu * mu;
    float inv = rsqrtf(var + LN_EPS);
    float* op = g_x + (size_t)gw * HID + d;
    float o[8];
#pragma unroll
    for (int q = 0; q < 8; q++){
        o[q] = (v[q] - mu) * inv * g[d + q] + b[d + q];
        op[q] = o[q];
    }
    uint32_t h0, l0, h1, l1, h2, l2, h3, l3;
    split2(o[0], o[1], h0, l0);  split2(o[2], o[3], h1, l1);
    split2(o[4], o[5], h2, l2);  split2(o[6], o[7], h3, l3);
    int idx = gw * (HID / 4) + lane * 2;
    ((uint2*)g_ahi)[idx]     = make_uint2(h0, h1);
    ((uint2*)g_ahi)[idx + 1] = make_uint2(h2, h3);
    ((uint2*)g_alo)[idx]     = make_uint2(l0, l1);
    ((uint2*)g_alo)[idx + 1] = make_uint2(l2, l3);
}

// ---------------- fused GAT hop: online softmax + agg + gbias + residual + LN + split -----
__global__ void k_gat(const float* __restrict__ att,
                      const float* __restrict__ gbias,
                      const float* __restrict__ lng,
                      const float* __restrict__ lnb){
    int gw = (int)((blockIdx.x * blockDim.x + threadIdx.x) >> 5);
    if (gw >= N_NODES) return;
    int lane = threadIdx.x & 31, d = lane * 8;

    const float4* pr = (const float4*)(g_xr + (size_t)gw * HID + d);
    float4 r0 = pr[0], r1 = pr[1];
    const float4* pa = (const float4*)(att + d);
    float4 a0 = __ldg(pa), a1 = __ldg(pa + 1);

    float m = -1e30f, denom = 0.f;
    float acc[8] = {0.f, 0.f, 0.f, 0.f, 0.f, 0.f, 0.f, 0.f};

    int s = g_rowstart[gw], e = g_rowstart[gw + 1];
    for (int j = s; j < e; j++){
        int src = g_src[j];
        const float4* pl = (const float4*)(g_xl + (size_t)src * HID + d);
        float4 l0 = pl[0], l1 = pl[1];

        float t = 0.f;
        t = fmaf(lrelu(l0.x + r0.x), a0.x, t);
        t = fmaf(lrelu(l0.y + r0.y), a0.y, t);
        t = fmaf(lrelu(l0.z + r0.z), a0.z, t);
        t = fmaf(lrelu(l0.w + r0.w), a0.w, t);
        t = fmaf(lrelu(l1.x + r1.x), a1.x, t);
        t = fmaf(lrelu(l1.y + r1.y), a1.y, t);
        t = fmaf(lrelu(l1.z + r1.z), a1.z, t);
        t = fmaf(lrelu(l1.w + r1.w), a1.w, t);
        t += __shfl_xor_sync(0xffffffffu, t, 1);
        t += __shfl_xor_sync(0xffffffffu, t, 2);
        t += __shfl_xor_sync(0xffffffffu, t, 4);

        float mn = fmaxf(m, t);
        float sc = expf(m - mn);      // first iter: expf(-inf) = 0
        float w  = expf(t - mn);
        denom = fmaf(denom, sc, w);
        acc[0] = fmaf(acc[0], sc, w * l0.x);
        acc[1] = fmaf(acc[1], sc, w * l0.y);
        acc[2] = fmaf(acc[2], sc, w * l0.z);
        acc[3] = fmaf(acc[3], sc, w * l0.w);
        acc[4] = fmaf(acc[4], sc, w * l1.x);
        acc[5] = fmaf(acc[5], sc, w * l1.y);
        acc[6] = fmaf(acc[6], sc, w * l1.z);
        acc[7] = fmaf(acc[7], sc, w * l1.w);
        m = mn;
    }

    float inv = 1.f / denom;
    float* xp = g_x + (size_t)gw * HID + d;
    float v[8];
#pragma unroll
    for (int q = 0; q < 8; q++) v[q] = fmaf(acc[q], inv, gbias[d + q] + xp[q]);

    float sm = 0.f, ss = 0.f;
#pragma unroll
    for (int q = 0; q < 8; q++){ sm += v[q]; ss += v[q] * v[q]; }
    sm = warp_sum32(sm);
    ss = warp_sum32(ss);
    float mu  = sm * (1.f / 256.f);
    float var = ss * (1.f / 256.f) - mu * mu;
    float rin = rsqrtf(var + LN_EPS);
    float o[8];
#pragma unroll
    for (int q = 0; q < 8; q++){
        o[q] = (v[q] - mu) * rin * lng[d + q] + lnb[d + q];
        xp[q] = o[q];
    }
    uint32_t h0, l0, h1, l1, h2, l2, h3, l3;
    split2(o[0], o[1], h0, l0);  split2(o[2], o[3], h1, l1);
    split2(o[4], o[5], h2, l2);  split2(o[6], o[7], h3, l3);
    int idx = gw * (HID / 4) + lane * 2;
    ((uint2*)g_ahi)[idx]     = make_uint2(h0, h1);
    ((uint2*)g_ahi)[idx + 1] = make_uint2(h2, h3);
    ((uint2*)g_alo)[idx]     = make_uint2(l0, l1);
    ((uint2*)g_alo)[idx + 1] = make_uint2(l2, l3);
}

// ---------------- head 2: out = gelu(xl + pp) @ h2_W + h2_b -------------------------------
__global__ void k_head2(const float* __restrict__ W2, const float* __restrict__ b2,
                        float* __restrict__ out){
    __shared__ float ws[HID * NCLS];
    int tid = threadIdx.x;
    for (int i = tid; i < HID * NCLS; i += blockDim.x) ws[i] = W2[i];
    __syncthreads();
    int gw = (int)((blockIdx.x * blockDim.x + tid) >> 5);
    if (gw >= N_NODES) return;
    int lane = tid & 31;
    const float* row = g_xl + (size_t)gw * HID;
    const float* prt = g_pp + (size_t)gw * HID;
    float a0 = 0.f, a1 = 0.f, a2 = 0.f;
#pragma unroll
    for (int q = 0; q < 8; q++){
        int k = lane + 32 * q;
        float xv = row[k] + prt[k];
        xv = 0.5f * xv * (1.f + erff(xv * 0.70710678118654752440f));
        a0 = fmaf(xv, ws[k * 3 + 0], a0);
        a1 = fmaf(xv, ws[k * 3 + 1], a1);
        a2 = fmaf(xv, ws[k * 3 + 2], a2);
    }
    a0 = warp_sum32(a0); a1 = warp_sum32(a1); a2 = warp_sum32(a2);
    if (lane == 0){
        out[(size_t)gw * NCLS + 0] = a0 + b2[0];
        out[(size_t)gw * NCLS + 1] = a1 + b2[1];
        out[(size_t)gw * NCLS + 2] = a2 + b2[2];
    }
}

// ---------------- launch ----------------
extern "C" void kernel_launch(void* const* d_in, const int* in_sizes, int n_in,
                              void* d_out, int out_size)
{
    const float* features = (const float*)d_in[0];
    const int*   ei       = (const int*)d_in[1];     // int32 (JAX x64 disabled)
    const float* proj_W = (const float*)d_in[2];
    const float* proj_b = (const float*)d_in[3];
    const float* n0_g   = (const float*)d_in[4];
    const float* n0_b   = (const float*)d_in[5];
    const float* Wl     = (const float*)d_in[6];
    const float* bl     = (const float*)d_in[7];
    const float* Wr     = (const float*)d_in[8];
    const float* br     = (const float*)d_in[9];
    const float* att    = (const float*)d_in[10];
    const float* gbias  = (const float*)d_in[11];
    const float* ln_g   = (const float*)d_in[12];
    const float* ln_b   = (const float*)d_in[13];
    const float* h1_W   = (const float*)d_in[14];
    const float* h1_b   = (const float*)d_in[15];
    const float* h2_W   = (const float*)d_in[16];
    const float* h2_b   = (const float*)d_in[17];
    float* out = (float*)d_out;

    const int DSM = 2 * STG_B;   // 81920 B dynamic smem
    cudaFuncSetAttribute(k_gemm<1, 0>, cudaFuncAttributeMaxDynamicSharedMemorySize, DSM);
    cudaFuncSetAttribute(k_gemm<0, 1>, cudaFuncAttributeMaxDynamicSharedMemorySize, DSM);
    (void)cudaGetLastError();   // clear any sticky non-fatal status before capture

    const int NT = (N_NODES + 127) / 128;      // 157 row tiles
    const dim3 GS(NT, 2, 2);                   // split-K grids (proj, h1)
    const dim3 GH(NT, 4);                      // fused hop grid (L cols0/1, R cols0/1)
    const int T4F = (N_NODES * IN_DIM) / 4;

    // weight + feature splits first, then proj at launch index 3 (ncu profiles index 3)
    k_tsplit <<<(IN_DIM * HID) / 256, 256>>>(proj_W, IN_DIM, HID, OFF_PROJ);   // 0
    k_tsplit7<<<(7 * 65536) / 256, 256>>>(Wl, Wr, h1_W);                       // 1
    k_asplit <<<(T4F + 255) / 256, 256>>>(features, T4F);                      // 2
    k_gemm<0, 1><<<GS, 256, DSM>>>(OFF_PROJ, 0, proj_b, nullptr, N_NODES, IN_DIM); // 3
    k_ln<<<(N_NODES * 32 + 255) / 256, 256>>>(n0_g, n0_b);                     // 4

    // CSR build (only needed before the first k_gat)
    k_clear  <<<(N_NODES + 255) / 256, 256>>>();                               // 5
    k_hist   <<<(EP + 255) / 256, 256>>>(ei);                                  // 6
    k_scan   <<<1, 1024>>>();                                                  // 7
    k_scatter<<<(EP + 255) / 256, 256>>>(ei);                                  // 8

    for (int h = 0; h < HOPS; h++){
        k_gemm<1, 0><<<GH, 256, DSM>>>(OFF_WL + h * HID * HID, OFF_WR + h * HID * HID,
                                       bl + h * HID, br + h * HID, N_NODES, HID);
        k_gat<<<(N_NODES * 32 + 255) / 256, 256>>>(att + h * HEADS * (HID / HEADS),
                                                   gbias + h * HID, ln_g + h * HID, ln_b + h * HID);
    }

    // head: h1 split-K partials -> g_xl/g_pp ; head2 fuses sum + exact GELU + final matmul
    k_gemm<0, 1><<<GS, 256, DSM>>>(OFF_H1, 0, h1_b, nullptr, N_NODES, HID);
    k_head2<<<(N_NODES * 32 + 255) / 256, 256>>>(h2_W, h2_b, out);

    (void)in_sizes; (void)n_in; (void)out_size;
}

// round 14
// speedup vs baseline: 2.2364x; 1.0103x over previous
#include <cuda_runtime.h>
#include <cuda_bf16.h>
#include <cstdint>
#include <cstddef>

#define N_NODES 20000
#define IN_DIM  1536
#define HID     256
#define HEADS   4
#define HOPS    3
#define NCLS    3
#define NE      320000
#define EP      (NE + N_NODES)     /* 340000 edges incl. self loops */
#define LN_EPS  1e-5f
#define NEG_SLOPE 0.2f

// weight arena offsets (bf16 elements), all K-major transposed: Wt[n][k] = W[k][n]
#define OFF_PROJ 0                         /* 256 x 1536 */
#define OFF_WL   393216                    /* 3 x 256 x 256 */
#define OFF_WR   589824                    /* 3 x 256 x 256 */
#define OFF_H1   786432                    /* 256 x 256 */
#define W_ARENA  851968

// ---------------- scratch (static device globals: no runtime allocation) ----------------
__device__ float g_x [N_NODES * HID];
__device__ float g_xl[N_NODES * HID];     // also head1 partial out
__device__ float g_xr[N_NODES * HID];
__device__ float g_pp[N_NODES * HID];     // split-K partial (proj / h1)
__device__ int   g_rowstart[N_NODES + 1];
__device__ int   g_counts[N_NODES];
__device__ int   g_cursor[N_NODES];
__device__ int   g_src[EP];
__device__ __nv_bfloat16 g_bhi[W_ARENA];          // weight hi split (K-major)
__device__ __nv_bfloat16 g_blo[W_ARENA];          // weight lo split
__device__ __nv_bfloat16 g_ahi[N_NODES * IN_DIM]; // activation hi split
__device__ __nv_bfloat16 g_alo[N_NODES * IN_DIM]; // activation lo split

// ---------------- small helpers ----------------
__device__ __forceinline__ float warp_sum32(float v){
#pragma unroll
    for (int o = 16; o > 0; o >>= 1) v += __shfl_xor_sync(0xffffffffu, v, o);
    return v;
}
__device__ __forceinline__ float lrelu(float t){ return t > 0.f ? t : NEG_SLOPE * t; }
__device__ __forceinline__ int clamp_idx(int v){
    return ((unsigned)v < (unsigned)N_NODES) ? v : 0;
}
__device__ __forceinline__ uint32_t smem_u32(const void* p){
    uint32_t a;
    asm("{ .reg .u64 t; cvta.to.shared.u64 t, %1; cvt.u32.u64 %0, t; }" : "=r"(a) : "l"(p));
    return a;
}
// split two fp32 into packed bf16x2 hi and lo parts (k-even in low half)
__device__ __forceinline__ void split2(float f0, float f1, uint32_t& hi, uint32_t& lo){
    __nv_bfloat16 h0 = __float2bfloat16(f0);
    __nv_bfloat16 h1 = __float2bfloat16(f1);
    hi = ((uint32_t)__bfloat16_as_ushort(h1) << 16) | (uint32_t)__bfloat16_as_ushort(h0);
    __nv_bfloat16 l0 = __float2bfloat16(f0 - __bfloat162float(h0));
    __nv_bfloat16 l1 = __float2bfloat16(f1 - __bfloat162float(h1));
    lo = ((uint32_t)__bfloat16_as_ushort(l1) << 16) | (uint32_t)__bfloat16_as_ushort(l0);
}
// async 16B copy; pred=false -> zero-fill (src not read)
__device__ __forceinline__ void cp16(uint32_t dst, const void* src, bool pred){
    int sz = pred ? 16 : 0;
    asm volatile("cp.async.cg.shared.global [%0], [%1], 16, %2;"
                 :: "r"(dst), "l"(src), "r"(sz));
}

#define LDMX4(r, addr) \
    asm volatile("ldmatrix.sync.aligned.m8n8.x4.shared.b16 {%0,%1,%2,%3}, [%4];" \
                 : "=r"((r)[0]), "=r"((r)[1]), "=r"((r)[2]), "=r"((r)[3]) : "r"(addr))

__device__ __forceinline__ void mma16816(float* c, const uint32_t* a, uint32_t b0, uint32_t b1){
    asm volatile(
        "mma.sync.aligned.m16n8k16.row.col.f32.bf16.bf16.f32 "
        "{%0,%1,%2,%3}, {%4,%5,%6,%7}, {%8,%9}, {%0,%1,%2,%3};"
        : "+f"(c[0]), "+f"(c[1]), "+f"(c[2]), "+f"(c[3])
        : "r"(a[0]), "r"(a[1]), "r"(a[2]), "r"(a[3]), "r"(b0), "r"(b1));
}

// ---------------- CSR build ----------------
__global__ void k_clear(){
    int i = blockIdx.x * blockDim.x + threadIdx.x;
    if (i < N_NODES){ g_counts[i] = 0; g_cursor[i] = 0; }
}
__global__ void k_hist(const int* __restrict__ ei){
    int e = blockIdx.x * blockDim.x + threadIdx.x;
    if (e >= EP) return;
    int dst = (e < NE) ? clamp_idx(ei[NE + e]) : (e - NE);
    atomicAdd(&g_counts[dst], 1);
}
__global__ void k_scan(){
    __shared__ int sm[1024];
    __shared__ int soff;
    int tid = threadIdx.x;
    if (tid == 0) soff = 0;
    __syncthreads();
    for (int base = 0; base < N_NODES; base += 1024){
        int idx = base + tid;
        int v = (idx < N_NODES) ? g_counts[idx] : 0;
        sm[tid] = v;
        __syncthreads();
        for (int s = 1; s < 1024; s <<= 1){
            int t = (tid >= s) ? sm[tid - s] : 0;
            __syncthreads();
            sm[tid] += t;
            __syncthreads();
        }
        if (idx < N_NODES) g_rowstart[idx] = soff + sm[tid] - v;
        int tot = sm[1023];
        __syncthreads();
        if (tid == 0) soff += tot;
        __syncthreads();
    }
    if (tid == 0) g_rowstart[N_NODES] = soff;
}
__global__ void k_scatter(const int* __restrict__ ei){
    int e = blockIdx.x * blockDim.x + threadIdx.x;
    if (e >= EP) return;
    int src, dst;
    if (e < NE){ src = clamp_idx(ei[e]); dst = clamp_idx(ei[NE + e]); }
    else       { src = e - NE;           dst = src; }
    int pos = g_rowstart[dst] + atomicAdd(&g_cursor[dst], 1);
    g_src[pos] = src;
}

// ---------------- weight transpose + bf16 split ----------------
__global__ void k_tsplit(const float* __restrict__ W, int K, int N, int ooff){
    int i = blockIdx.x * blockDim.x + threadIdx.x;
    if (i >= K * N) return;
    int k = i / N, n = i - k * N;
    float w = W[i];
    __nv_bfloat16 h = __float2bfloat16(w);
    g_bhi[ooff + (size_t)n * K + k] = h;
    g_blo[ooff + (size_t)n * K + k] = __float2bfloat16(w - __bfloat162float(h));
}
// all seven 256x256 weights in one launch: 3x Wl, 3x Wr, h1
__global__ void k_tsplit7(const float* __restrict__ Wl, const float* __restrict__ Wr,
                          const float* __restrict__ h1){
    int i = blockIdx.x * blockDim.x + threadIdx.x;
    if (i >= 7 * 65536) return;
    int slab = i >> 16, j = i & 65535;
    const float* src; int ooff;
    if (slab < 3){ src = Wl + slab * 65536;      ooff = OFF_WL + slab * 65536; }
    else if (slab < 6){ src = Wr + (slab - 3) * 65536; ooff = OFF_WR + (slab - 3) * 65536; }
    else { src = h1; ooff = OFF_H1; }
    int k = j >> 8, n = j & 255;
    float w = src[j];
    __nv_bfloat16 h = __float2bfloat16(w);
    g_bhi[ooff + n * 256 + k] = h;
    g_blo[ooff + n * 256 + k] = __float2bfloat16(w - __bfloat162float(h));
}

// ---------------- feature bf16 split (proj input only) ----------------
__global__ void k_asplit(const float* __restrict__ A, int total4){
    int i = blockIdx.x * blockDim.x + threadIdx.x;
    if (i >= total4) return;
    float4 f = ((const float4*)A)[i];
    uint32_t h0, l0, h1, l1;
    split2(f.x, f.y, h0, l0);
    split2(f.z, f.w, h1, l1);
    ((uint2*)g_ahi)[i] = make_uint2(h0, h1);
    ((uint2*)g_alo)[i] = make_uint2(l0, l1);
}

// ---------------- warp-MMA bf16 split GEMM, cp.async double-buffered --------------------
// CTA tile 128x128, 8 warps (4m x 2n), warp tile 32x64, BK=32.
// D = Ah*Bh + Al*Bh + Ah*Bl  (residual ~2^-17). A pre-split in g_ahi/g_alo.
// Inner loop is TERM-PASS ordered: per 4-column group, all hi*hi MMAs, then all
// lo*hi, then all hi*lo -> dependent MMAs on the same accumulator are 8 apart
// (RAW chain hidden), bit-identical accumulation order per accumulator.
// HOP=1: grid (tiles,4): (y&1)->nc0, (y>>1)->L/R weight + g_xl/g_xr output.
// SPLITK=1 (HOP=0): grid (tiles,2,2): z = K-half; z=0 -> g_xl (+bias), z=1 -> g_pp (raw).
#define SROW 40
#define OFF_AH  0
#define OFF_AL  10240
#define OFF_BH  20480
#define OFF_BL  30720
#define STG_B   40960

template<int HOP, int SPLITK>
__global__ __launch_bounds__(256, 2)
void k_gemm(int boffL, int boffR, const float* __restrict__ biasL,
            const float* __restrict__ biasR, int M, int K)
{
    extern __shared__ __align__(16) uint8_t dyn[];

    int tid = threadIdx.x, wid = tid >> 5, lane = tid & 31;
    int warp_m = wid & 3, warp_n = wid >> 2;
    int row0 = blockIdx.x * 128;

    int nc0, boff, kbase = 0, Keff = K;
    bool addb = true;
    const float* bias;
    float* out;
    if (HOP){
        int yy = blockIdx.y;
        int isR = yy >> 1;
        nc0  = (yy & 1) * 128;
        boff = isR ? boffR : boffL;
        bias = isR ? biasR : biasL;
        out  = isR ? g_xr : g_xl;
    } else {
        nc0  = blockIdx.y * 128;
        boff = boffL;
        bias = biasL;
        out  = g_xl;
        if (SPLITK){
            int z = blockIdx.z;
            Keff  = K >> 1;
            kbase = z * Keff;
            out   = z ? g_pp : g_xl;
            addb  = (z == 0);
        }
    }

    float acc[2][8][4];
#pragma unroll
    for (int mt = 0; mt < 2; mt++)
#pragma unroll
        for (int nt = 0; nt < 8; nt++)
#pragma unroll
            for (int q = 0; q < 4; q++) acc[mt][nt][q] = 0.f;

    // ---- loader mapping: thread -> (row r, k-half) ----
    int r = tid >> 1, half = tid & 1;
    int grow = row0 + r;
    bool rok = grow < M;
    const __nv_bfloat16* ahp = g_ahi + (size_t)grow * K + kbase + half * 16;
    const __nv_bfloat16* alp = g_alo + (size_t)grow * K + kbase + half * 16;
    const __nv_bfloat16* bhp = g_bhi + boff + (size_t)(nc0 + r) * K + kbase + half * 16;
    const __nv_bfloat16* blp = g_blo + boff + (size_t)(nc0 + r) * K + kbase + half * 16;

    uint32_t base = smem_u32(dyn);
    uint32_t ldOff = (uint32_t)((r * SROW + half * 16) * 2);

    // ---- ldmatrix per-lane fragment offsets (within an array) ----
    int lrow = lane & 15, lcol = (lane >> 4) * 8;
    uint32_t aFrag = (uint32_t)(((warp_m * 32 + lrow) * SROW + lcol) * 2);
    uint32_t bFrag = (uint32_t)(((warp_n * 64 + lrow) * SROW + lcol) * 2);

    int iters = Keff >> 5;

    // prologue: stage 0 loads
    {
        uint32_t sb = base;
        cp16(sb + OFF_AH + ldOff,      ahp,     rok);
        cp16(sb + OFF_AH + ldOff + 16, ahp + 8, rok);
        cp16(sb + OFF_AL + ldOff,      alp,     rok);
        cp16(sb + OFF_AL + ldOff + 16, alp + 8, rok);
        cp16(sb + OFF_BH + ldOff,      bhp,     true);
        cp16(sb + OFF_BH + ldOff + 16, bhp + 8, true);
        cp16(sb + OFF_BL + ldOff,      blp,     true);
        cp16(sb + OFF_BL + ldOff + 16, blp + 8, true);
        asm volatile("cp.async.commit_group;" ::: "memory");
    }

    for (int it = 0; it < iters; it++){
        if (it + 1 < iters){
            int k1 = (it + 1) << 5;
            uint32_t sb = base + ((it + 1) & 1) * STG_B;
            cp16(sb + OFF_AH + ldOff,      ahp + k1,     rok);
            cp16(sb + OFF_AH + ldOff + 16, ahp + k1 + 8, rok);
            cp16(sb + OFF_AL + ldOff,      alp + k1,     rok);
            cp16(sb + OFF_AL + ldOff + 16, alp + k1 + 8, rok);
            cp16(sb + OFF_BH + ldOff,      bhp + k1,     true);
            cp16(sb + OFF_BH + ldOff + 16, bhp + k1 + 8, true);
            cp16(sb + OFF_BL + ldOff,      blp + k1,     true);
            cp16(sb + OFF_BL + ldOff + 16, blp + k1 + 8, true);
            asm volatile("cp.async.commit_group;" ::: "memory");
            asm volatile("cp.async.wait_group 1;" ::: "memory");
        } else {
            asm volatile("cp.async.wait_group 0;" ::: "memory");
        }
        __syncthreads();

        uint32_t sb = base + (it & 1) * STG_B;
        uint32_t aBH = sb + OFF_AH + aFrag, aBL = sb + OFF_AL + aFrag;
        uint32_t bBH = sb + OFF_BH + bFrag, bBL = sb + OFF_BL + bFrag;

#pragma unroll
        for (int kc = 0; kc < 2; kc++){
            uint32_t ah[2][4], al[2][4];
#pragma unroll
            for (int mt = 0; mt < 2; mt++){
                LDMX4(ah[mt], aBH + (uint32_t)((mt * 16 * SROW + kc * 16) * 2));
                LDMX4(al[mt], aBL + (uint32_t)((mt * 16 * SROW + kc * 16) * 2));
            }
#pragma unroll
            for (int g = 0; g < 2; g++){          // column group: nt = 4g .. 4g+3
                uint32_t bh[2][4], bl[2][4];
#pragma unroll
                for (int q = 0; q < 2; q++){      // nt2 within group
                    int nt2 = g * 2 + q;
                    LDMX4(bh[q], bBH + (uint32_t)((nt2 * 16 * SROW + kc * 16) * 2));
                    LDMX4(bl[q], bBL + (uint32_t)((nt2 * 16 * SROW + kc * 16) * 2));
                }
                // pass 1: hi*hi  (8 MMAs, all distinct accumulators)
#pragma unroll
                for (int q = 0; q < 2; q++)
#pragma unroll
                    for (int p = 0; p < 2; p++)
#pragma unroll
                        for (int mt = 0; mt < 2; mt++)
                            mma16816(acc[mt][g * 4 + q * 2 + p], ah[mt], bh[q][p], bh[q][p + 2]);
                // pass 2: lo*hi
#pragma unroll
                for (int q = 0; q < 2; q++)
#pragma unroll
                    for (int p = 0; p < 2; p++)
#pragma unroll
                        for (int mt = 0; mt < 2; mt++)
                            mma16816(acc[mt][g * 4 + q * 2 + p], al[mt], bh[q][p], bh[q][p + 2]);
                // pass 3: hi*lo
#pragma unroll
                for (int q = 0; q < 2; q++)
#pragma unroll
                    for (int p = 0; p < 2; p++)
#pragma unroll
                        for (int mt = 0; mt < 2; mt++)
                            mma16816(acc[mt][g * 4 + q * 2 + p], ah[mt], bl[q][p], bl[q][p + 2]);
            }
        }
        __syncthreads();   // all fragment reads done before stage is overwritten
    }

    // ---------------- epilogue: (+bias on z=0), fp32 store ----------------
    int groupID = lane >> 2, tig = lane & 3;
#pragma unroll
    for (int mt = 0; mt < 2; mt++){
        int ra = row0 + warp_m * 32 + mt * 16 + groupID;
        int rb = ra + 8;
#pragma unroll
        for (int nt = 0; nt < 8; nt++){
            int col = nc0 + warp_n * 64 + nt * 8 + tig * 2;
            float b0 = addb ? bias[col]     : 0.f;
            float b1 = addb ? bias[col + 1] : 0.f;
            float v0 = acc[mt][nt][0] + b0, v1 = acc[mt][nt][1] + b1;
            float v2 = acc[mt][nt][2] + b0, v3 = acc[mt][nt][3] + b1;
            if (ra < M){
                out[(size_t)ra * HID + col]     = v0;
                out[(size_t)ra * HID + col + 1] = v1;
            }
            if (rb < M){
                out[(size_t)rb * HID + col]     = v2;
                out[(size_t)rb * HID + col + 1] = v3;
            }
        }
    }
}

// ---------------- LayerNorm (proj): g_x = LN(g_xl + g_pp); emits bf16 splits --------------
__global__ void k_ln(const float* __restrict__ g, const float* __restrict__ b){
    int gw = (int)((blockIdx.x * blockDim.x + threadIdx.x) >> 5);
    if (gw >= N_NODES) return;
    int lane = threadIdx.x & 31, d = lane * 8;
    const float4* p  = (const float4*)(g_xl + (size_t)gw * HID + d);
    const float4* pq = (const float4*)(g_pp + (size_t)gw * HID + d);
    float4 v0 = p[0], v1 = p[1];
    float4 w0 = pq[0], w1 = pq[1];
    float v[8] = {v0.x + w0.x, v0.y + w0.y, v0.z + w0.z, v0.w + w0.w,
                  v1.x + w1.x, v1.y + w1.y, v1.z + w1.z, v1.w + w1.w};
    float s = 0.f, ss = 0.f;
#pragma unroll
    for (int q = 0; q < 8; q++){ s += v[q]; ss += v[q] * v[q]; }
    s  = warp_sum32(s);
    ss = warp_sum32(ss);
    float mu  = s  * (1.f / 256.f);
    float var = ss * (1.f / 256.f) - mu * mu;
    float inv = rsqrtf(var + LN_EPS);
    float* op = g_x + (size_t)gw * HID + d;
    float o[8];
#pragma unroll
    for (int q = 0; q < 8; q++){
        o[q] = (v[q] - mu) * inv * g[d + q] + b[d + q];
        op[q] = o[q];
    }
    uint32_t h0, l0, h1, l1, h2, l2, h3, l3;
    split2(o[0], o[1], h0, l0);  split2(o[2], o[3], h1, l1);
    split2(o[4], o[5], h2, l2);  split2(o[6], o[7], h3, l3);
    int idx = gw * (HID / 4) + lane * 2;
    ((uint2*)g_ahi)[idx]     = make_uint2(h0, h1);
    ((uint2*)g_ahi)[idx + 1] = make_uint2(h2, h3);
    ((uint2*)g_alo)[idx]     = make_uint2(l0, l1);
    ((uint2*)g_alo)[idx + 1] = make_uint2(l2, l3);
}

// ---------------- fused GAT hop: online softmax + agg + gbias + residual + LN + split -----
__global__ void k_gat(const float* __restrict__ att,
                      const float* __restrict__ gbias,
                      const float* __restrict__ lng,
                      const float* __restrict__ lnb){
    int gw = (int)((blockIdx.x * blockDim.x + threadIdx.x) >> 5);
    if (gw >= N_NODES) return;
    int lane = threadIdx.x & 31, d = lane * 8;

    const float4* pr = (const float4*)(g_xr + (size_t)gw * HID + d);
    float4 r0 = pr[0], r1 = pr[1];
    const float4* pa = (const float4*)(att + d);
    float4 a0 = __ldg(pa), a1 = __ldg(pa + 1);

    float m = -1e30f, denom = 0.f;
    float acc[8] = {0.f, 0.f, 0.f, 0.f, 0.f, 0.f, 0.f, 0.f};

    int s = g_rowstart[gw], e = g_rowstart[gw + 1];
    for (int j = s; j < e; j++){
        int src = g_src[j];
        const float4* pl = (const float4*)(g_xl + (size_t)src * HID + d);
        float4 l0 = pl[0], l1 = pl[1];

        float t = 0.f;
        t = fmaf(lrelu(l0.x + r0.x), a0.x, t);
        t = fmaf(lrelu(l0.y + r0.y), a0.y, t);
        t = fmaf(lrelu(l0.z + r0.z), a0.z, t);
        t = fmaf(lrelu(l0.w + r0.w), a0.w, t);
        t = fmaf(lrelu(l1.x + r1.x), a1.x, t);
        t = fmaf(lrelu(l1.y + r1.y), a1.y, t);
        t = fmaf(lrelu(l1.z + r1.z), a1.z, t);
        t = fmaf(lrelu(l1.w + r1.w), a1.w, t);
        t += __shfl_xor_sync(0xffffffffu, t, 1);
        t += __shfl_xor_sync(0xffffffffu, t, 2);
        t += __shfl_xor_sync(0xffffffffu, t, 4);

        float mn = fmaxf(m, t);
        float sc = expf(m - mn);      // first iter: expf(-inf) = 0
        float w  = expf(t - mn);
        denom = fmaf(denom, sc, w);
        acc[0] = fmaf(acc[0], sc, w * l0.x);
        acc[1] = fmaf(acc[1], sc, w * l0.y);
        acc[2] = fmaf(acc[2], sc, w * l0.z);
        acc[3] = fmaf(acc[3], sc, w * l0.w);
        acc[4] = fmaf(acc[4], sc, w * l1.x);
        acc[5] = fmaf(acc[5], sc, w * l1.y);
        acc[6] = fmaf(acc[6], sc, w * l1.z);
        acc[7] = fmaf(acc[7], sc, w * l1.w);
        m = mn;
    }

    float inv = 1.f / denom;
    float* xp = g_x + (size_t)gw * HID + d;
    float v[8];
#pragma unroll
    for (int q = 0; q < 8; q++) v[q] = fmaf(acc[q], inv, gbias[d + q] + xp[q]);

    float sm = 0.f, ss = 0.f;
#pragma unroll
    for (int q = 0; q < 8; q++){ sm += v[q]; ss += v[q] * v[q]; }
    sm = warp_sum32(sm);
    ss = warp_sum32(ss);
    float mu  = sm * (1.f / 256.f);
    float var = ss * (1.f / 256.f) - mu * mu;
    float rin = rsqrtf(var + LN_EPS);
    float o[8];
#pragma unroll
    for (int q = 0; q < 8; q++){
        o[q] = (v[q] - mu) * rin * lng[d + q] + lnb[d + q];
        xp[q] = o[q];
    }
    uint32_t h0, l0, h1, l1, h2, l2, h3, l3;
    split2(o[0], o[1], h0, l0);  split2(o[2], o[3], h1, l1);
    split2(o[4], o[5], h2, l2);  split2(o[6], o[7], h3, l3);
    int idx = gw * (HID / 4) + lane * 2;
    ((uint2*)g_ahi)[idx]     = make_uint2(h0, h1);
    ((uint2*)g_ahi)[idx + 1] = make_uint2(h2, h3);
    ((uint2*)g_alo)[idx]     = make_uint2(l0, l1);
    ((uint2*)g_alo)[idx + 1] = make_uint2(l2, l3);
}

// ---------------- head 2: out = gelu(xl + pp) @ h2_W + h2_b -------------------------------
__global__ void k_head2(const float* __restrict__ W2, const float* __restrict__ b2,
                        float* __restrict__ out){
    __shared__ float ws[HID * NCLS];
    int tid = threadIdx.x;
    for (int i = tid; i < HID * NCLS; i += blockDim.x) ws[i] = W2[i];
    __syncthreads();
    int gw = (int)((blockIdx.x * blockDim.x + tid) >> 5);
    if (gw >= N_NODES) return;
    int lane = tid & 31;
    const float* row = g_xl + (size_t)gw * HID;
    const float* prt = g_pp + (size_t)gw * HID;
    float a0 = 0.f, a1 = 0.f, a2 = 0.f;
#pragma unroll
    for (int q = 0; q < 8; q++){
        int k = lane + 32 * q;
        float xv = row[k] + prt[k];
        xv = 0.5f * xv * (1.f + erff(xv * 0.70710678118654752440f));
        a0 = fmaf(xv, ws[k * 3 + 0], a0);
        a1 = fmaf(xv, ws[k * 3 + 1], a1);
        a2 = fmaf(xv, ws[k * 3 + 2], a2);
    }
    a0 = warp_sum32(a0); a1 = warp_sum32(a1); a2 = warp_sum32(a2);
    if (lane == 0){
        out[(size_t)gw * NCLS + 0] = a0 + b2[0];
        out[(size_t)gw * NCLS + 1] = a1 + b2[1];
        out[(size_t)gw * NCLS + 2] = a2 + b2[2];
    }
}

// ---------------- launch ----------------
extern "C" void kernel_launch(void* const* d_in, const int* in_sizes, int n_in,
                              void* d_out, int out_size)
{
    const float* features = (const float*)d_in[0];
    const int*   ei       = (const int*)d_in[1];     // int32 (JAX x64 disabled)
    const float* proj_W = (const float*)d_in[2];
    const float* proj_b = (const float*)d_in[3];
    const float* n0_g   = (const float*)d_in[4];
    const float* n0_b   = (const float*)d_in[5];
    const float* Wl     = (const float*)d_in[6];
    const float* bl     = (const float*)d_in[7];
    const float* Wr     = (const float*)d_in[8];
    const float* br     = (const float*)d_in[9];
    const float* att    = (const float*)d_in[10];
    const float* gbias  = (const float*)d_in[11];
    const float* ln_g   = (const float*)d_in[12];
    const float* ln_b   = (const float*)d_in[13];
    const float* h1_W   = (const float*)d_in[14];
    const float* h1_b   = (const float*)d_in[15];
    const float* h2_W   = (const float*)d_in[16];
    const float* h2_b   = (const float*)d_in[17];
    float* out = (float*)d_out;

    const int DSM = 2 * STG_B;   // 81920 B dynamic smem
    cudaFuncSetAttribute(k_gemm<1, 0>, cudaFuncAttributeMaxDynamicSharedMemorySize, DSM);
    cudaFuncSetAttribute(k_gemm<0, 1>, cudaFuncAttributeMaxDynamicSharedMemorySize, DSM);
    (void)cudaGetLastError();   // clear any sticky non-fatal status before capture

    const int NT = (N_NODES + 127) / 128;      // 157 row tiles
    const dim3 GS(NT, 2, 2);                   // split-K grids (proj, h1)
    const dim3 GH(NT, 4);                      // fused hop grid (L cols0/1, R cols0/1)
    const int T4F = (N_NODES * IN_DIM) / 4;

    // weight + feature splits first, then proj at launch index 3 (ncu profiles index 3)
    k_tsplit <<<(IN_DIM * HID) / 256, 256>>>(proj_W, IN_DIM, HID, OFF_PROJ);   // 0
    k_tsplit7<<<(7 * 65536) / 256, 256>>>(Wl, Wr, h1_W);                       // 1
    k_asplit <<<(T4F + 255) / 256, 256>>>(features, T4F);                      // 2
    k_gemm<0, 1><<<GS, 256, DSM>>>(OFF_PROJ, 0, proj_b, nullptr, N_NODES, IN_DIM); // 3
    k_ln<<<(N_NODES * 32 + 255) / 256, 256>>>(n0_g, n0_b);                     // 4

    // CSR build (only needed before the first k_gat)
    k_clear  <<<(N_NODES + 255) / 256, 256>>>();                               // 5
    k_hist   <<<(EP + 255) / 256, 256>>>(ei);                                  // 6
    k_scan   <<<1, 1024>>>();                                                  // 7
    k_scatter<<<(EP + 255) / 256, 256>>>(ei);                                  // 8

    for (int h = 0; h < HOPS; h++){
        k_gemm<1, 0><<<GH, 256, DSM>>>(OFF_WL + h * HID * HID, OFF_WR + h * HID * HID,
                                       bl + h * HID, br + h * HID, N_NODES, HID);
        k_gat<<<(N_NODES * 32 + 255) / 256, 256>>>(att + h * HEADS * (HID / HEADS),
                                                   gbias + h * HID, ln_g + h * HID, ln_b + h * HID);
    }

    // head: h1 split-K partials -> g_xl/g_pp ; head2 fuses sum + exact GELU + final matmul
    k_gemm<0, 1><<<GS, 256, DSM>>>(OFF_H1, 0, h1_b, nullptr, N_NODES, HID);
    k_head2<<<(N_NODES * 32 + 255) / 256, 256>>>(h2_W, h2_b, out);

    (void)in_sizes; (void)n_in; (void)out_size;
}

// round 15
// speedup vs baseline: 2.2696x; 1.0149x over previous
#include <cuda_runtime.h>
#include <cuda_bf16.h>
#include <cstdint>
#include <cstddef>

#define N_NODES 20000
#define IN_DIM  1536
#define HID     256
#define HEADS   4
#define HOPS    3
#define NCLS    3
#define NE      320000
#define EP      (NE + N_NODES)     /* 340000 edges incl. self loops */
#define LN_EPS  1e-5f
#define NEG_SLOPE 0.2f

// weight arena offsets (bf16 elements), all K-major transposed: Wt[n][k] = W[k][n]
#define OFF_PROJ 0                         /* 256 x 1536 */
#define OFF_WL   393216                    /* 3 x 256 x 256 */
#define OFF_WR   589824                    /* 3 x 256 x 256 */
#define OFF_H1   786432                    /* 256 x 256 */
#define W_ARENA  851968

// ---------------- scratch (static device globals: no runtime allocation) ----------------
__device__ float g_x [N_NODES * HID];
__device__ float g_xl[N_NODES * HID];     // also head1 partial out
__device__ float g_xr[N_NODES * HID];
__device__ float g_pp[N_NODES * HID];     // split-K partial (proj / h1)
__device__ int   g_rowstart[N_NODES + 1];
__device__ int   g_counts[N_NODES];
__device__ int   g_cursor[N_NODES];
__device__ int   g_src[EP];
__device__ __nv_bfloat16 g_bhi[W_ARENA];          // weight hi split (K-major)
__device__ __nv_bfloat16 g_blo[W_ARENA];          // weight lo split
__device__ __nv_bfloat16 g_ahi[N_NODES * IN_DIM]; // activation hi split
__device__ __nv_bfloat16 g_alo[N_NODES * IN_DIM]; // activation lo split

// ---------------- small helpers ----------------
__device__ __forceinline__ float warp_sum32(float v){
#pragma unroll
    for (int o = 16; o > 0; o >>= 1) v += __shfl_xor_sync(0xffffffffu, v, o);
    return v;
}
__device__ __forceinline__ float lrelu(float t){ return t > 0.f ? t : NEG_SLOPE * t; }
__device__ __forceinline__ int clamp_idx(int v){
    return ((unsigned)v < (unsigned)N_NODES) ? v : 0;
}
__device__ __forceinline__ uint32_t smem_u32(const void* p){
    uint32_t a;
    asm("{ .reg .u64 t; cvta.to.shared.u64 t, %1; cvt.u32.u64 %0, t; }" : "=r"(a) : "l"(p));
    return a;
}
// split two fp32 into packed bf16x2 hi and lo parts (k-even in low half)
__device__ __forceinline__ void split2(float f0, float f1, uint32_t& hi, uint32_t& lo){
    __nv_bfloat16 h0 = __float2bfloat16(f0);
    __nv_bfloat16 h1 = __float2bfloat16(f1);
    hi = ((uint32_t)__bfloat16_as_ushort(h1) << 16) | (uint32_t)__bfloat16_as_ushort(h0);
    __nv_bfloat16 l0 = __float2bfloat16(f0 - __bfloat162float(h0));
    __nv_bfloat16 l1 = __float2bfloat16(f1 - __bfloat162float(h1));
    lo = ((uint32_t)__bfloat16_as_ushort(l1) << 16) | (uint32_t)__bfloat16_as_ushort(l0);
}
// async 16B copy; pred=false -> zero-fill (src not read)
__device__ __forceinline__ void cp16(uint32_t dst, const void* src, bool pred){
    int sz = pred ? 16 : 0;
    asm volatile("cp.async.cg.shared.global [%0], [%1], 16, %2;"
                 :: "r"(dst), "l"(src), "r"(sz));
}

#define LDMX4(r, addr) \
    asm volatile("ldmatrix.sync.aligned.m8n8.x4.shared.b16 {%0,%1,%2,%3}, [%4];" \
                 : "=r"((r)[0]), "=r"((r)[1]), "=r"((r)[2]), "=r"((r)[3]) : "r"(addr))

__device__ __forceinline__ void mma16816(float* c, const uint32_t* a, uint32_t b0, uint32_t b1){
    asm volatile(
        "mma.sync.aligned.m16n8k16.row.col.f32.bf16.bf16.f32 "
        "{%0,%1,%2,%3}, {%4,%5,%6,%7}, {%8,%9}, {%0,%1,%2,%3};"
        : "+f"(c[0]), "+f"(c[1]), "+f"(c[2]), "+f"(c[3])
        : "r"(a[0]), "r"(a[1]), "r"(a[2]), "r"(a[3]), "r"(b0), "r"(b1));
}

// ---------------- CSR build ----------------
__global__ void k_clear(){
    int i = blockIdx.x * blockDim.x + threadIdx.x;
    if (i < N_NODES){ g_counts[i] = 0; g_cursor[i] = 0; }
}
__global__ void k_hist(const int* __restrict__ ei){
    int e = blockIdx.x * blockDim.x + threadIdx.x;
    if (e >= EP) return;
    int dst = (e < NE) ? clamp_idx(ei[NE + e]) : (e - NE);
    atomicAdd(&g_counts[dst], 1);
}
__global__ void k_scan(){
    __shared__ int sm[1024];
    __shared__ int soff;
    int tid = threadIdx.x;
    if (tid == 0) soff = 0;
    __syncthreads();
    for (int base = 0; base < N_NODES; base += 1024){
        int idx = base + tid;
        int v = (idx < N_NODES) ? g_counts[idx] : 0;
        sm[tid] = v;
        __syncthreads();
        for (int s = 1; s < 1024; s <<= 1){
            int t = (tid >= s) ? sm[tid - s] : 0;
            __syncthreads();
            sm[tid] += t;
            __syncthreads();
        }
        if (idx < N_NODES) g_rowstart[idx] = soff + sm[tid] - v;
        int tot = sm[1023];
        __syncthreads();
        if (tid == 0) soff += tot;
        __syncthreads();
    }
    if (tid == 0) g_rowstart[N_NODES] = soff;
}
__global__ void k_scatter(const int* __restrict__ ei){
    int e = blockIdx.x * blockDim.x + threadIdx.x;
    if (e >= EP) return;
    int src, dst;
    if (e < NE){ src = clamp_idx(ei[e]); dst = clamp_idx(ei[NE + e]); }
    else       { src = e - NE;           dst = src; }
    int pos = g_rowstart[dst] + atomicAdd(&g_cursor[dst], 1);
    g_src[pos] = src;
}

// ---------------- weight transpose + bf16 split ----------------
__global__ void k_tsplit(const float* __restrict__ W, int K, int N, int ooff){
    int i = blockIdx.x * blockDim.x + threadIdx.x;
    if (i >= K * N) return;
    int k = i / N, n = i - k * N;
    float w = W[i];
    __nv_bfloat16 h = __float2bfloat16(w);
    g_bhi[ooff + (size_t)n * K + k] = h;
    g_blo[ooff + (size_t)n * K + k] = __float2bfloat16(w - __bfloat162float(h));
}
// all seven 256x256 weights in one launch: 3x Wl, 3x Wr, h1
__global__ void k_tsplit7(const float* __restrict__ Wl, const float* __restrict__ Wr,
                          const float* __restrict__ h1){
    int i = blockIdx.x * blockDim.x + threadIdx.x;
    if (i >= 7 * 65536) return;
    int slab = i >> 16, j = i & 65535;
    const float* src; int ooff;
    if (slab < 3){ src = Wl + slab * 65536;      ooff = OFF_WL + slab * 65536; }
    else if (slab < 6){ src = Wr + (slab - 3) * 65536; ooff = OFF_WR + (slab - 3) * 65536; }
    else { src = h1; ooff = OFF_H1; }
    int k = j >> 8, n = j & 255;
    float w = src[j];
    __nv_bfloat16 h = __float2bfloat16(w);
    g_bhi[ooff + n * 256 + k] = h;
    g_blo[ooff + n * 256 + k] = __float2bfloat16(w - __bfloat162float(h));
}

// ---------------- feature bf16 split (proj input only) ----------------
__global__ void k_asplit(const float* __restrict__ A, int total4){
    int i = blockIdx.x * blockDim.x + threadIdx.x;
    if (i >= total4) return;
    float4 f = ((const float4*)A)[i];
    uint32_t h0, l0, h1, l1;
    split2(f.x, f.y, h0, l0);
    split2(f.z, f.w, h1, l1);
    ((uint2*)g_ahi)[i] = make_uint2(h0, h1);
    ((uint2*)g_alo)[i] = make_uint2(l0, l1);
}

// ---------------- warp-MMA bf16 split GEMM, cp.async double-buffered --------------------
// CTA tile 128x64, 8 warps (4m x 2n), warp tile 32x32, BK=32 -> ~75 regs,
// 3 CTAs/SM (24 warps, occ 33%) and last wave 83% full (1256 tiles / 444 slots).
// D = Ah*Bh + Al*Bh + Ah*Bl  (residual ~2^-17). A pre-split in g_ahi/g_alo.
// Stage smem: A 2x10240 + B 2x5120 = 30720 B; 2 stages = 61440 B dynamic.
// HOP=1: grid (157,8): (y&3)*64 -> nc0, (y>>2) -> L/R weight + g_xl/g_xr output.
// SPLITK=1 (HOP=0): grid (157,4,2): z = K-half; z=0 -> g_xl (+bias), z=1 -> g_pp (raw).
#define SROW 40
#define OFF_AH  0
#define OFF_AL  10240
#define OFF_BH  20480
#define OFF_BL  25600
#define STG_B   30720

template<int HOP, int SPLITK>
__global__ __launch_bounds__(256, 3)
void k_gemm(int boffL, int boffR, const float* __restrict__ biasL,
            const float* __restrict__ biasR, int M, int K)
{
    extern __shared__ __align__(16) uint8_t dyn[];

    int tid = threadIdx.x, wid = tid >> 5, lane = tid & 31;
    int warp_m = wid & 3, warp_n = wid >> 2;
    int row0 = blockIdx.x * 128;

    int nc0, boff, kbase = 0, Keff = K;
    bool addb = true;
    const float* bias;
    float* out;
    if (HOP){
        int yy = blockIdx.y;
        int isR = yy >> 2;
        nc0  = (yy & 3) * 64;
        boff = isR ? boffR : boffL;
        bias = isR ? biasR : biasL;
        out  = isR ? g_xr : g_xl;
    } else {
        nc0  = blockIdx.y * 64;
        boff = boffL;
        bias = biasL;
        out  = g_xl;
        if (SPLITK){
            int z = blockIdx.z;
            Keff  = K >> 1;
            kbase = z * Keff;
            out   = z ? g_pp : g_xl;
            addb  = (z == 0);
        }
    }

    float acc[2][4][4];
#pragma unroll
    for (int mt = 0; mt < 2; mt++)
#pragma unroll
        for (int nt = 0; nt < 4; nt++)
#pragma unroll
            for (int q = 0; q < 4; q++) acc[mt][nt][q] = 0.f;

    // ---- loader mapping: thread -> (row r, k-half); warps 0-3 also load B (64 rows) ----
    int r = tid >> 1, half = tid & 1;
    int grow = row0 + r;
    bool rok = grow < M;
    bool bld = (tid < 128);              // uniform per warp
    const __nv_bfloat16* ahp = g_ahi + (size_t)grow * K + kbase + half * 16;
    const __nv_bfloat16* alp = g_alo + (size_t)grow * K + kbase + half * 16;
    int brow = nc0 + (bld ? r : 0);
    const __nv_bfloat16* bhp = g_bhi + boff + (size_t)brow * K + kbase + half * 16;
    const __nv_bfloat16* blp = g_blo + boff + (size_t)brow * K + kbase + half * 16;

    uint32_t base = smem_u32(dyn);
    uint32_t ldOff = (uint32_t)((r * SROW + half * 16) * 2);   // A dst (r<128) / B dst (r<64)

    // ---- ldmatrix per-lane fragment offsets (within an array) ----
    int lrow = lane & 15, lcol = (lane >> 4) * 8;
    uint32_t aFrag = (uint32_t)(((warp_m * 32 + lrow) * SROW + lcol) * 2);
    uint32_t bFrag = (uint32_t)(((warp_n * 32 + lrow) * SROW + lcol) * 2);

    int iters = Keff >> 5;

    // prologue: stage 0 loads
    {
        uint32_t sb = base;
        cp16(sb + OFF_AH + ldOff,      ahp,     rok);
        cp16(sb + OFF_AH + ldOff + 16, ahp + 8, rok);
        cp16(sb + OFF_AL + ldOff,      alp,     rok);
        cp16(sb + OFF_AL + ldOff + 16, alp + 8, rok);
        if (bld){
            cp16(sb + OFF_BH + ldOff,      bhp,     true);
            cp16(sb + OFF_BH + ldOff + 16, bhp + 8, true);
            cp16(sb + OFF_BL + ldOff,      blp,     true);
            cp16(sb + OFF_BL + ldOff + 16, blp + 8, true);
        }
        asm volatile("cp.async.commit_group;" ::: "memory");
    }

    for (int it = 0; it < iters; it++){
        if (it + 1 < iters){
            int k1 = (it + 1) << 5;
            uint32_t sb = base + ((it + 1) & 1) * STG_B;
            cp16(sb + OFF_AH + ldOff,      ahp + k1,     rok);
            cp16(sb + OFF_AH + ldOff + 16, ahp + k1 + 8, rok);
            cp16(sb + OFF_AL + ldOff,      alp + k1,     rok);
            cp16(sb + OFF_AL + ldOff + 16, alp + k1 + 8, rok);
            if (bld){
                cp16(sb + OFF_BH + ldOff,      bhp + k1,     true);
                cp16(sb + OFF_BH + ldOff + 16, bhp + k1 + 8, true);
                cp16(sb + OFF_BL + ldOff,      blp + k1,     true);
                cp16(sb + OFF_BL + ldOff + 16, blp + k1 + 8, true);
            }
            asm volatile("cp.async.commit_group;" ::: "memory");
            asm volatile("cp.async.wait_group 1;" ::: "memory");
        } else {
            asm volatile("cp.async.wait_group 0;" ::: "memory");
        }
        __syncthreads();

        uint32_t sb = base + (it & 1) * STG_B;
        uint32_t aBH = sb + OFF_AH + aFrag, aBL = sb + OFF_AL + aFrag;
        uint32_t bBH = sb + OFF_BH + bFrag, bBL = sb + OFF_BL + bFrag;

#pragma unroll
        for (int kc = 0; kc < 2; kc++){
            uint32_t ah[2][4], al[2][4];
#pragma unroll
            for (int mt = 0; mt < 2; mt++){
                LDMX4(ah[mt], aBH + (uint32_t)((mt * 16 * SROW + kc * 16) * 2));
                LDMX4(al[mt], aBL + (uint32_t)((mt * 16 * SROW + kc * 16) * 2));
            }
#pragma unroll
            for (int nt2 = 0; nt2 < 2; nt2++){
                uint32_t bh[4], bl[4];
                LDMX4(bh, bBH + (uint32_t)((nt2 * 16 * SROW + kc * 16) * 2));
                LDMX4(bl, bBL + (uint32_t)((nt2 * 16 * SROW + kc * 16) * 2));
#pragma unroll
                for (int p = 0; p < 2; p++){
                    int nt = nt2 * 2 + p;
                    uint32_t b0h = bh[p], b1h = bh[p + 2];
                    uint32_t b0l = bl[p], b1l = bl[p + 2];
#pragma unroll
                    for (int mt = 0; mt < 2; mt++){
                        mma16816(acc[mt][nt], ah[mt], b0h, b1h);   // hi*hi
                        mma16816(acc[mt][nt], al[mt], b0h, b1h);   // lo*hi
                        mma16816(acc[mt][nt], ah[mt], b0l, b1l);   // hi*lo
                    }
                }
            }
        }
        __syncthreads();   // all fragment reads done before stage is overwritten
    }

    // ---------------- epilogue: (+bias on z=0), fp32 store ----------------
    int groupID = lane >> 2, tig = lane & 3;
#pragma unroll
    for (int mt = 0; mt < 2; mt++){
        int ra = row0 + warp_m * 32 + mt * 16 + groupID;
        int rb = ra + 8;
#pragma unroll
        for (int nt = 0; nt < 4; nt++){
            int col = nc0 + warp_n * 32 + nt * 8 + tig * 2;
            float b0 = addb ? bias[col]     : 0.f;
            float b1 = addb ? bias[col + 1] : 0.f;
            float v0 = acc[mt][nt][0] + b0, v1 = acc[mt][nt][1] + b1;
            float v2 = acc[mt][nt][2] + b0, v3 = acc[mt][nt][3] + b1;
            if (ra < M){
                out[(size_t)ra * HID + col]     = v0;
                out[(size_t)ra * HID + col + 1] = v1;
            }
            if (rb < M){
                out[(size_t)rb * HID + col]     = v2;
                out[(size_t)rb * HID + col + 1] = v3;
            }
        }
    }
}

// ---------------- LayerNorm (proj): g_x = LN(g_xl + g_pp); emits bf16 splits --------------
__global__ void k_ln(const float* __restrict__ g, const float* __restrict__ b){
    int gw = (int)((blockIdx.x * blockDim.x + threadIdx.x) >> 5);
    if (gw >= N_NODES) return;
    int lane = threadIdx.x & 31, d = lane * 8;
    const float4* p  = (const float4*)(g_xl + (size_t)gw * HID + d);
    const float4* pq = (const float4*)(g_pp + (size_t)gw * HID + d);
    float4 v0 = p[0], v1 = p[1];
    float4 w0 = pq[0], w1 = pq[1];
    float v[8] = {v0.x + w0.x, v0.y + w0.y, v0.z + w0.z, v0.w + w0.w,
                  v1.x + w1.x, v1.y + w1.y, v1.z + w1.z, v1.w + w1.w};
    float s = 0.f, ss = 0.f;
#pragma unroll
    for (int q = 0; q < 8; q++){ s += v[q]; ss += v[q] * v[q]; }
    s  = warp_sum32(s);
    ss = warp_sum32(ss);
    float mu  = s  * (1.f / 256.f);
    float var = ss * (1.f / 256.f) - mu * mu;
    float inv = rsqrtf(var + LN_EPS);
    float* op = g_x + (size_t)gw * HID + d;
    float o[8];
#pragma unroll
    for (int q = 0; q < 8; q++){
        o[q] = (v[q] - mu) * inv * g[d + q] + b[d + q];
        op[q] = o[q];
    }
    uint32_t h0, l0, h1, l1, h2, l2, h3, l3;
    split2(o[0], o[1], h0, l0);  split2(o[2], o[3], h1, l1);
    split2(o[4], o[5], h2, l2);  split2(o[6], o[7], h3, l3);
    int idx = gw * (HID / 4) + lane * 2;
    ((uint2*)g_ahi)[idx]     = make_uint2(h0, h1);
    ((uint2*)g_ahi)[idx + 1] = make_uint2(h2, h3);
    ((uint2*)g_alo)[idx]     = make_uint2(l0, l1);
    ((uint2*)g_alo)[idx + 1] = make_uint2(l2, l3);
}

// ---------------- fused GAT hop: online softmax + agg + gbias + residual + LN + split -----
__global__ void k_gat(const float* __restrict__ att,
                      const float* __restrict__ gbias,
                      const float* __restrict__ lng,
                      const float* __restrict__ lnb){
    int gw = (int)((blockIdx.x * blockDim.x + threadIdx.x) >> 5);
    if (gw >= N_NODES) return;
    int lane = threadIdx.x & 31, d = lane * 8;

    const float4* pr = (const float4*)(g_xr + (size_t)gw * HID + d);
    float4 r0 = pr[0], r1 = pr[1];
    const float4* pa = (const float4*)(att + d);
    float4 a0 = __ldg(pa), a1 = __ldg(pa + 1);

    float m = -1e30f, denom = 0.f;
    float acc[8] = {0.f, 0.f, 0.f, 0.f, 0.f, 0.f, 0.f, 0.f};

    int s = g_rowstart[gw], e = g_rowstart[gw + 1];
    for (int j = s; j < e; j++){
        int src = g_src[j];
        const float4* pl = (const float4*)(g_xl + (size_t)src * HID + d);
        float4 l0 = pl[0], l1 = pl[1];

        float t = 0.f;
        t = fmaf(lrelu(l0.x + r0.x), a0.x, t);
        t = fmaf(lrelu(l0.y + r0.y), a0.y, t);
        t = fmaf(lrelu(l0.z + r0.z), a0.z, t);
        t = fmaf(lrelu(l0.w + r0.w), a0.w, t);
        t = fmaf(lrelu(l1.x + r1.x), a1.x, t);
        t = fmaf(lrelu(l1.y + r1.y), a1.y, t);
        t = fmaf(lrelu(l1.z + r1.z), a1.z, t);
        t = fmaf(lrelu(l1.w + r1.w), a1.w, t);
        t += __shfl_xor_sync(0xffffffffu, t, 1);
        t += __shfl_xor_sync(0xffffffffu, t, 2);
        t += __shfl_xor_sync(0xffffffffu, t, 4);

        float mn = fmaxf(m, t);
        float sc = expf(m - mn);      // first iter: expf(-inf) = 0
        float w  = expf(t - mn);
        denom = fmaf(denom, sc, w);
        acc[0] = fmaf(acc[0], sc, w * l0.x);
        acc[1] = fmaf(acc[1], sc, w * l0.y);
        acc[2] = fmaf(acc[2], sc, w * l0.z);
        acc[3] = fmaf(acc[3], sc, w * l0.w);
        acc[4] = fmaf(acc[4], sc, w * l1.x);
        acc[5] = fmaf(acc[5], sc, w * l1.y);
        acc[6] = fmaf(acc[6], sc, w * l1.z);
        acc[7] = fmaf(acc[7], sc, w * l1.w);
        m = mn;
    }

    float inv = 1.f / denom;
    float* xp = g_x + (size_t)gw * HID + d;
    float v[8];
#pragma unroll
    for (int q = 0; q < 8; q++) v[q] = fmaf(acc[q], inv, gbias[d + q] + xp[q]);

    float sm = 0.f, ss = 0.f;
#pragma unroll
    for (int q = 0; q < 8; q++){ sm += v[q]; ss += v[q] * v[q]; }
    sm = warp_sum32(sm);
    ss = warp_sum32(ss);
    float mu  = sm * (1.f / 256.f);
    float var = ss * (1.f / 256.f) - mu * mu;
    float rin = rsqrtf(var + LN_EPS);
    float o[8];
#pragma unroll
    for (int q = 0; q < 8; q++){
        o[q] = (v[q] - mu) * rin * lng[d + q] + lnb[d + q];
        xp[q] = o[q];
    }
    uint32_t h0, l0, h1, l1, h2, l2, h3, l3;
    split2(o[0], o[1], h0, l0);  split2(o[2], o[3], h1, l1);
    split2(o[4], o[5], h2, l2);  split2(o[6], o[7], h3, l3);
    int idx = gw * (HID / 4) + lane * 2;
    ((uint2*)g_ahi)[idx]     = make_uint2(h0, h1);
    ((uint2*)g_ahi)[idx + 1] = make_uint2(h2, h3);
    ((uint2*)g_alo)[idx]     = make_uint2(l0, l1);
    ((uint2*)g_alo)[idx + 1] = make_uint2(l2, l3);
}

// ---------------- head 2: out = gelu(xl + pp) @ h2_W + h2_b -------------------------------
__global__ void k_head2(const float* __restrict__ W2, const float* __restrict__ b2,
                        float* __restrict__ out){
    __shared__ float ws[HID * NCLS];
    int tid = threadIdx.x;
    for (int i = tid; i < HID * NCLS; i += blockDim.x) ws[i] = W2[i];
    __syncthreads();
    int gw = (int)((blockIdx.x * blockDim.x + tid) >> 5);
    if (gw >= N_NODES) return;
    int lane = tid & 31;
    const float* row = g_xl + (size_t)gw * HID;
    const float* prt = g_pp + (size_t)gw * HID;
    float a0 = 0.f, a1 = 0.f, a2 = 0.f;
#pragma unroll
    for (int q = 0; q < 8; q++){
        int k = lane + 32 * q;
        float xv = row[k] + prt[k];
        xv = 0.5f * xv * (1.f + erff(xv * 0.70710678118654752440f));
        a0 = fmaf(xv, ws[k * 3 + 0], a0);
        a1 = fmaf(xv, ws[k * 3 + 1], a1);
        a2 = fmaf(xv, ws[k * 3 + 2], a2);
    }
    a0 = warp_sum32(a0); a1 = warp_sum32(a1); a2 = warp_sum32(a2);
    if (lane == 0){
        out[(size_t)gw * NCLS + 0] = a0 + b2[0];
        out[(size_t)gw * NCLS + 1] = a1 + b2[1];
        out[(size_t)gw * NCLS + 2] = a2 + b2[2];
    }
}

// ---------------- launch ----------------
extern "C" void kernel_launch(void* const* d_in, const int* in_sizes, int n_in,
                              void* d_out, int out_size)
{
    const float* features = (const float*)d_in[0];
    const int*   ei       = (const int*)d_in[1];     // int32 (JAX x64 disabled)
    const float* proj_W = (const float*)d_in[2];
    const float* proj_b = (const float*)d_in[3];
    const float* n0_g   = (const float*)d_in[4];
    const float* n0_b   = (const float*)d_in[5];
    const float* Wl     = (const float*)d_in[6];
    const float* bl     = (const float*)d_in[7];
    const float* Wr     = (const float*)d_in[8];
    const float* br     = (const float*)d_in[9];
    const float* att    = (const float*)d_in[10];
    const float* gbias  = (const float*)d_in[11];
    const float* ln_g   = (const float*)d_in[12];
    const float* ln_b   = (const float*)d_in[13];
    const float* h1_W   = (const float*)d_in[14];
    const float* h1_b   = (const float*)d_in[15];
    const float* h2_W   = (const float*)d_in[16];
    const float* h2_b   = (const float*)d_in[17];
    float* out = (float*)d_out;

    const int DSM = 2 * STG_B;   // 61440 B dynamic smem
    cudaFuncSetAttribute(k_gemm<1, 0>, cudaFuncAttributeMaxDynamicSharedMemorySize, DSM);
    cudaFuncSetAttribute(k_gemm<0, 1>, cudaFuncAttributeMaxDynamicSharedMemorySize, DSM);
    (void)cudaGetLastError();   // clear any sticky non-fatal status before capture

    const int NT = (N_NODES + 127) / 128;      // 157 row tiles
    const dim3 GS(NT, 4, 2);                   // split-K grids (proj, h1): 1256 CTAs
    const dim3 GH(NT, 8);                      // fused hop grid (L/R x 4 col tiles): 1256 CTAs
    const int T4F = (N_NODES * IN_DIM) / 4;

    // weight + feature splits first, then proj at launch index 3 (ncu profiles index 3)
    k_tsplit <<<(IN_DIM * HID) / 256, 256>>>(proj_W, IN_DIM, HID, OFF_PROJ);   // 0
    k_tsplit7<<<(7 * 65536) / 256, 256>>>(Wl, Wr, h1_W);                       // 1
    k_asplit <<<(T4F + 255) / 256, 256>>>(features, T4F);                      // 2
    k_gemm<0, 1><<<GS, 256, DSM>>>(OFF_PROJ, 0, proj_b, nullptr, N_NODES, IN_DIM); // 3
    k_ln<<<(N_NODES * 32 + 255) / 256, 256>>>(n0_g, n0_b);                     // 4

    // CSR build (only needed before the first k_gat)
    k_clear  <<<(N_NODES + 255) / 256, 256>>>();                               // 5
    k_hist   <<<(EP + 255) / 256, 256>>>(ei);                                  // 6
    k_scan   <<<1, 1024>>>();                                                  // 7
    k_scatter<<<(EP + 255) / 256, 256>>>(ei);                                  // 8

    for (int h = 0; h < HOPS; h++){
        k_gemm<1, 0><<<GH, 256, DSM>>>(OFF_WL + h * HID * HID, OFF_WR + h * HID * HID,
                                       bl + h * HID, br + h * HID, N_NODES, HID);
        k_gat<<<(N_NODES * 32 + 255) / 256, 256>>>(att + h * HEADS * (HID / HEADS),
                                                   gbias + h * HID, ln_g + h * HID, ln_b + h * HID);
    }

    // head: h1 split-K partials -> g_xl/g_pp ; head2 fuses sum + exact GELU + final matmul
    k_gemm<0, 1><<<GS, 256, DSM>>>(OFF_H1, 0, h1_b, nullptr, N_NODES, HID);
    k_head2<<<(N_NODES * 32 + 255) / 256, 256>>>(h2_W, h2_b, out);

    (void)in_sizes; (void)n_in; (void)out_size;
}

// round 16
// speedup vs baseline: 2.2986x; 1.0128x over previous
#include <cuda_runtime.h>
#include <cuda_bf16.h>
#include <cstdint>
#include <cstddef>

#define N_NODES 20000
#define IN_DIM  1536
#define HID     256
#define HEADS   4
#define HOPS    3
#define NCLS    3
#define NE      320000
#define EP      (NE + N_NODES)     /* 340000 edges incl. self loops */
#define LN_EPS  1e-5f
#define NEG_SLOPE 0.2f

// weight arena offsets (bf16 elements), all K-major transposed: Wt[n][k] = W[k][n]
#define OFF_PROJ 0                         /* 256 x 1536 */
#define OFF_WL   393216                    /* 3 x 256 x 256 */
#define OFF_WR   589824                    /* 3 x 256 x 256 */
#define OFF_H1   786432                    /* 256 x 256 */
#define W_ARENA  851968

// ---------------- scratch (static device globals: no runtime allocation) ----------------
__device__ float g_x [N_NODES * HID];
__device__ float g_xl[N_NODES * HID];     // also head1 partial out
__device__ float g_xr[N_NODES * HID];
__device__ float g_pp[N_NODES * HID];     // split-K partial (proj / h1)
__device__ int   g_rowstart[N_NODES + 1];
__device__ int   g_counts[N_NODES];
__device__ int   g_cursor[N_NODES];
__device__ int   g_src[EP];
__device__ __nv_bfloat16 g_bhi[W_ARENA];          // weight hi split (K-major)
__device__ __nv_bfloat16 g_blo[W_ARENA];          // weight lo split
__device__ __nv_bfloat16 g_ahi[N_NODES * IN_DIM]; // activation hi split
__device__ __nv_bfloat16 g_alo[N_NODES * IN_DIM]; // activation lo split

// ---------------- small helpers ----------------
__device__ __forceinline__ float warp_sum32(float v){
#pragma unroll
    for (int o = 16; o > 0; o >>= 1) v += __shfl_xor_sync(0xffffffffu, v, o);
    return v;
}
__device__ __forceinline__ float lrelu(float t){ return t > 0.f ? t : NEG_SLOPE * t; }
__device__ __forceinline__ int clamp_idx(int v){
    return ((unsigned)v < (unsigned)N_NODES) ? v : 0;
}
__device__ __forceinline__ uint32_t smem_u32(const void* p){
    uint32_t a;
    asm("{ .reg .u64 t; cvta.to.shared.u64 t, %1; cvt.u32.u64 %0, t; }" : "=r"(a) : "l"(p));
    return a;
}
// split two fp32 into packed bf16x2 hi and lo parts (k-even in low half)
__device__ __forceinline__ void split2(float f0, float f1, uint32_t& hi, uint32_t& lo){
    __nv_bfloat16 h0 = __float2bfloat16(f0);
    __nv_bfloat16 h1 = __float2bfloat16(f1);
    hi = ((uint32_t)__bfloat16_as_ushort(h1) << 16) | (uint32_t)__bfloat16_as_ushort(h0);
    __nv_bfloat16 l0 = __float2bfloat16(f0 - __bfloat162float(h0));
    __nv_bfloat16 l1 = __float2bfloat16(f1 - __bfloat162float(h1));
    lo = ((uint32_t)__bfloat16_as_ushort(l1) << 16) | (uint32_t)__bfloat16_as_ushort(l0);
}
// async 16B copy; pred=false -> zero-fill (src not read)
__device__ __forceinline__ void cp16(uint32_t dst, const void* src, bool pred){
    int sz = pred ? 16 : 0;
    asm volatile("cp.async.cg.shared.global [%0], [%1], 16, %2;"
                 :: "r"(dst), "l"(src), "r"(sz));
}

#define LDMX4(r, addr) \
    asm volatile("ldmatrix.sync.aligned.m8n8.x4.shared.b16 {%0,%1,%2,%3}, [%4];" \
                 : "=r"((r)[0]), "=r"((r)[1]), "=r"((r)[2]), "=r"((r)[3]) : "r"(addr))

__device__ __forceinline__ void mma16816(float* c, const uint32_t* a, uint32_t b0, uint32_t b1){
    asm volatile(
        "mma.sync.aligned.m16n8k16.row.col.f32.bf16.bf16.f32 "
        "{%0,%1,%2,%3}, {%4,%5,%6,%7}, {%8,%9}, {%0,%1,%2,%3};"
        : "+f"(c[0]), "+f"(c[1]), "+f"(c[2]), "+f"(c[3])
        : "r"(a[0]), "r"(a[1]), "r"(a[2]), "r"(a[3]), "r"(b0), "r"(b1));
}

// ---------------- CSR build ----------------
__global__ void k_clear(){
    int i = blockIdx.x * blockDim.x + threadIdx.x;
    if (i < N_NODES){ g_counts[i] = 0; g_cursor[i] = 0; }
}
__global__ void k_hist(const int* __restrict__ ei){
    int e = blockIdx.x * blockDim.x + threadIdx.x;
    if (e >= EP) return;
    int dst = (e < NE) ? clamp_idx(ei[NE + e]) : (e - NE);
    atomicAdd(&g_counts[dst], 1);
}
__global__ void k_scan(){
    __shared__ int sm[1024];
    __shared__ int soff;
    int tid = threadIdx.x;
    if (tid == 0) soff = 0;
    __syncthreads();
    for (int base = 0; base < N_NODES; base += 1024){
        int idx = base + tid;
        int v = (idx < N_NODES) ? g_counts[idx] : 0;
        sm[tid] = v;
        __syncthreads();
        for (int s = 1; s < 1024; s <<= 1){
            int t = (tid >= s) ? sm[tid - s] : 0;
            __syncthreads();
            sm[tid] += t;
            __syncthreads();
        }
        if (idx < N_NODES) g_rowstart[idx] = soff + sm[tid] - v;
        int tot = sm[1023];
        __syncthreads();
        if (tid == 0) soff += tot;
        __syncthreads();
    }
    if (tid == 0) g_rowstart[N_NODES] = soff;
}
__global__ void k_scatter(const int* __restrict__ ei){
    int e = blockIdx.x * blockDim.x + threadIdx.x;
    if (e >= EP) return;
    int src, dst;
    if (e < NE){ src = clamp_idx(ei[e]); dst = clamp_idx(ei[NE + e]); }
    else       { src = e - NE;           dst = src; }
    int pos = g_rowstart[dst] + atomicAdd(&g_cursor[dst], 1);
    g_src[pos] = src;
}

// ---------------- weight transpose + bf16 split ----------------
__global__ void k_tsplit(const float* __restrict__ W, int K, int N, int ooff){
    int i = blockIdx.x * blockDim.x + threadIdx.x;
    if (i >= K * N) return;
    int k = i / N, n = i - k * N;
    float w = W[i];
    __nv_bfloat16 h = __float2bfloat16(w);
    g_bhi[ooff + (size_t)n * K + k] = h;
    g_blo[ooff + (size_t)n * K + k] = __float2bfloat16(w - __bfloat162float(h));
}
// all seven 256x256 weights in one launch: 3x Wl, 3x Wr, h1
__global__ void k_tsplit7(const float* __restrict__ Wl, const float* __restrict__ Wr,
                          const float* __restrict__ h1){
    int i = blockIdx.x * blockDim.x + threadIdx.x;
    if (i >= 7 * 65536) return;
    int slab = i >> 16, j = i & 65535;
    const float* src; int ooff;
    if (slab < 3){ src = Wl + slab * 65536;      ooff = OFF_WL + slab * 65536; }
    else if (slab < 6){ src = Wr + (slab - 3) * 65536; ooff = OFF_WR + (slab - 3) * 65536; }
    else { src = h1; ooff = OFF_H1; }
    int k = j >> 8, n = j & 255;
    float w = src[j];
    __nv_bfloat16 h = __float2bfloat16(w);
    g_bhi[ooff + n * 256 + k] = h;
    g_blo[ooff + n * 256 + k] = __float2bfloat16(w - __bfloat162float(h));
}

// ---------------- feature bf16 split (proj input only) ----------------
__global__ void k_asplit(const float* __restrict__ A, int total4){
    int i = blockIdx.x * blockDim.x + threadIdx.x;
    if (i >= total4) return;
    float4 f = ((const float4*)A)[i];
    uint32_t h0, l0, h1, l1;
    split2(f.x, f.y, h0, l0);
    split2(f.z, f.w, h1, l1);
    ((uint2*)g_ahi)[i] = make_uint2(h0, h1);
    ((uint2*)g_alo)[i] = make_uint2(l0, l1);
}

// ---------------- warp-MMA bf16 split GEMM, cp.async double-buffered --------------------
// CTA tile 128x64, 8 warps (4m x 2n), warp tile 32x32, BK=32 -> ~80 regs, 3 CTAs/SM.
// D = Ah*Bh + Al*Bh + Ah*Bl  (residual ~2^-17). A pre-split in g_ahi/g_alo.
// Stage smem: A 2x10240 + B 2x5120 = 30720 B; 2 stages = 61440 B dynamic.
// HOP=1: grid (157,8): (y&3)*64 -> nc0, (y>>2) -> L/R weight + g_xl/g_xr output.
// SPLITK=1 (HOP=0): grid (157,4,2): z = K-half; z=0 -> g_xl (+bias), z=1 -> g_pp (raw).
#define SROW 40
#define OFF_AH  0
#define OFF_AL  10240
#define OFF_BH  20480
#define OFF_BL  25600
#define STG_B   30720

template<int HOP, int SPLITK>
__global__ __launch_bounds__(256, 3)
void k_gemm(int boffL, int boffR, const float* __restrict__ biasL,
            const float* __restrict__ biasR, int M, int K)
{
    extern __shared__ __align__(16) uint8_t dyn[];

    int tid = threadIdx.x, wid = tid >> 5, lane = tid & 31;
    int warp_m = wid & 3, warp_n = wid >> 2;
    int row0 = blockIdx.x * 128;

    int nc0, boff, kbase = 0, Keff = K;
    bool addb = true;
    const float* bias;
    float* out;
    if (HOP){
        int yy = blockIdx.y;
        int isR = yy >> 2;
        nc0  = (yy & 3) * 64;
        boff = isR ? boffR : boffL;
        bias = isR ? biasR : biasL;
        out  = isR ? g_xr : g_xl;
    } else {
        nc0  = blockIdx.y * 64;
        boff = boffL;
        bias = biasL;
        out  = g_xl;
        if (SPLITK){
            int z = blockIdx.z;
            Keff  = K >> 1;
            kbase = z * Keff;
            out   = z ? g_pp : g_xl;
            addb  = (z == 0);
        }
    }

    float acc[2][4][4];
#pragma unroll
    for (int mt = 0; mt < 2; mt++)
#pragma unroll
        for (int nt = 0; nt < 4; nt++)
#pragma unroll
            for (int q = 0; q < 4; q++) acc[mt][nt][q] = 0.f;

    // ---- loader mapping: thread -> (row r, k-half); warps 0-3 also load B (64 rows) ----
    int r = tid >> 1, half = tid & 1;
    int grow = row0 + r;
    bool rok = grow < M;
    bool bld = (tid < 128);              // uniform per warp
    const __nv_bfloat16* ahp = g_ahi + (size_t)grow * K + kbase + half * 16;
    const __nv_bfloat16* alp = g_alo + (size_t)grow * K + kbase + half * 16;
    int brow = nc0 + (bld ? r : 0);
    const __nv_bfloat16* bhp = g_bhi + boff + (size_t)brow * K + kbase + half * 16;
    const __nv_bfloat16* blp = g_blo + boff + (size_t)brow * K + kbase + half * 16;

    uint32_t base = smem_u32(dyn);
    uint32_t ldOff = (uint32_t)((r * SROW + half * 16) * 2);   // A dst (r<128) / B dst (r<64)

    // ---- ldmatrix per-lane fragment offsets (within an array) ----
    int lrow = lane & 15, lcol = (lane >> 4) * 8;
    uint32_t aFrag = (uint32_t)(((warp_m * 32 + lrow) * SROW + lcol) * 2);
    uint32_t bFrag = (uint32_t)(((warp_n * 32 + lrow) * SROW + lcol) * 2);

    int iters = Keff >> 5;

    // prologue: stage 0 loads
    {
        uint32_t sb = base;
        cp16(sb + OFF_AH + ldOff,      ahp,     rok);
        cp16(sb + OFF_AH + ldOff + 16, ahp + 8, rok);
        cp16(sb + OFF_AL + ldOff,      alp,     rok);
        cp16(sb + OFF_AL + ldOff + 16, alp + 8, rok);
        if (bld){
            cp16(sb + OFF_BH + ldOff,      bhp,     true);
            cp16(sb + OFF_BH + ldOff + 16, bhp + 8, true);
            cp16(sb + OFF_BL + ldOff,      blp,     true);
            cp16(sb + OFF_BL + ldOff + 16, blp + 8, true);
        }
        asm volatile("cp.async.commit_group;" ::: "memory");
    }

    for (int it = 0; it < iters; it++){
        if (it + 1 < iters){
            int k1 = (it + 1) << 5;
            uint32_t sb = base + ((it + 1) & 1) * STG_B;
            cp16(sb + OFF_AH + ldOff,      ahp + k1,     rok);
            cp16(sb + OFF_AH + ldOff + 16, ahp + k1 + 8, rok);
            cp16(sb + OFF_AL + ldOff,      alp + k1,     rok);
            cp16(sb + OFF_AL + ldOff + 16, alp + k1 + 8, rok);
            if (bld){
                cp16(sb + OFF_BH + ldOff,      bhp + k1,     true);
                cp16(sb + OFF_BH + ldOff + 16, bhp + k1 + 8, true);
                cp16(sb + OFF_BL + ldOff,      blp + k1,     true);
                cp16(sb + OFF_BL + ldOff + 16, blp + k1 + 8, true);
            }
            asm volatile("cp.async.commit_group;" ::: "memory");
            asm volatile("cp.async.wait_group 1;" ::: "memory");
        } else {
            asm volatile("cp.async.wait_group 0;" ::: "memory");
        }
        __syncthreads();

        uint32_t sb = base + (it & 1) * STG_B;
        uint32_t aBH = sb + OFF_AH + aFrag, aBL = sb + OFF_AL + aFrag;
        uint32_t bBH = sb + OFF_BH + bFrag, bBL = sb + OFF_BL + bFrag;

#pragma unroll
        for (int kc = 0; kc < 2; kc++){
            uint32_t ah[2][4], al[2][4];
#pragma unroll
            for (int mt = 0; mt < 2; mt++){
                LDMX4(ah[mt], aBH + (uint32_t)((mt * 16 * SROW + kc * 16) * 2));
                LDMX4(al[mt], aBL + (uint32_t)((mt * 16 * SROW + kc * 16) * 2));
            }
#pragma unroll
            for (int nt2 = 0; nt2 < 2; nt2++){
                uint32_t bh[4], bl[4];
                LDMX4(bh, bBH + (uint32_t)((nt2 * 16 * SROW + kc * 16) * 2));
                LDMX4(bl, bBL + (uint32_t)((nt2 * 16 * SROW + kc * 16) * 2));
#pragma unroll
                for (int p = 0; p < 2; p++){
                    int nt = nt2 * 2 + p;
                    uint32_t b0h = bh[p], b1h = bh[p + 2];
                    uint32_t b0l = bl[p], b1l = bl[p + 2];
#pragma unroll
                    for (int mt = 0; mt < 2; mt++){
                        mma16816(acc[mt][nt], ah[mt], b0h, b1h);   // hi*hi
                        mma16816(acc[mt][nt], al[mt], b0h, b1h);   // lo*hi
                        mma16816(acc[mt][nt], ah[mt], b0l, b1l);   // hi*lo
                    }
                }
            }
        }
        __syncthreads();   // all fragment reads done before stage is overwritten
    }

    // ---------------- epilogue: (+bias on z=0), fp32 store ----------------
    int groupID = lane >> 2, tig = lane & 3;
#pragma unroll
    for (int mt = 0; mt < 2; mt++){
        int ra = row0 + warp_m * 32 + mt * 16 + groupID;
        int rb = ra + 8;
#pragma unroll
        for (int nt = 0; nt < 4; nt++){
            int col = nc0 + warp_n * 32 + nt * 8 + tig * 2;
            float b0 = addb ? bias[col]     : 0.f;
            float b1 = addb ? bias[col + 1] : 0.f;
            float v0 = acc[mt][nt][0] + b0, v1 = acc[mt][nt][1] + b1;
            float v2 = acc[mt][nt][2] + b0, v3 = acc[mt][nt][3] + b1;
            if (ra < M){
                out[(size_t)ra * HID + col]     = v0;
                out[(size_t)ra * HID + col + 1] = v1;
            }
            if (rb < M){
                out[(size_t)rb * HID + col]     = v2;
                out[(size_t)rb * HID + col + 1] = v3;
            }
        }
    }
}

// ---------------- LayerNorm (proj): g_x = LN(g_xl + g_pp); emits bf16 splits --------------
__global__ void k_ln(const float* __restrict__ g, const float* __restrict__ b){
    int gw = (int)((blockIdx.x * blockDim.x + threadIdx.x) >> 5);
    if (gw >= N_NODES) return;
    int lane = threadIdx.x & 31, d = lane * 8;
    const float4* p  = (const float4*)(g_xl + (size_t)gw * HID + d);
    const float4* pq = (const float4*)(g_pp + (size_t)gw * HID + d);
    float4 v0 = p[0], v1 = p[1];
    float4 w0 = pq[0], w1 = pq[1];
    float v[8] = {v0.x + w0.x, v0.y + w0.y, v0.z + w0.z, v0.w + w0.w,
                  v1.x + w1.x, v1.y + w1.y, v1.z + w1.z, v1.w + w1.w};
    float s = 0.f, ss = 0.f;
#pragma unroll
    for (int q = 0; q < 8; q++){ s += v[q]; ss += v[q] * v[q]; }
    s  = warp_sum32(s);
    ss = warp_sum32(ss);
    float mu  = s  * (1.f / 256.f);
    float var = ss * (1.f / 256.f) - mu * mu;
    float inv = rsqrtf(var + LN_EPS);
    float* op = g_x + (size_t)gw * HID + d;
    float o[8];
#pragma unroll
    for (int q = 0; q < 8; q++){
        o[q] = (v[q] - mu) * inv * g[d + q] + b[d + q];
        op[q] = o[q];
    }
    uint32_t h0, l0, h1, l1, h2, l2, h3, l3;
    split2(o[0], o[1], h0, l0);  split2(o[2], o[3], h1, l1);
    split2(o[4], o[5], h2, l2);  split2(o[6], o[7], h3, l3);
    int idx = gw * (HID / 4) + lane * 2;
    ((uint2*)g_ahi)[idx]     = make_uint2(h0, h1);
    ((uint2*)g_ahi)[idx + 1] = make_uint2(h2, h3);
    ((uint2*)g_alo)[idx]     = make_uint2(l0, l1);
    ((uint2*)g_alo)[idx + 1] = make_uint2(l2, l3);
}

// ---------------- fused GAT hop: 2-edge ILP online softmax + agg + residual + LN + split --
// One warp per dst node; lane owns 8 dims (one head: head = lane>>3). Two CSR slots per
// iteration: two independent row-load chains + one pairwise online-softmax merge.
__global__ void k_gat(const float* __restrict__ att,
                      const float* __restrict__ gbias,
                      const float* __restrict__ lng,
                      const float* __restrict__ lnb){
    int gw = (int)((blockIdx.x * blockDim.x + threadIdx.x) >> 5);
    if (gw >= N_NODES) return;
    int lane = threadIdx.x & 31, d = lane * 8;

    const float4* pr = (const float4*)(g_xr + (size_t)gw * HID + d);
    float4 r0 = pr[0], r1 = pr[1];
    const float4* pa = (const float4*)(att + d);
    float4 a0 = __ldg(pa), a1 = __ldg(pa + 1);

    float m = -1e30f, denom = 0.f;
    float acc[8] = {0.f, 0.f, 0.f, 0.f, 0.f, 0.f, 0.f, 0.f};

    int s = g_rowstart[gw], e = g_rowstart[gw + 1];
    int j = s;
    for (; j + 1 < e; j += 2){
        int s1 = g_src[j], s2 = g_src[j + 1];
        const float4* p1 = (const float4*)(g_xl + (size_t)s1 * HID + d);
        const float4* p2 = (const float4*)(g_xl + (size_t)s2 * HID + d);
        float4 u0 = p1[0], u1 = p1[1];       // two independent 32B chains
        float4 w0 = p2[0], w1 = p2[1];

        float t1 = 0.f, t2 = 0.f;
        t1 = fmaf(lrelu(u0.x + r0.x), a0.x, t1);  t2 = fmaf(lrelu(w0.x + r0.x), a0.x, t2);
        t1 = fmaf(lrelu(u0.y + r0.y), a0.y, t1);  t2 = fmaf(lrelu(w0.y + r0.y), a0.y, t2);
        t1 = fmaf(lrelu(u0.z + r0.z), a0.z, t1);  t2 = fmaf(lrelu(w0.z + r0.z), a0.z, t2);
        t1 = fmaf(lrelu(u0.w + r0.w), a0.w, t1);  t2 = fmaf(lrelu(w0.w + r0.w), a0.w, t2);
        t1 = fmaf(lrelu(u1.x + r1.x), a1.x, t1);  t2 = fmaf(lrelu(w1.x + r1.x), a1.x, t2);
        t1 = fmaf(lrelu(u1.y + r1.y), a1.y, t1);  t2 = fmaf(lrelu(w1.y + r1.y), a1.y, t2);
        t1 = fmaf(lrelu(u1.z + r1.z), a1.z, t1);  t2 = fmaf(lrelu(w1.z + r1.z), a1.z, t2);
        t1 = fmaf(lrelu(u1.w + r1.w), a1.w, t1);  t2 = fmaf(lrelu(w1.w + r1.w), a1.w, t2);
        t1 += __shfl_xor_sync(0xffffffffu, t1, 1);  t2 += __shfl_xor_sync(0xffffffffu, t2, 1);
        t1 += __shfl_xor_sync(0xffffffffu, t1, 2);  t2 += __shfl_xor_sync(0xffffffffu, t2, 2);
        t1 += __shfl_xor_sync(0xffffffffu, t1, 4);  t2 += __shfl_xor_sync(0xffffffffu, t2, 4);

        float mn = fmaxf(m, fmaxf(t1, t2));
        float sc = expf(m - mn);             // first iter: expf(-inf) = 0
        float q1 = expf(t1 - mn);
        float q2 = expf(t2 - mn);
        denom = fmaf(denom, sc, q1 + q2);
        acc[0] = fmaf(acc[0], sc, fmaf(q1, u0.x, q2 * w0.x));
        acc[1] = fmaf(acc[1], sc, fmaf(q1, u0.y, q2 * w0.y));
        acc[2] = fmaf(acc[2], sc, fmaf(q1, u0.z, q2 * w0.z));
        acc[3] = fmaf(acc[3], sc, fmaf(q1, u0.w, q2 * w0.w));
        acc[4] = fmaf(acc[4], sc, fmaf(q1, u1.x, q2 * w1.x));
        acc[5] = fmaf(acc[5], sc, fmaf(q1, u1.y, q2 * w1.y));
        acc[6] = fmaf(acc[6], sc, fmaf(q1, u1.z, q2 * w1.z));
        acc[7] = fmaf(acc[7], sc, fmaf(q1, u1.w, q2 * w1.w));
        m = mn;
    }
    if (j < e){   // odd tail: single edge
        int s1 = g_src[j];
        const float4* p1 = (const float4*)(g_xl + (size_t)s1 * HID + d);
        float4 u0 = p1[0], u1 = p1[1];
        float t1 = 0.f;
        t1 = fmaf(lrelu(u0.x + r0.x), a0.x, t1);
        t1 = fmaf(lrelu(u0.y + r0.y), a0.y, t1);
        t1 = fmaf(lrelu(u0.z + r0.z), a0.z, t1);
        t1 = fmaf(lrelu(u0.w + r0.w), a0.w, t1);
        t1 = fmaf(lrelu(u1.x + r1.x), a1.x, t1);
        t1 = fmaf(lrelu(u1.y + r1.y), a1.y, t1);
        t1 = fmaf(lrelu(u1.z + r1.z), a1.z, t1);
        t1 = fmaf(lrelu(u1.w + r1.w), a1.w, t1);
        t1 += __shfl_xor_sync(0xffffffffu, t1, 1);
        t1 += __shfl_xor_sync(0xffffffffu, t1, 2);
        t1 += __shfl_xor_sync(0xffffffffu, t1, 4);
        float mn = fmaxf(m, t1);
        float sc = expf(m - mn);
        float q1 = expf(t1 - mn);
        denom = fmaf(denom, sc, q1);
        acc[0] = fmaf(acc[0], sc, q1 * u0.x);
        acc[1] = fmaf(acc[1], sc, q1 * u0.y);
        acc[2] = fmaf(acc[2], sc, q1 * u0.z);
        acc[3] = fmaf(acc[3], sc, q1 * u0.w);
        acc[4] = fmaf(acc[4], sc, q1 * u1.x);
        acc[5] = fmaf(acc[5], sc, q1 * u1.y);
        acc[6] = fmaf(acc[6], sc, q1 * u1.z);
        acc[7] = fmaf(acc[7], sc, q1 * u1.w);
        m = mn;
    }

    float inv = 1.f / denom;
    float* xp = g_x + (size_t)gw * HID + d;
    float v[8];
#pragma unroll
    for (int q = 0; q < 8; q++) v[q] = fmaf(acc[q], inv, gbias[d + q] + xp[q]);

    float sm = 0.f, ss = 0.f;
#pragma unroll
    for (int q = 0; q < 8; q++){ sm += v[q]; ss += v[q] * v[q]; }
    sm = warp_sum32(sm);
    ss = warp_sum32(ss);
    float mu  = sm * (1.f / 256.f);
    float var = ss * (1.f / 256.f) - mu * mu;
    float rin = rsqrtf(var + LN_EPS);
    float o[8];
#pragma unroll
    for (int q = 0; q < 8; q++){
        o[q] = (v[q] - mu) * rin * lng[d + q] + lnb[d + q];
        xp[q] = o[q];
    }
    uint32_t h0, l0, h1, l1, h2, l2, h3, l3;
    split2(o[0], o[1], h0, l0);  split2(o[2], o[3], h1, l1);
    split2(o[4], o[5], h2, l2);  split2(o[6], o[7], h3, l3);
    int idx = gw * (HID / 4) + lane * 2;
    ((uint2*)g_ahi)[idx]     = make_uint2(h0, h1);
    ((uint2*)g_ahi)[idx + 1] = make_uint2(h2, h3);
    ((uint2*)g_alo)[idx]     = make_uint2(l0, l1);
    ((uint2*)g_alo)[idx + 1] = make_uint2(l2, l3);
}

// ---------------- head 2: out = gelu(xl + pp) @ h2_W + h2_b -------------------------------
__global__ void k_head2(const float* __restrict__ W2, const float* __restrict__ b2,
                        float* __restrict__ out){
    __shared__ float ws[HID * NCLS];
    int tid = threadIdx.x;
    for (int i = tid; i < HID * NCLS; i += blockDim.x) ws[i] = W2[i];
    __syncthreads();
    int gw = (int)((blockIdx.x * blockDim.x + tid) >> 5);
    if (gw >= N_NODES) return;
    int lane = tid & 31;
    const float* row = g_xl + (size_t)gw * HID;
    const float* prt = g_pp + (size_t)gw * HID;
    float a0 = 0.f, a1 = 0.f, a2 = 0.f;
#pragma unroll
    for (int q = 0; q < 8; q++){
        int k = lane + 32 * q;
        float xv = row[k] + prt[k];
        xv = 0.5f * xv * (1.f + erff(xv * 0.70710678118654752440f));
        a0 = fmaf(xv, ws[k * 3 + 0], a0);
        a1 = fmaf(xv, ws[k * 3 + 1], a1);
        a2 = fmaf(xv, ws[k * 3 + 2], a2);
    }
    a0 = warp_sum32(a0); a1 = warp_sum32(a1); a2 = warp_sum32(a2);
    if (lane == 0){
        out[(size_t)gw * NCLS + 0] = a0 + b2[0];
        out[(size_t)gw * NCLS + 1] = a1 + b2[1];
        out[(size_t)gw * NCLS + 2] = a2 + b2[2];
    }
}

// ---------------- launch ----------------
extern "C" void kernel_launch(void* const* d_in, const int* in_sizes, int n_in,
                              void* d_out, int out_size)
{
    const float* features = (const float*)d_in[0];
    const int*   ei       = (const int*)d_in[1];     // int32 (JAX x64 disabled)
    const float* proj_W = (const float*)d_in[2];
    const float* proj_b = (const float*)d_in[3];
    const float* n0_g   = (const float*)d_in[4];
    const float* n0_b   = (const float*)d_in[5];
    const float* Wl     = (const float*)d_in[6];
    const float* bl     = (const float*)d_in[7];
    const float* Wr     = (const float*)d_in[8];
    const float* br     = (const float*)d_in[9];
    const float* att    = (const float*)d_in[10];
    const float* gbias  = (const float*)d_in[11];
    const float* ln_g   = (const float*)d_in[12];
    const float* ln_b   = (const float*)d_in[13];
    const float* h1_W   = (const float*)d_in[14];
    const float* h1_b   = (const float*)d_in[15];
    const float* h2_W   = (const float*)d_in[16];
    const float* h2_b   = (const float*)d_in[17];
    float* out = (float*)d_out;

    const int DSM = 2 * STG_B;   // 61440 B dynamic smem
    cudaFuncSetAttribute(k_gemm<1, 0>, cudaFuncAttributeMaxDynamicSharedMemorySize, DSM);
    cudaFuncSetAttribute(k_gemm<0, 1>, cudaFuncAttributeMaxDynamicSharedMemorySize, DSM);
    (void)cudaGetLastError();   // clear any sticky non-fatal status before capture

    const int NT = (N_NODES + 127) / 128;      // 157 row tiles
    const dim3 GS(NT, 4, 2);                   // split-K grids (proj, h1): 1256 CTAs
    const dim3 GH(NT, 8);                      // fused hop grid (L/R x 4 col tiles): 1256 CTAs
    const int T4F = (N_NODES * IN_DIM) / 4;

    // weight + feature splits first, then proj at launch index 3 (ncu profiles index 3)
    k_tsplit <<<(IN_DIM * HID) / 256, 256>>>(proj_W, IN_DIM, HID, OFF_PROJ);   // 0
    k_tsplit7<<<(7 * 65536) / 256, 256>>>(Wl, Wr, h1_W);                       // 1
    k_asplit <<<(T4F + 255) / 256, 256>>>(features, T4F);                      // 2
    k_gemm<0, 1><<<GS, 256, DSM>>>(OFF_PROJ, 0, proj_b, nullptr, N_NODES, IN_DIM); // 3
    k_ln<<<(N_NODES * 32 + 255) / 256, 256>>>(n0_g, n0_b);                     // 4

    // CSR build (only needed before the first k_gat)
    k_clear  <<<(N_NODES + 255) / 256, 256>>>();                               // 5
    k_hist   <<<(EP + 255) / 256, 256>>>(ei);                                  // 6
    k_scan   <<<1, 1024>>>();                                                  // 7
    k_scatter<<<(EP + 255) / 256, 256>>>(ei);                                  // 8

    for (int h = 0; h < HOPS; h++){
        k_gemm<1, 0><<<GH, 256, DSM>>>(OFF_WL + h * HID * HID, OFF_WR + h * HID * HID,
                                       bl + h * HID, br + h * HID, N_NODES, HID);
        k_gat<<<(N_NODES * 32 + 255) / 256, 256>>>(att + h * HEADS * (HID / HEADS),
                                                   gbias + h * HID, ln_g + h * HID, ln_b + h * HID);
    }

    // head: h1 split-K partials -> g_xl/g_pp ; head2 fuses sum + exact GELU + final matmul
    k_gemm<0, 1><<<GS, 256, DSM>>>(OFF_H1, 0, h1_b, nullptr, N_NODES, HID);
    k_head2<<<(N_NODES * 32 + 255) / 256, 256>>>(h2_W, h2_b, out);

    (void)in_sizes; (void)n_in; (void)out_size;
}

// round 17
// speedup vs baseline: 2.6604x; 1.1574x over previous
#include <cuda_runtime.h>
#include <cuda_fp16.h>
#include <cstdint>
#include <cstddef>

#define N_NODES 20000
#define IN_DIM  1536
#define HID     256
#define HEADS   4
#define HOPS    3
#define NCLS    3
#define NE      320000
#define EP      (NE + N_NODES)     /* 340000 edges incl. self loops */
#define LN_EPS  1e-5f
#define NEG_SLOPE 0.2f

// weight arena offsets (fp16 elements), all K-major transposed: Wt[n][k] = W[k][n]
#define OFF_PROJ 0                         /* 256 x 1536 */
#define OFF_WL   393216                    /* 3 x 256 x 256 */
#define OFF_WR   589824                    /* 3 x 256 x 256 */
#define OFF_H1   786432                    /* 256 x 256 */
#define W_ARENA  851968

// ---------------- scratch (static device globals: no runtime allocation) ----------------
__device__ float g_x [N_NODES * HID];
__device__ float g_xl[N_NODES * HID];     // also head1 partial out
__device__ float g_xr[N_NODES * HID];
__device__ float g_pp[N_NODES * HID];     // split-K partial (proj / h1)
__device__ int   g_rowstart[N_NODES + 1];
__device__ int   g_counts[N_NODES];
__device__ int   g_cursor[N_NODES];
__device__ int   g_src[EP];
__device__ __half g_bh[W_ARENA];            // weight fp16 hi (K-major)
__device__ __half g_ah[N_NODES * IN_DIM];   // activation fp16 hi
__device__ __half g_al[N_NODES * IN_DIM];   // activation fp16 lo (x - hi)

// ---------------- small helpers ----------------
__device__ __forceinline__ float warp_sum32(float v){
#pragma unroll
    for (int o = 16; o > 0; o >>= 1) v += __shfl_xor_sync(0xffffffffu, v, o);
    return v;
}
__device__ __forceinline__ float lrelu(float t){ return t > 0.f ? t : NEG_SLOPE * t; }
__device__ __forceinline__ int clamp_idx(int v){
    return ((unsigned)v < (unsigned)N_NODES) ? v : 0;
}
__device__ __forceinline__ uint32_t smem_u32(const void* p){
    uint32_t a;
    asm("{ .reg .u64 t; cvta.to.shared.u64 t, %1; cvt.u32.u64 %0, t; }" : "=r"(a) : "l"(p));
    return a;
}
// split two fp32 into packed fp16x2 hi and lo (k-even in low half)
__device__ __forceinline__ void split2h(float f0, float f1, uint32_t& hi, uint32_t& lo){
    __half h0 = __float2half_rn(f0);
    __half h1 = __float2half_rn(f1);
    hi = ((uint32_t)__half_as_ushort(h1) << 16) | (uint32_t)__half_as_ushort(h0);
    __half l0 = __float2half_rn(f0 - __half2float(h0));
    __half l1 = __float2half_rn(f1 - __half2float(h1));
    lo = ((uint32_t)__half_as_ushort(l1) << 16) | (uint32_t)__half_as_ushort(l0);
}
__device__ __forceinline__ uint32_t pack2h(float f0, float f1){
    __half h0 = __float2half_rn(f0);
    __half h1 = __float2half_rn(f1);
    return ((uint32_t)__half_as_ushort(h1) << 16) | (uint32_t)__half_as_ushort(h0);
}
// async 16B copy; pred=false -> zero-fill (src not read)
__device__ __forceinline__ void cp16(uint32_t dst, const void* src, bool pred){
    int sz = pred ? 16 : 0;
    asm volatile("cp.async.cg.shared.global [%0], [%1], 16, %2;"
                 :: "r"(dst), "l"(src), "r"(sz));
}

#define LDMX4(r, addr) \
    asm volatile("ldmatrix.sync.aligned.m8n8.x4.shared.b16 {%0,%1,%2,%3}, [%4];" \
                 : "=r"((r)[0]), "=r"((r)[1]), "=r"((r)[2]), "=r"((r)[3]) : "r"(addr))

__device__ __forceinline__ void mma16816h(float* c, const uint32_t* a, uint32_t b0, uint32_t b1){
    asm volatile(
        "mma.sync.aligned.m16n8k16.row.col.f32.f16.f16.f32 "
        "{%0,%1,%2,%3}, {%4,%5,%6,%7}, {%8,%9}, {%0,%1,%2,%3};"
        : "+f"(c[0]), "+f"(c[1]), "+f"(c[2]), "+f"(c[3])
        : "r"(a[0]), "r"(a[1]), "r"(a[2]), "r"(a[3]), "r"(b0), "r"(b1));
}

// ---------------- CSR build ----------------
__global__ void k_clear(){
    int i = blockIdx.x * blockDim.x + threadIdx.x;
    if (i < N_NODES){ g_counts[i] = 0; g_cursor[i] = 0; }
}
__global__ void k_hist(const int* __restrict__ ei){
    int e = blockIdx.x * blockDim.x + threadIdx.x;
    if (e >= EP) return;
    int dst = (e < NE) ? clamp_idx(ei[NE + e]) : (e - NE);
    atomicAdd(&g_counts[dst], 1);
}
__global__ void k_scan(){
    __shared__ int sm[1024];
    __shared__ int soff;
    int tid = threadIdx.x;
    if (tid == 0) soff = 0;
    __syncthreads();
    for (int base = 0; base < N_NODES; base += 1024){
        int idx = base + tid;
        int v = (idx < N_NODES) ? g_counts[idx] : 0;
        sm[tid] = v;
        __syncthreads();
        for (int s = 1; s < 1024; s <<= 1){
            int t = (tid >= s) ? sm[tid - s] : 0;
            __syncthreads();
            sm[tid] += t;
            __syncthreads();
        }
        if (idx < N_NODES) g_rowstart[idx] = soff + sm[tid] - v;
        int tot = sm[1023];
        __syncthreads();
        if (tid == 0) soff += tot;
        __syncthreads();
    }
    if (tid == 0) g_rowstart[N_NODES] = soff;
}
__global__ void k_scatter(const int* __restrict__ ei){
    int e = blockIdx.x * blockDim.x + threadIdx.x;
    if (e >= EP) return;
    int src, dst;
    if (e < NE){ src = clamp_idx(ei[e]); dst = clamp_idx(ei[NE + e]); }
    else       { src = e - NE;           dst = src; }
    int pos = g_rowstart[dst] + atomicAdd(&g_cursor[dst], 1);
    g_src[pos] = src;
}

// ---------------- weight transpose + fp16 pack ----------------
__global__ void k_tsplit(const float* __restrict__ W, int K, int N, int ooff){
    int i = blockIdx.x * blockDim.x + threadIdx.x;
    if (i >= K * N) return;
    int k = i / N, n = i - k * N;
    g_bh[ooff + (size_t)n * K + k] = __float2half_rn(W[i]);
}
// all seven 256x256 weights in one launch: 3x Wl, 3x Wr, h1
__global__ void k_tsplit7(const float* __restrict__ Wl, const float* __restrict__ Wr,
                          const float* __restrict__ h1){
    int i = blockIdx.x * blockDim.x + threadIdx.x;
    if (i >= 7 * 65536) return;
    int slab = i >> 16, j = i & 65535;
    const float* src; int ooff;
    if (slab < 3){ src = Wl + slab * 65536;      ooff = OFF_WL + slab * 65536; }
    else if (slab < 6){ src = Wr + (slab - 3) * 65536; ooff = OFF_WR + (slab - 3) * 65536; }
    else { src = h1; ooff = OFF_H1; }
    int k = j >> 8, n = j & 255;
    g_bh[ooff + n * 256 + k] = __float2half_rn(src[j]);
}

// ---------------- feature fp16 split (proj input only) ----------------
__global__ void k_asplit(const float* __restrict__ A, int total4){
    int i = blockIdx.x * blockDim.x + threadIdx.x;
    if (i >= total4) return;
    float4 f = ((const float4*)A)[i];
    uint32_t h0, l0, h1, l1;
    split2h(f.x, f.y, h0, l0);
    split2h(f.z, f.w, h1, l1);
    ((uint2*)g_ah)[i] = make_uint2(h0, h1);
    ((uint2*)g_al)[i] = make_uint2(l0, l1);
}

// ---------------- warp-MMA fp16 2-term GEMM, cp.async double-buffered --------------------
// CTA tile 128x64, 8 warps (4m x 2n), warp tile 32x32, BK=32, 3 CTAs/SM.
// D = Ah*Bh + Al*Bh  (A to 2^-22, B to 2^-12 -> per-GEMM rel err ~2.4e-4).
// Stage smem: AH 10240 + AL 10240 + BH 5120 = 25600 B; 2 stages = 51200 B dynamic.
// HOP=1: grid (157,8): (y&3)*64 -> nc0, (y>>2) -> L/R weight + g_xl/g_xr output.
// SPLITK=1 (HOP=0): grid (157,4,2): z = K-half; z=0 -> g_xl (+bias), z=1 -> g_pp (raw).
#define SROW 40
#define OFF_AHs 0
#define OFF_ALs 10240
#define OFF_BHs 20480
#define STG_B   25600

template<int HOP, int SPLITK>
__global__ __launch_bounds__(256, 3)
void k_gemm(int boffL, int boffR, const float* __restrict__ biasL,
            const float* __restrict__ biasR, int M, int K)
{
    extern __shared__ __align__(16) uint8_t dyn[];

    int tid = threadIdx.x, wid = tid >> 5, lane = tid & 31;
    int warp_m = wid & 3, warp_n = wid >> 2;
    int row0 = blockIdx.x * 128;

    int nc0, boff, kbase = 0, Keff = K;
    bool addb = true;
    const float* bias;
    float* out;
    if (HOP){
        int yy = blockIdx.y;
        int isR = yy >> 2;
        nc0  = (yy & 3) * 64;
        boff = isR ? boffR : boffL;
        bias = isR ? biasR : biasL;
        out  = isR ? g_xr : g_xl;
    } else {
        nc0  = blockIdx.y * 64;
        boff = boffL;
        bias = biasL;
        out  = g_xl;
        if (SPLITK){
            int z = blockIdx.z;
            Keff  = K >> 1;
            kbase = z * Keff;
            out   = z ? g_pp : g_xl;
            addb  = (z == 0);
        }
    }

    float acc[2][4][4];
#pragma unroll
    for (int mt = 0; mt < 2; mt++)
#pragma unroll
        for (int nt = 0; nt < 4; nt++)
#pragma unroll
            for (int q = 0; q < 4; q++) acc[mt][nt][q] = 0.f;

    // ---- loader mapping: thread -> (row r, k-half); warps 0-3 also load B (64 rows) ----
    int r = tid >> 1, half = tid & 1;
    int grow = row0 + r;
    bool rok = grow < M;
    bool bld = (tid < 128);              // uniform per warp
    const __half* ahp = g_ah + (size_t)grow * K + kbase + half * 16;
    const __half* alp = g_al + (size_t)grow * K + kbase + half * 16;
    int brow = nc0 + (bld ? r : 0);
    const __half* bhp = g_bh + boff + (size_t)brow * K + kbase + half * 16;

    uint32_t base = smem_u32(dyn);
    uint32_t ldOff = (uint32_t)((r * SROW + half * 16) * 2);   // A dst (r<128) / B dst (r<64)

    // ---- ldmatrix per-lane fragment offsets (within an array) ----
    int lrow = lane & 15, lcol = (lane >> 4) * 8;
    uint32_t aFrag = (uint32_t)(((warp_m * 32 + lrow) * SROW + lcol) * 2);
    uint32_t bFrag = (uint32_t)(((warp_n * 32 + lrow) * SROW + lcol) * 2);

    int iters = Keff >> 5;

    // prologue: stage 0 loads
    {
        uint32_t sb = base;
        cp16(sb + OFF_AHs + ldOff,      ahp,     rok);
        cp16(sb + OFF_AHs + ldOff + 16, ahp + 8, rok);
        cp16(sb + OFF_ALs + ldOff,      alp,     rok);
        cp16(sb + OFF_ALs + ldOff + 16, alp + 8, rok);
        if (bld){
            cp16(sb + OFF_BHs + ldOff,      bhp,     true);
            cp16(sb + OFF_BHs + ldOff + 16, bhp + 8, true);
        }
        asm volatile("cp.async.commit_group;" ::: "memory");
    }

    for (int it = 0; it < iters; it++){
        if (it + 1 < iters){
            int k1 = (it + 1) << 5;
            uint32_t sb = base + ((it + 1) & 1) * STG_B;
            cp16(sb + OFF_AHs + ldOff,      ahp + k1,     rok);
            cp16(sb + OFF_AHs + ldOff + 16, ahp + k1 + 8, rok);
            cp16(sb + OFF_ALs + ldOff,      alp + k1,     rok);
            cp16(sb + OFF_ALs + ldOff + 16, alp + k1 + 8, rok);
            if (bld){
                cp16(sb + OFF_BHs + ldOff,      bhp + k1,     true);
                cp16(sb + OFF_BHs + ldOff + 16, bhp + k1 + 8, true);
            }
            asm volatile("cp.async.commit_group;" ::: "memory");
            asm volatile("cp.async.wait_group 1;" ::: "memory");
        } else {
            asm volatile("cp.async.wait_group 0;" ::: "memory");
        }
        __syncthreads();

        uint32_t sb = base + (it & 1) * STG_B;
        uint32_t aBH = sb + OFF_AHs + aFrag, aBL = sb + OFF_ALs + aFrag;
        uint32_t bBH = sb + OFF_BHs + bFrag;

#pragma unroll
        for (int kc = 0; kc < 2; kc++){
            uint32_t ah[2][4], al[2][4];
#pragma unroll
            for (int mt = 0; mt < 2; mt++){
                LDMX4(ah[mt], aBH + (uint32_t)((mt * 16 * SROW + kc * 16) * 2));
                LDMX4(al[mt], aBL + (uint32_t)((mt * 16 * SROW + kc * 16) * 2));
            }
#pragma unroll
            for (int nt2 = 0; nt2 < 2; nt2++){
                uint32_t bh[4];
                LDMX4(bh, bBH + (uint32_t)((nt2 * 16 * SROW + kc * 16) * 2));
#pragma unroll
                for (int p = 0; p < 2; p++){
                    int nt = nt2 * 2 + p;
                    uint32_t b0h = bh[p], b1h = bh[p + 2];
#pragma unroll
                    for (int mt = 0; mt < 2; mt++){
                        mma16816h(acc[mt][nt], ah[mt], b0h, b1h);   // hi*hi
                        mma16816h(acc[mt][nt], al[mt], b0h, b1h);   // lo*hi
                    }
                }
            }
        }
        __syncthreads();   // all fragment reads done before stage is overwritten
    }

    // ---------------- epilogue: (+bias on z=0), fp32 store ----------------
    int groupID = lane >> 2, tig = lane & 3;
#pragma unroll
    for (int mt = 0; mt < 2; mt++){
        int ra = row0 + warp_m * 32 + mt * 16 + groupID;
        int rb = ra + 8;
#pragma unroll
        for (int nt = 0; nt < 4; nt++){
            int col = nc0 + warp_n * 32 + nt * 8 + tig * 2;
            float b0 = addb ? bias[col]     : 0.f;
            float b1 = addb ? bias[col + 1] : 0.f;
            float v0 = acc[mt][nt][0] + b0, v1 = acc[mt][nt][1] + b1;
            float v2 = acc[mt][nt][2] + b0, v3 = acc[mt][nt][3] + b1;
            if (ra < M){
                out[(size_t)ra * HID + col]     = v0;
                out[(size_t)ra * HID + col + 1] = v1;
            }
            if (rb < M){
                out[(size_t)rb * HID + col]     = v2;
                out[(size_t)rb * HID + col + 1] = v3;
            }
        }
    }
}

// ---------------- LayerNorm (proj): g_x = LN(g_xl + g_pp); emits fp16 splits --------------
__global__ void k_ln(const float* __restrict__ g, const float* __restrict__ b){
    int gw = (int)((blockIdx.x * blockDim.x + threadIdx.x) >> 5);
    if (gw >= N_NODES) return;
    int lane = threadIdx.x & 31, d = lane * 8;
    const float4* p  = (const float4*)(g_xl + (size_t)gw * HID + d);
    const float4* pq = (const float4*)(g_pp + (size_t)gw * HID + d);
    float4 v0 = p[0], v1 = p[1];
    float4 w0 = pq[0], w1 = pq[1];
    float v[8] = {v0.x + w0.x, v0.y + w0.y, v0.z + w0.z, v0.w + w0.w,
                  v1.x + w1.x, v1.y + w1.y, v1.z + w1.z, v1.w + w1.w};
    float s = 0.f, ss = 0.f;
#pragma unroll
    for (int q = 0; q < 8; q++){ s += v[q]; ss += v[q] * v[q]; }
    s  = warp_sum32(s);
    ss = warp_sum32(ss);
    float mu  = s  * (1.f / 256.f);
    float var = ss * (1.f / 256.f) - mu * mu;
    float inv = rsqrtf(var + LN_EPS);
    float* op = g_x + (size_t)gw * HID + d;
    float o[8];
#pragma unroll
    for (int q = 0; q < 8; q++){
        o[q] = (v[q] - mu) * inv * g[d + q] + b[d + q];
        op[q] = o[q];
    }
    uint32_t h0, l0, h1, l1, h2, l2, h3, l3;
    split2h(o[0], o[1], h0, l0);  split2h(o[2], o[3], h1, l1);
    split2h(o[4], o[5], h2, l2);  split2h(o[6], o[7], h3, l3);
    int idx = gw * (HID / 4) + lane * 2;
    ((uint2*)g_ah)[idx]     = make_uint2(h0, h1);
    ((uint2*)g_ah)[idx + 1] = make_uint2(h2, h3);
    ((uint2*)g_al)[idx]     = make_uint2(l0, l1);
    ((uint2*)g_al)[idx + 1] = make_uint2(l2, l3);
}

// ---------------- fused GAT hop: 2-edge ILP online softmax + agg + residual + LN + split --
__global__ void k_gat(const float* __restrict__ att,
                      const float* __restrict__ gbias,
                      const float* __restrict__ lng,
                      const float* __restrict__ lnb){
    int gw = (int)((blockIdx.x * blockDim.x + threadIdx.x) >> 5);
    if (gw >= N_NODES) return;
    int lane = threadIdx.x & 31, d = lane * 8;

    const float4* pr = (const float4*)(g_xr + (size_t)gw * HID + d);
    float4 r0 = pr[0], r1 = pr[1];
    const float4* pa = (const float4*)(att + d);
    float4 a0 = __ldg(pa), a1 = __ldg(pa + 1);

    float m = -1e30f, denom = 0.f;
    float acc[8] = {0.f, 0.f, 0.f, 0.f, 0.f, 0.f, 0.f, 0.f};

    int s = g_rowstart[gw], e = g_rowstart[gw + 1];
    int j = s;
    for (; j + 1 < e; j += 2){
        int s1 = g_src[j], s2 = g_src[j + 1];
        const float4* p1 = (const float4*)(g_xl + (size_t)s1 * HID + d);
        const float4* p2 = (const float4*)(g_xl + (size_t)s2 * HID + d);
        float4 u0 = p1[0], u1 = p1[1];       // two independent 32B chains
        float4 w0 = p2[0], w1 = p2[1];

        float t1 = 0.f, t2 = 0.f;
        t1 = fmaf(lrelu(u0.x + r0.x), a0.x, t1);  t2 = fmaf(lrelu(w0.x + r0.x), a0.x, t2);
        t1 = fmaf(lrelu(u0.y + r0.y), a0.y, t1);  t2 = fmaf(lrelu(w0.y + r0.y), a0.y, t2);
        t1 = fmaf(lrelu(u0.z + r0.z), a0.z, t1);  t2 = fmaf(lrelu(w0.z + r0.z), a0.z, t2);
        t1 = fmaf(lrelu(u0.w + r0.w), a0.w, t1);  t2 = fmaf(lrelu(w0.w + r0.w), a0.w, t2);
        t1 = fmaf(lrelu(u1.x + r1.x), a1.x, t1);  t2 = fmaf(lrelu(w1.x + r1.x), a1.x, t2);
        t1 = fmaf(lrelu(u1.y + r1.y), a1.y, t1);  t2 = fmaf(lrelu(w1.y + r1.y), a1.y, t2);
        t1 = fmaf(lrelu(u1.z + r1.z), a1.z, t1);  t2 = fmaf(lrelu(w1.z + r1.z), a1.z, t2);
        t1 = fmaf(lrelu(u1.w + r1.w), a1.w, t1);  t2 = fmaf(lrelu(w1.w + r1.w), a1.w, t2);
        t1 += __shfl_xor_sync(0xffffffffu, t1, 1);  t2 += __shfl_xor_sync(0xffffffffu, t2, 1);
        t1 += __shfl_xor_sync(0xffffffffu, t1, 2);  t2 += __shfl_xor_sync(0xffffffffu, t2, 2);
        t1 += __shfl_xor_sync(0xffffffffu, t1, 4);  t2 += __shfl_xor_sync(0xffffffffu, t2, 4);

        float mn = fmaxf(m, fmaxf(t1, t2));
        float sc = expf(m - mn);             // first iter: expf(-inf) = 0
        float q1 = expf(t1 - mn);
        float q2 = expf(t2 - mn);
        denom = fmaf(denom, sc, q1 + q2);
        acc[0] = fmaf(acc[0], sc, fmaf(q1, u0.x, q2 * w0.x));
        acc[1] = fmaf(acc[1], sc, fmaf(q1, u0.y, q2 * w0.y));
        acc[2] = fmaf(acc[2], sc, fmaf(q1, u0.z, q2 * w0.z));
        acc[3] = fmaf(acc[3], sc, fmaf(q1, u0.w, q2 * w0.w));
        acc[4] = fmaf(acc[4], sc, fmaf(q1, u1.x, q2 * w1.x));
        acc[5] = fmaf(acc[5], sc, fmaf(q1, u1.y, q2 * w1.y));
        acc[6] = fmaf(acc[6], sc, fmaf(q1, u1.z, q2 * w1.z));
        acc[7] = fmaf(acc[7], sc, fmaf(q1, u1.w, q2 * w1.w));
        m = mn;
    }
    if (j < e){   // odd tail: single edge
        int s1 = g_src[j];
        const float4* p1 = (const float4*)(g_xl + (size_t)s1 * HID + d);
        float4 u0 = p1[0], u1 = p1[1];
        float t1 = 0.f;
        t1 = fmaf(lrelu(u0.x + r0.x), a0.x, t1);
        t1 = fmaf(lrelu(u0.y + r0.y), a0.y, t1);
        t1 = fmaf(lrelu(u0.z + r0.z), a0.z, t1);
        t1 = fmaf(lrelu(u0.w + r0.w), a0.w, t1);
        t1 = fmaf(lrelu(u1.x + r1.x), a1.x, t1);
        t1 = fmaf(lrelu(u1.y + r1.y), a1.y, t1);
        t1 = fmaf(lrelu(u1.z + r1.z), a1.z, t1);
        t1 = fmaf(lrelu(u1.w + r1.w), a1.w, t1);
        t1 += __shfl_xor_sync(0xffffffffu, t1, 1);
        t1 += __shfl_xor_sync(0xffffffffu, t1, 2);
        t1 += __shfl_xor_sync(0xffffffffu, t1, 4);
        float mn = fmaxf(m, t1);
        float sc = expf(m - mn);
        float q1 = expf(t1 - mn);
        denom = fmaf(denom, sc, q1);
        acc[0] = fmaf(acc[0], sc, q1 * u0.x);
        acc[1] = fmaf(acc[1], sc, q1 * u0.y);
        acc[2] = fmaf(acc[2], sc, q1 * u0.z);
        acc[3] = fmaf(acc[3], sc, q1 * u0.w);
        acc[4] = fmaf(acc[4], sc, q1 * u1.x);
        acc[5] = fmaf(acc[5], sc, q1 * u1.y);
        acc[6] = fmaf(acc[6], sc, q1 * u1.z);
        acc[7] = fmaf(acc[7], sc, q1 * u1.w);
        m = mn;
    }

    float inv = 1.f / denom;
    float* xp = g_x + (size_t)gw * HID + d;
    float v[8];
#pragma unroll
    for (int q = 0; q < 8; q++) v[q] = fmaf(acc[q], inv, gbias[d + q] + xp[q]);

    float sm = 0.f, ss = 0.f;
#pragma unroll
    for (int q = 0; q < 8; q++){ sm += v[q]; ss += v[q] * v[q]; }
    sm = warp_sum32(sm);
    ss = warp_sum32(ss);
    float mu  = sm * (1.f / 256.f);
    float var = ss * (1.f / 256.f) - mu * mu;
    float rin = rsqrtf(var + LN_EPS);
    float o[8];
#pragma unroll
    for (int q = 0; q < 8; q++){
        o[q] = (v[q] - mu) * rin * lng[d + q] + lnb[d + q];
        xp[q] = o[q];
    }
    uint32_t h0, l0, h1, l1, h2, l2, h3, l3;
    split2h(o[0], o[1], h0, l0);  split2h(o[2], o[3], h1, l1);
    split2h(o[4], o[5], h2, l2);  split2h(o[6], o[7], h3, l3);
    int idx = gw * (HID / 4) + lane * 2;
    ((uint2*)g_ah)[idx]     = make_uint2(h0, h1);
    ((uint2*)g_ah)[idx + 1] = make_uint2(h2, h3);
    ((uint2*)g_al)[idx]     = make_uint2(l0, l1);
    ((uint2*)g_al)[idx + 1] = make_uint2(l2, l3);
}

// ---------------- head 2: out = gelu(xl + pp) @ h2_W + h2_b -------------------------------
__global__ void k_head2(const float* __restrict__ W2, const float* __restrict__ b2,
                        float* __restrict__ out){
    __shared__ float ws[HID * NCLS];
    int tid = threadIdx.x;
    for (int i = tid; i < HID * NCLS; i += blockDim.x) ws[i] = W2[i];
    __syncthreads();
    int gw = (int)((blockIdx.x * blockDim.x + tid) >> 5);
    if (gw >= N_NODES) return;
    int lane = tid & 31;
    const float* row = g_xl + (size_t)gw * HID;
    const float* prt = g_pp + (size_t)gw * HID;
    float a0 = 0.f, a1 = 0.f, a2 = 0.f;
#pragma unroll
    for (int q = 0; q < 8; q++){
        int k = lane + 32 * q;
        float xv = row[k] + prt[k];
        xv = 0.5f * xv * (1.f + erff(xv * 0.70710678118654752440f));
        a0 = fmaf(xv, ws[k * 3 + 0], a0);
        a1 = fmaf(xv, ws[k * 3 + 1], a1);
        a2 = fmaf(xv, ws[k * 3 + 2], a2);
    }
    a0 = warp_sum32(a0); a1 = warp_sum32(a1); a2 = warp_sum32(a2);
    if (lane == 0){
        out[(size_t)gw * NCLS + 0] = a0 + b2[0];
        out[(size_t)gw * NCLS + 1] = a1 + b2[1];
        out[(size_t)gw * NCLS + 2] = a2 + b2[2];
    }
}

// ---------------- launch ----------------
extern "C" void kernel_launch(void* const* d_in, const int* in_sizes, int n_in,
                              void* d_out, int out_size)
{
    const float* features = (const float*)d_in[0];
    const int*   ei       = (const int*)d_in[1];     // int32 (JAX x64 disabled)
    const float* proj_W = (const float*)d_in[2];
    const float* proj_b = (const float*)d_in[3];
    const float* n0_g   = (const float*)d_in[4];
    const float* n0_b   = (const float*)d_in[5];
    const float* Wl     = (const float*)d_in[6];
    const float* bl     = (const float*)d_in[7];
    const float* Wr     = (const float*)d_in[8];
    const float* br     = (const float*)d_in[9];
    const float* att    = (const float*)d_in[10];
    const float* gbias  = (const float*)d_in[11];
    const float* ln_g   = (const float*)d_in[12];
    const float* ln_b   = (const float*)d_in[13];
    const float* h1_W   = (const float*)d_in[14];
    const float* h1_b   = (const float*)d_in[15];
    const float* h2_W   = (const float*)d_in[16];
    const float* h2_b   = (const float*)d_in[17];
    float* out = (float*)d_out;

    const int DSM = 2 * STG_B;   // 51200 B dynamic smem
    cudaFuncSetAttribute(k_gemm<1, 0>, cudaFuncAttributeMaxDynamicSharedMemorySize, DSM);
    cudaFuncSetAttribute(k_gemm<0, 1>, cudaFuncAttributeMaxDynamicSharedMemorySize, DSM);
    (void)cudaGetLastError();   // clear any sticky non-fatal status before capture

    const int NT = (N_NODES + 127) / 128;      // 157 row tiles
    const dim3 GS(NT, 4, 2);                   // split-K grids (proj, h1): 1256 CTAs
    const dim3 GH(NT, 8);                      // fused hop grid (L/R x 4 col tiles): 1256 CTAs
    const int T4F = (N_NODES * IN_DIM) / 4;

    // weight + feature packs first, then proj at launch index 3 (ncu profiles index 3)
    k_tsplit <<<(IN_DIM * HID) / 256, 256>>>(proj_W, IN_DIM, HID, OFF_PROJ);   // 0
    k_tsplit7<<<(7 * 65536) / 256, 256>>>(Wl, Wr, h1_W);                       // 1
    k_asplit <<<(T4F + 255) / 256, 256>>>(features, T4F);                      // 2
    k_gemm<0, 1><<<GS, 256, DSM>>>(OFF_PROJ, 0, proj_b, nullptr, N_NODES, IN_DIM); // 3
    k_ln<<<(N_NODES * 32 + 255) / 256, 256>>>(n0_g, n0_b);                     // 4

    // CSR build (only needed before the first k_gat)
    k_clear  <<<(N_NODES + 255) / 256, 256>>>();                               // 5
    k_hist   <<<(EP + 255) / 256, 256>>>(ei);                                  // 6
    k_scan   <<<1, 1024>>>();                                                  // 7
    k_scatter<<<(EP + 255) / 256, 256>>>(ei);                                  // 8

    for (int h = 0; h < HOPS; h++){
        k_gemm<1, 0><<<GH, 256, DSM>>>(OFF_WL + h * HID * HID, OFF_WR + h * HID * HID,
                                       bl + h * HID, br + h * HID, N_NODES, HID);
        k_gat<<<(N_NODES * 32 + 255) / 256, 256>>>(att + h * HEADS * (HID / HEADS),
                                                   gbias + h * HID, ln_g + h * HID, ln_b + h * HID);
    }

    // head: h1 split-K partials -> g_xl/g_pp ; head2 fuses sum + exact GELU + final matmul
    k_gemm<0, 1><<<GS, 256, DSM>>>(OFF_H1, 0, h1_b, nullptr, N_NODES, HID);
    k_head2<<<(N_NODES * 32 + 255) / 256, 256>>>(h2_W, h2_b, out);

    (void)in_sizes; (void)n_in; (void)out_size;
}